// round 1
// baseline (speedup 1.0000x reference)
#include <cuda_runtime.h>
#include <math.h>

// Problem dims
#define B_  4
#define S_  1024
#define D_  512
#define H_  8
#define DK_ 64
#define FF_ 2048
#define L_  4
#define IN_ 768
#define NS_ 4
#define SD_ 64

#define BS  (B_*S_)            // 4096
#define BSD ((long long)BS*D_) // 2097152

// ---------------- scratch (device globals: allocation-free) ----------------
__device__ float g_pe[S_*D_];
__device__ float g_y[BS*D_];
__device__ float g_h1[NS_*BS*IN_];
__device__ float g_experts[NS_*BS*D_];
__device__ float g_summary[BS*D_];
__device__ float g_x[BS*D_];
__device__ float g_v[L_*BS*D_];
__device__ float g_k[BS*D_];
__device__ float g_ctx[BS*D_];
__device__ float g_ffn[BS*FF_];

// ---------------- positional embedding ----------------
__global__ void pe_kernel(float* __restrict__ pe) {
    int s = blockIdx.x;          // 0..1023
    int j = threadIdx.x;         // 0..255 (pair index)
    float div = expf((float)(2*j) * (-9.210340371976184f / (float)D_));
    float arg = (float)s * div;
    pe[s*D_ + 2*j]     = sinf(arg);
    pe[s*D_ + 2*j + 1] = cosf(arg);
}

__global__ void add_pe_kernel(const float* __restrict__ qa,
                              const float* __restrict__ pe,
                              float* __restrict__ y) {
    int i = blockIdx.x * 256 + threadIdx.x;   // grid covers BS*D
    y[i] = qa[i] + pe[i & (S_*D_ - 1)];
}

// ---------------- generic tiled SGEMM (row-major, exact-tile dims) ---------
// C[z] = op(A[z] @ B[z] + bias[z] + res), op = optional relu
// A: M x K, row stride lda, batch elem stride sA
// B: K x N (ld = N), batch stride sB
// C: M x N (ld = N), batch stride sC
// All of M%128==0, N%128==0, K%16==0 hold for every call in this net.
#define BM 128
#define BN 128
#define BK 16
#define TM 8
#define TN 8

__global__ __launch_bounds__(256) void sgemm_kernel(
    const float* __restrict__ A, int lda, long long sA,
    const float* __restrict__ Bm, long long sB,
    const float* __restrict__ bias, int sBias,
    const float* __restrict__ res,
    float* __restrict__ C, long long sC,
    int M, int N, int K, int relu)
{
    __shared__ float As[BK][BM];
    __shared__ float Bs[BK][BN];

    const int z = blockIdx.z;
    A  += (long long)z * sA;
    Bm += (long long)z * sB;
    C  += (long long)z * sC;
    if (bias) bias += (long long)z * sBias;

    const int tid  = threadIdx.x;
    const int brow = blockIdx.y * BM;
    const int bcol = blockIdx.x * BN;

    const int arow = tid >> 2;          // 0..63
    const int acol = (tid & 3) * 4;     // 0,4,8,12
    const int brb  = tid >> 5;          // 0..7
    const int bcb  = (tid & 31) * 4;    // 0..124

    const int ty = tid >> 4;            // 0..15
    const int tx = tid & 15;            // 0..15

    float acc[TM][TN] = {};

    for (int k0 = 0; k0 < K; k0 += BK) {
        #pragma unroll
        for (int i = 0; i < 2; i++) {
            int r = arow + i * 64;
            float4 v = *(const float4*)(A + (long long)(brow + r) * lda + k0 + acol);
            As[acol + 0][r] = v.x;
            As[acol + 1][r] = v.y;
            As[acol + 2][r] = v.z;
            As[acol + 3][r] = v.w;
        }
        #pragma unroll
        for (int i = 0; i < 2; i++) {
            int r = brb + i * 8;
            *(float4*)&Bs[r][bcb] =
                *(const float4*)(Bm + (long long)(k0 + r) * N + bcol + bcb);
        }
        __syncthreads();

        #pragma unroll
        for (int k = 0; k < BK; k++) {
            float4 a0 = *(const float4*)&As[k][ty * TM];
            float4 a1 = *(const float4*)&As[k][ty * TM + 4];
            float4 b0 = *(const float4*)&Bs[k][tx * TN];
            float4 b1 = *(const float4*)&Bs[k][tx * TN + 4];
            float ra[TM] = {a0.x, a0.y, a0.z, a0.w, a1.x, a1.y, a1.z, a1.w};
            float rb[TN] = {b0.x, b0.y, b0.z, b0.w, b1.x, b1.y, b1.z, b1.w};
            #pragma unroll
            for (int i = 0; i < TM; i++)
                #pragma unroll
                for (int j = 0; j < TN; j++)
                    acc[i][j] += ra[i] * rb[j];
        }
        __syncthreads();
    }

    #pragma unroll
    for (int i = 0; i < TM; i++) {
        int m = brow + ty * TM + i;
        #pragma unroll
        for (int j = 0; j < TN; j += 4) {
            int n = bcol + tx * TN + j;
            float4 o = make_float4(acc[i][j], acc[i][j+1], acc[i][j+2], acc[i][j+3]);
            if (bias) {
                o.x += bias[n]; o.y += bias[n+1]; o.z += bias[n+2]; o.w += bias[n+3];
            }
            if (res) {
                float4 rv = *(const float4*)(res + (long long)m * N + n);
                o.x += rv.x; o.y += rv.y; o.z += rv.z; o.w += rv.w;
            }
            if (relu) {
                o.x = fmaxf(o.x, 0.f); o.y = fmaxf(o.y, 0.f);
                o.z = fmaxf(o.z, 0.f); o.w = fmaxf(o.w, 0.f);
            }
            *(float4*)(C + (long long)m * N + n) = o;
        }
    }
}

// ---------------- MoE gate + combine + LN + PE -> x ----------------
__global__ __launch_bounds__(256) void moe_kernel(
    const float* __restrict__ summary, const float* __restrict__ m_seq,
    const float* __restrict__ gate_w,  const float* __restrict__ gate_b,
    const float* __restrict__ experts,
    const float* __restrict__ lng, const float* __restrict__ lnb,
    const float* __restrict__ pe, float* __restrict__ x)
{
    __shared__ float red[4][8];
    __shared__ float wgt[4];
    __shared__ float r1[8], r2[8];

    const int row = blockIdx.x;          // b*S + s
    const int tid = threadIdx.x;
    const int s_idx = row & (S_ - 1);

    // gate logits: concat(summary, m_seq) @ gate_w + gate_b
    float p0 = 0, p1 = 0, p2 = 0, p3 = 0;
    for (int e = tid; e < D_ + SD_; e += 256) {
        float xv = (e < D_) ? summary[(long long)row * D_ + e]
                            : m_seq[(long long)row * SD_ + (e - D_)];
        float4 w = *(const float4*)(gate_w + e * 4);
        p0 += xv * w.x; p1 += xv * w.y; p2 += xv * w.z; p3 += xv * w.w;
    }
    #pragma unroll
    for (int o = 16; o > 0; o >>= 1) {
        p0 += __shfl_xor_sync(0xffffffffu, p0, o);
        p1 += __shfl_xor_sync(0xffffffffu, p1, o);
        p2 += __shfl_xor_sync(0xffffffffu, p2, o);
        p3 += __shfl_xor_sync(0xffffffffu, p3, o);
    }
    if ((tid & 31) == 0) {
        int w = tid >> 5;
        red[0][w] = p0; red[1][w] = p1; red[2][w] = p2; red[3][w] = p3;
    }
    __syncthreads();

    if (tid == 0) {
        float l[4];
        #pragma unroll
        for (int j = 0; j < 4; j++) {
            float t = gate_b[j];
            #pragma unroll
            for (int w = 0; w < 8; w++) t += red[j][w];
            l[j] = t;
        }
        // top-2 threshold (ties kept, matching logits >= thresh)
        float m1 = -INFINITY, m2 = -INFINITY;
        #pragma unroll
        for (int j = 0; j < 4; j++) {
            if (l[j] > m1) { m2 = m1; m1 = l[j]; }
            else if (l[j] > m2) { m2 = l[j]; }
        }
        float sum = 0.f, e4[4];
        #pragma unroll
        for (int j = 0; j < 4; j++) {
            e4[j] = (l[j] >= m2) ? __expf(l[j] - m1) : 0.f;
            sum += e4[j];
        }
        #pragma unroll
        for (int j = 0; j < 4; j++) wgt[j] = e4[j] / sum;
    }
    __syncthreads();

    const float w0 = wgt[0], w1 = wgt[1], w2 = wgt[2], w3 = wgt[3];
    const long long base = (long long)row * D_;
    const int t2 = tid + 256;
    float c0 = w0 * experts[0*BSD + base + tid] + w1 * experts[1*BSD + base + tid]
             + w2 * experts[2*BSD + base + tid] + w3 * experts[3*BSD + base + tid];
    float c1 = w0 * experts[0*BSD + base + t2]  + w1 * experts[1*BSD + base + t2]
             + w2 * experts[2*BSD + base + t2]  + w3 * experts[3*BSD + base + t2];

    float s = c0 + c1, q = c0 * c0 + c1 * c1;
    #pragma unroll
    for (int o = 16; o > 0; o >>= 1) {
        s += __shfl_xor_sync(0xffffffffu, s, o);
        q += __shfl_xor_sync(0xffffffffu, q, o);
    }
    if ((tid & 31) == 0) { r1[tid >> 5] = s; r2[tid >> 5] = q; }
    __syncthreads();
    float ts = 0, tq = 0;
    #pragma unroll
    for (int w = 0; w < 8; w++) { ts += r1[w]; tq += r2[w]; }
    float mu = ts * (1.f / 512.f);
    float var = tq * (1.f / 512.f) - mu * mu;
    float rstd = rsqrtf(var + 1e-5f);

    x[base + tid] = (c0 - mu) * rstd * lng[tid] + lnb[tid] + pe[s_idx * D_ + tid];
    x[base + t2]  = (c1 - mu) * rstd * lng[t2]  + lnb[t2]  + pe[s_idx * D_ + t2];
}

// ---------------- LayerNorm (block per row, D=512) ----------------
__global__ __launch_bounds__(256) void ln_kernel(
    const float* __restrict__ in, const float* __restrict__ g,
    const float* __restrict__ b, float* __restrict__ out)
{
    __shared__ float r1[8], r2[8];
    const int row = blockIdx.x, tid = threadIdx.x;
    const long long base = (long long)row * D_;
    float v0 = in[base + tid], v1 = in[base + tid + 256];
    float s = v0 + v1, q = v0 * v0 + v1 * v1;
    #pragma unroll
    for (int o = 16; o > 0; o >>= 1) {
        s += __shfl_xor_sync(0xffffffffu, s, o);
        q += __shfl_xor_sync(0xffffffffu, q, o);
    }
    if ((tid & 31) == 0) { r1[tid >> 5] = s; r2[tid >> 5] = q; }
    __syncthreads();
    float ts = 0, tq = 0;
    #pragma unroll
    for (int w = 0; w < 8; w++) { ts += r1[w]; tq += r2[w]; }
    float mu = ts * (1.f / 512.f);
    float var = tq * (1.f / 512.f) - mu * mu;
    float rstd = rsqrtf(var + 1e-5f);
    out[base + tid]       = (v0 - mu) * rstd * g[tid]       + b[tid];
    out[base + tid + 256] = (v1 - mu) * rstd * g[tid + 256] + b[tid + 256];
}

// ---------------- flash attention (strict causal, Q == K) ----------------
// grid (S/128, H, B), 128 threads; thread t owns query row m0+t.
__global__ __launch_bounds__(128) void attn_kernel(
    const float* __restrict__ Kg, const float* __restrict__ Vg,
    float* __restrict__ Og)
{
    __shared__ float Ks[64][64];
    __shared__ float Vs[64][64];

    const int m0 = blockIdx.x * 128;
    const int h  = blockIdx.y;
    const int b  = blockIdx.z;
    const int tid = threadIdx.x;
    const int row = m0 + tid;

    const float* Kbh = Kg + ((long long)b * S_) * D_ + h * DK_;
    const float* Vbh = Vg + ((long long)b * S_) * D_ + h * DK_;

    float4 q[16], acc[16];
    {
        const float4* qp = (const float4*)(Kbh + (long long)row * D_);
        #pragma unroll
        for (int i = 0; i < 16; i++) { q[i] = qp[i]; acc[i] = make_float4(0.f,0.f,0.f,0.f); }
    }
    float mmax = -INFINITY, lsum = 0.f;

    const int ntiles = (m0 + 190) / 64;   // covers keys 0..m0+126
    for (int t = 0; t < ntiles; t++) {
        __syncthreads();
        #pragma unroll
        for (int i = 0; i < 8; i++) {
            int idx = tid + i * 128;         // 0..1023 float4 slots
            int r = idx >> 4, c = (idx & 15) * 4;
            *(float4*)&Ks[r][c] = *(const float4*)(Kbh + (long long)(t*64 + r) * D_ + c);
            *(float4*)&Vs[r][c] = *(const float4*)(Vbh + (long long)(t*64 + r) * D_ + c);
        }
        __syncthreads();

        const int kbase = t * 64;
        #pragma unroll 1
        for (int c0 = 0; c0 < 64; c0 += 16) {
            float sc[16];
            float cmax = -INFINITY;
            #pragma unroll
            for (int jj = 0; jj < 16; jj++) {
                const float4* kr = (const float4*)(&Ks[c0 + jj][0]);
                float d0 = 0, d1 = 0, d2 = 0, d3 = 0;
                #pragma unroll
                for (int d4 = 0; d4 < 16; d4++) {
                    float4 kv = kr[d4];
                    d0 += q[d4].x * kv.x; d1 += q[d4].y * kv.y;
                    d2 += q[d4].z * kv.z; d3 += q[d4].w * kv.w;
                }
                float dot = (d0 + d1) + (d2 + d3);
                sc[jj] = (kbase + c0 + jj < row) ? dot * 0.125f : -INFINITY;
                cmax = fmaxf(cmax, sc[jj]);
            }
            if (cmax == -INFINITY) continue;    // fully masked chunk
            float mnew = fmaxf(mmax, cmax);
            float corr = __expf(mmax - mnew);   // exp(-inf)=0 when first live chunk
            lsum *= corr;
            #pragma unroll
            for (int i = 0; i < 16; i++) {
                acc[i].x *= corr; acc[i].y *= corr; acc[i].z *= corr; acc[i].w *= corr;
            }
            mmax = mnew;
            #pragma unroll
            for (int jj = 0; jj < 16; jj++) {
                float p = __expf(sc[jj] - mnew);
                lsum += p;
                const float4* vr = (const float4*)(&Vs[c0 + jj][0]);
                #pragma unroll
                for (int d4 = 0; d4 < 16; d4++) {
                    float4 vv = vr[d4];
                    acc[d4].x += p * vv.x; acc[d4].y += p * vv.y;
                    acc[d4].z += p * vv.z; acc[d4].w += p * vv.w;
                }
            }
        }
    }

    float inv = (lsum > 0.f) ? 1.f / lsum : 0.f;  // row 0 -> zeros (ref sets attn row0=0)
    float4* op = (float4*)(Og + ((long long)b * S_ + row) * D_ + h * DK_);
    #pragma unroll
    for (int i = 0; i < 16; i++) {
        op[i] = make_float4(acc[i].x * inv, acc[i].y * inv, acc[i].z * inv, acc[i].w * inv);
    }
}

// ---------------- launch ----------------
extern "C" void kernel_launch(void* const* d_in, const int* in_sizes, int n_in,
                              void* d_out, int out_size)
{
    const float* q_raw   = (const float*)d_in[0];
    const float* m_seq   = (const float*)d_in[1];
    const float* qa      = (const float*)d_in[2];
    const float* exp_w1  = (const float*)d_in[3];
    const float* exp_b1  = (const float*)d_in[4];
    const float* exp_w2  = (const float*)d_in[5];
    const float* exp_b2  = (const float*)d_in[6];
    const float* adapt_w = (const float*)d_in[7];
    const float* adapt_b = (const float*)d_in[8];
    const float* gate_w  = (const float*)d_in[9];
    const float* gate_b  = (const float*)d_in[10];
    const float* moe_g   = (const float*)d_in[11];
    const float* moe_b   = (const float*)d_in[12];
    const float* kw      = (const float*)d_in[13];
    const float* kb      = (const float*)d_in[14];
    const float* vw      = (const float*)d_in[15];
    const float* vb      = (const float*)d_in[16];
    const float* ow      = (const float*)d_in[17];
    const float* ob      = (const float*)d_in[18];
    const float* ln1g    = (const float*)d_in[19];
    const float* ln1b    = (const float*)d_in[20];
    const float* fw1     = (const float*)d_in[21];
    const float* fb1     = (const float*)d_in[22];
    const float* fw2     = (const float*)d_in[23];
    const float* fb2     = (const float*)d_in[24];
    const float* ln2g    = (const float*)d_in[25];
    const float* ln2b    = (const float*)d_in[26];

    float *pe, *y, *h1, *experts, *summary, *x, *v, *kk, *ctx, *ffn;
    cudaGetSymbolAddress((void**)&pe, g_pe);
    cudaGetSymbolAddress((void**)&y, g_y);
    cudaGetSymbolAddress((void**)&h1, g_h1);
    cudaGetSymbolAddress((void**)&experts, g_experts);
    cudaGetSymbolAddress((void**)&summary, g_summary);
    cudaGetSymbolAddress((void**)&x, g_x);
    cudaGetSymbolAddress((void**)&v, g_v);
    cudaGetSymbolAddress((void**)&kk, g_k);
    cudaGetSymbolAddress((void**)&ctx, g_ctx);
    cudaGetSymbolAddress((void**)&ffn, g_ffn);

    // positional embedding + y = qa + pe (y is layer-invariant: ref overwrites y=x)
    pe_kernel<<<S_, 256>>>(pe);
    add_pe_kernel<<<(int)(BSD / 256), 256>>>(qa, pe, y);

    // MoE experts (batched over 4 experts)
    sgemm_kernel<<<dim3(IN_/BN, BS/BM, NS_), 256>>>(
        q_raw, NS_*IN_, IN_, exp_w1, (long long)IN_*IN_, exp_b1, IN_,
        nullptr, h1, (long long)BS*IN_, BS, IN_, IN_, 1);
    sgemm_kernel<<<dim3(D_/BN, BS/BM, NS_), 256>>>(
        h1, IN_, (long long)BS*IN_, exp_w2, (long long)IN_*D_, exp_b2, D_,
        nullptr, experts, BSD, BS, D_, IN_, 0);

    // adapter summary
    sgemm_kernel<<<dim3(D_/BN, BS/BM, 1), 256>>>(
        q_raw, NS_*IN_, 0, adapt_w, 0, adapt_b, 0,
        nullptr, summary, 0, BS, D_, NS_*IN_, 1);

    // gate + combine + moe LN + pe -> x
    moe_kernel<<<BS, 256>>>(summary, m_seq, gate_w, gate_b, experts,
                            moe_g, moe_b, pe, x);

    // all 4 layers' V = y @ vw[i] + vb[i] (batched; y never changes)
    sgemm_kernel<<<dim3(D_/BN, BS/BM, L_), 256>>>(
        y, D_, 0, vw, (long long)D_*D_, vb, D_,
        nullptr, v, BSD, BS, D_, D_, 0);

    for (int i = 0; i < L_; i++) {
        // K projection
        sgemm_kernel<<<dim3(D_/BN, BS/BM, 1), 256>>>(
            x, D_, 0, kw + (long long)i*D_*D_, 0, kb + i*D_, 0,
            nullptr, kk, 0, BS, D_, D_, 0);
        // causal attention (Q = K = kk)
        attn_kernel<<<dim3(S_/128, H_, B_), 128>>>(kk, v + (long long)i*BSD, ctx);
        // O projection + residual
        sgemm_kernel<<<dim3(D_/BN, BS/BM, 1), 256>>>(
            ctx, D_, 0, ow + (long long)i*D_*D_, 0, ob + i*D_, 0,
            x, x, 0, BS, D_, D_, 0);
        ln_kernel<<<BS, 256>>>(x, ln1g + i*D_, ln1b + i*D_, x);
        // FFN
        sgemm_kernel<<<dim3(FF_/BN, BS/BM, 1), 256>>>(
            x, D_, 0, fw1 + (long long)i*D_*FF_, 0, fb1 + i*FF_, 0,
            nullptr, ffn, 0, BS, FF_, D_, 1);
        sgemm_kernel<<<dim3(D_/BN, BS/BM, 1), 256>>>(
            ffn, FF_, 0, fw2 + (long long)i*FF_*D_, 0, fb2 + i*D_, 0,
            x, x, 0, BS, D_, FF_, 0);
        ln_kernel<<<BS, 256>>>(x, ln2g + i*D_, ln2b + i*D_,
                               (i == L_-1) ? (float*)d_out : x);
    }
}

// round 3
// speedup vs baseline: 1.8317x; 1.8317x over previous
#include <cuda_runtime.h>
#include <cuda_bf16.h>
#include <cstdint>
#include <math.h>

// Problem dims
#define B_  4
#define S_  1024
#define D_  512
#define H_  8
#define DK_ 64
#define FF_ 2048
#define L_  4
#define IN_ 768
#define NS_ 4
#define SD_ 64

#define BS  (B_*S_)            // 4096
#define BSD ((long long)BS*D_) // 2097152

// ---------------- scratch (device globals: allocation-free) ----------------
__device__ float g_pe[S_*D_];
__device__ float g_y[BS*D_];
__device__ float g_h1[NS_*BS*IN_];
__device__ float g_experts[NS_*BS*D_];
__device__ float g_summary[BS*D_];
__device__ float g_x[BS*D_];
__device__ float g_v[L_*BS*D_];
__device__ float g_k[BS*D_];
__device__ float g_ctx[BS*D_];
__device__ float g_ffn[BS*FF_];
// bf16 split buffers: A' = M x 3K (max 4*4096*2304), B't = N x 3K (max 4*768*2304)
__device__ __nv_bfloat16 g_abf[37748736];
__device__ __nv_bfloat16 g_bbf[7077888];

// ================= PTX helpers ===============================================
__device__ __forceinline__ uint32_t smem_u32(const void* p) {
    uint32_t a;
    asm("{ .reg .u64 t; cvta.to.shared.u64 t, %1; cvt.u32.u64 %0, t; }" : "=r"(a) : "l"(p));
    return a;
}

__device__ __forceinline__ void cp_async16(uint32_t dst, const void* src) {
    asm volatile("cp.async.cg.shared.global [%0], [%1], 16;" :: "r"(dst), "l"(src));
}
#define CP_COMMIT() asm volatile("cp.async.commit_group;" ::: "memory")
#define CP_WAIT0()  asm volatile("cp.async.wait_group 0;" ::: "memory")

__device__ __forceinline__ void ldsm_x4(uint32_t& r0, uint32_t& r1, uint32_t& r2,
                                        uint32_t& r3, uint32_t addr) {
    asm volatile("ldmatrix.sync.aligned.m8n8.x4.shared.b16 {%0,%1,%2,%3}, [%4];"
        : "=r"(r0), "=r"(r1), "=r"(r2), "=r"(r3) : "r"(addr));
}

__device__ __forceinline__ void mma16816(float* c, const uint32_t* a, const uint32_t* b) {
    asm volatile(
        "mma.sync.aligned.m16n8k16.row.col.f32.bf16.bf16.f32 "
        "{%0,%1,%2,%3}, {%4,%5,%6,%7}, {%8,%9}, {%0,%1,%2,%3};"
        : "+f"(c[0]), "+f"(c[1]), "+f"(c[2]), "+f"(c[3])
        : "r"(a[0]), "r"(a[1]), "r"(a[2]), "r"(a[3]), "r"(b[0]), "r"(b[1]));
}

// swizzled smem offset: 128B rows of 8x16B chunks, chunk xor (row&7)
__device__ __forceinline__ uint32_t swz(uint32_t base, int r, int ch) {
    return base + r * 128 + ((ch ^ (r & 7)) << 4);
}

// ================= fp32 -> bf16 hi/lo split conversions ======================
// A' layout per z: M x 3K, columns [Ah | Ah | Al]
__global__ __launch_bounds__(256) void convA_kernel(
    const float* __restrict__ src, int rowStride, long long zOff,
    int K, __nv_bfloat16* __restrict__ dst, int M)
{
    int idx = blockIdx.x * 256 + threadIdx.x;          // over M*K/4
    int kq = K >> 2;
    if (idx >= M * kq) return;
    int m = idx / kq;
    int k = (idx - m * kq) * 4;
    int z = blockIdx.z;
    float4 v = *(const float4*)(src + (long long)z * zOff + (long long)m * rowStride + k);
    unsigned short hb[4], lb[4];
    float vv[4] = {v.x, v.y, v.z, v.w};
    #pragma unroll
    for (int i = 0; i < 4; i++) {
        __nv_bfloat16 h = __float2bfloat16_rn(vv[i]);
        __nv_bfloat16 l = __float2bfloat16_rn(vv[i] - __bfloat162float(h));
        hb[i] = __bfloat16_as_ushort(h);
        lb[i] = __bfloat16_as_ushort(l);
    }
    uint2 hv = make_uint2((uint32_t)hb[0] | ((uint32_t)hb[1] << 16),
                          (uint32_t)hb[2] | ((uint32_t)hb[3] << 16));
    uint2 lv = make_uint2((uint32_t)lb[0] | ((uint32_t)lb[1] << 16),
                          (uint32_t)lb[2] | ((uint32_t)lb[3] << 16));
    long long base = ((long long)z * M + m) * (3LL * K);
    *(uint2*)(dst + base + k)          = hv;
    *(uint2*)(dst + base + K + k)      = hv;
    *(uint2*)(dst + base + 2LL*K + k)  = lv;
}

// B fp32 (K x N row-major, per-z stride sBz) -> B't per z: N x 3K, [Bh | Bl | Bh]
__global__ __launch_bounds__(256) void convB_kernel(
    const float* __restrict__ src, long long sBz, int K, int N,
    __nv_bfloat16* __restrict__ dst)
{
    __shared__ float t[32][33];
    int k0 = blockIdx.x * 32, n0 = blockIdx.y * 32, z = blockIdx.z;
    int tx = threadIdx.x, ty = threadIdx.y;   // (32, 8)
    const float* s = src + (long long)z * sBz;
    #pragma unroll
    for (int r = ty; r < 32; r += 8)
        t[r][tx] = s[(long long)(k0 + r) * N + n0 + tx];
    __syncthreads();
    #pragma unroll
    for (int r = ty; r < 32; r += 8) {
        float x = t[tx][r];                   // = B[k0+tx][n0+r]
        __nv_bfloat16 h = __float2bfloat16_rn(x);
        __nv_bfloat16 l = __float2bfloat16_rn(x - __bfloat162float(h));
        long long base = ((long long)z * N + (n0 + r)) * (3LL * K) + k0 + tx;
        dst[base]          = h;
        dst[base + K]      = l;
        dst[base + 2LL*K]  = h;
    }
}

// ================= mma.sync bf16 GEMM, 128x128 tile, BK=64, K'=3K ============
// C[m][n] = sum_k A'[m][k] * B't[n][k], fp32 accumulation.
#define G_SMEM_TOTAL 65536

__global__ __launch_bounds__(256) void gemm_bf3_kernel(
    const __nv_bfloat16* __restrict__ A, long long sA,
    const __nv_bfloat16* __restrict__ Bt, long long sB,
    const float* __restrict__ bias, int sBias,
    const float* __restrict__ res,
    float* __restrict__ C, long long sC,
    int N, int K3, int relu)
{
    extern __shared__ __align__(16) char smem[];

    const int tid = threadIdx.x;
    const int wid = tid >> 5, lane = tid & 31;
    const int wy = wid >> 2, wx = wid & 3;        // warp tile: 64 x 32
    const int z = blockIdx.z;
    const int brow = blockIdx.y * 128, bcol = blockIdx.x * 128;

    A  += (long long)z * sA + (long long)brow * K3;
    Bt += (long long)z * sB + (long long)bcol * K3;
    C  += (long long)z * sC;
    if (bias) bias += (long long)z * sBias;

    const uint32_t sb = smem_u32(smem);
    // buffers: A0 @0, A1 @16K, B0 @32K, B1 @48K (each 128 rows x 128B)

    float acc[4][4][4] = {};

    const int NC = K3 >> 6;    // 64-element K chunks

    // ---- tile loader (cp.async, swizzled) ----
    auto load_tile = [&](int c, int s) {
        const long long kc = (long long)c * 64;
        const uint32_t baseA = sb + s * 16384;
        const uint32_t baseB = sb + 32768 + s * 16384;
        #pragma unroll
        for (int i = 0; i < 4; i++) {
            int idx = tid + i * 256;           // 0..1023
            int r = idx >> 3, ch = idx & 7;
            cp_async16(swz(baseA, r, ch),
                       (const char*)(A + (long long)r * K3 + kc) + ch * 16);
            cp_async16(swz(baseB, r, ch),
                       (const char*)(Bt + (long long)r * K3 + kc) + ch * 16);
        }
        CP_COMMIT();
    };

    load_tile(0, 0);

    for (int c = 0; c < NC; c++) {
        const int s = c & 1;
        CP_WAIT0();
        __syncthreads();
        if (c + 1 < NC) load_tile(c + 1, s ^ 1);

        const uint32_t baseA = sb + s * 16384;
        const uint32_t baseB = sb + 32768 + s * 16384;

        #pragma unroll
        for (int ks = 0; ks < 4; ks++) {
            const int cb = ks * 2;
            uint32_t af[4][4];
            #pragma unroll
            for (int ms = 0; ms < 4; ms++) {
                int r = wy * 64 + ms * 16 + (lane & 15);
                ldsm_x4(af[ms][0], af[ms][1], af[ms][2], af[ms][3],
                        swz(baseA, r, cb + (lane >> 4)));
            }
            uint32_t bf[4][2];
            #pragma unroll
            for (int nh = 0; nh < 2; nh++) {
                int g = lane >> 3;
                int r = wx * 32 + nh * 16 + ((g & 2) << 2) + (lane & 7);
                uint32_t r0, r1, r2, r3;
                ldsm_x4(r0, r1, r2, r3, swz(baseB, r, cb + (g & 1)));
                bf[nh*2][0] = r0; bf[nh*2][1] = r1;
                bf[nh*2+1][0] = r2; bf[nh*2+1][1] = r3;
            }
            #pragma unroll
            for (int ms = 0; ms < 4; ms++)
                #pragma unroll
                for (int ns = 0; ns < 4; ns++)
                    mma16816(acc[ms][ns], af[ms], bf[ns]);
        }
        __syncthreads();
    }

    // ---- epilogue: bias / residual / relu ----
    const int qrow = lane >> 2, qcol = (lane & 3) * 2;
    #pragma unroll
    for (int ms = 0; ms < 4; ms++) {
        #pragma unroll
        for (int ns = 0; ns < 4; ns++) {
            int m = brow + wy * 64 + ms * 16 + qrow;
            int n = bcol + wx * 32 + ns * 8 + qcol;
            float2 v0 = make_float2(acc[ms][ns][0], acc[ms][ns][1]);
            float2 v1 = make_float2(acc[ms][ns][2], acc[ms][ns][3]);
            if (bias) {
                float b0 = bias[n], b1 = bias[n + 1];
                v0.x += b0; v0.y += b1; v1.x += b0; v1.y += b1;
            }
            if (res) {
                float2 r0 = *(const float2*)(res + (long long)m * N + n);
                float2 r1 = *(const float2*)(res + (long long)(m + 8) * N + n);
                v0.x += r0.x; v0.y += r0.y; v1.x += r1.x; v1.y += r1.y;
            }
            if (relu) {
                v0.x = fmaxf(v0.x, 0.f); v0.y = fmaxf(v0.y, 0.f);
                v1.x = fmaxf(v1.x, 0.f); v1.y = fmaxf(v1.y, 0.f);
            }
            *(float2*)(C + (long long)m * N + n)       = v0;
            *(float2*)(C + (long long)(m + 8) * N + n) = v1;
        }
    }
}

// ---------------- positional embedding ----------------
__global__ void pe_kernel(float* __restrict__ pe) {
    int s = blockIdx.x;
    int j = threadIdx.x;
    float div = expf((float)(2*j) * (-9.210340371976184f / (float)D_));
    float arg = (float)s * div;
    pe[s*D_ + 2*j]     = sinf(arg);
    pe[s*D_ + 2*j + 1] = cosf(arg);
}

__global__ void add_pe_kernel(const float* __restrict__ qa,
                              const float* __restrict__ pe,
                              float* __restrict__ y) {
    int i = blockIdx.x * 256 + threadIdx.x;
    y[i] = qa[i] + pe[i & (S_*D_ - 1)];
}

// ---------------- MoE gate + combine + LN + PE -> x ----------------
__global__ __launch_bounds__(256) void moe_kernel(
    const float* __restrict__ summary, const float* __restrict__ m_seq,
    const float* __restrict__ gate_w,  const float* __restrict__ gate_b,
    const float* __restrict__ experts,
    const float* __restrict__ lng, const float* __restrict__ lnb,
    const float* __restrict__ pe, float* __restrict__ x)
{
    __shared__ float red[4][8];
    __shared__ float wgt[4];
    __shared__ float r1[8], r2[8];

    const int row = blockIdx.x;
    const int tid = threadIdx.x;
    const int s_idx = row & (S_ - 1);

    float p0 = 0, p1 = 0, p2 = 0, p3 = 0;
    for (int e = tid; e < D_ + SD_; e += 256) {
        float xv = (e < D_) ? summary[(long long)row * D_ + e]
                            : m_seq[(long long)row * SD_ + (e - D_)];
        float4 w = *(const float4*)(gate_w + e * 4);
        p0 += xv * w.x; p1 += xv * w.y; p2 += xv * w.z; p3 += xv * w.w;
    }
    #pragma unroll
    for (int o = 16; o > 0; o >>= 1) {
        p0 += __shfl_xor_sync(0xffffffffu, p0, o);
        p1 += __shfl_xor_sync(0xffffffffu, p1, o);
        p2 += __shfl_xor_sync(0xffffffffu, p2, o);
        p3 += __shfl_xor_sync(0xffffffffu, p3, o);
    }
    if ((tid & 31) == 0) {
        int w = tid >> 5;
        red[0][w] = p0; red[1][w] = p1; red[2][w] = p2; red[3][w] = p3;
    }
    __syncthreads();

    if (tid == 0) {
        float l[4];
        #pragma unroll
        for (int j = 0; j < 4; j++) {
            float t = gate_b[j];
            #pragma unroll
            for (int w = 0; w < 8; w++) t += red[j][w];
            l[j] = t;
        }
        float m1 = -INFINITY, m2 = -INFINITY;
        #pragma unroll
        for (int j = 0; j < 4; j++) {
            if (l[j] > m1) { m2 = m1; m1 = l[j]; }
            else if (l[j] > m2) { m2 = l[j]; }
        }
        float sum = 0.f, e4[4];
        #pragma unroll
        for (int j = 0; j < 4; j++) {
            e4[j] = (l[j] >= m2) ? __expf(l[j] - m1) : 0.f;
            sum += e4[j];
        }
        #pragma unroll
        for (int j = 0; j < 4; j++) wgt[j] = e4[j] / sum;
    }
    __syncthreads();

    const float w0 = wgt[0], w1 = wgt[1], w2 = wgt[2], w3 = wgt[3];
    const long long base = (long long)row * D_;
    const int t2 = tid + 256;
    float c0 = w0 * experts[0*BSD + base + tid] + w1 * experts[1*BSD + base + tid]
             + w2 * experts[2*BSD + base + tid] + w3 * experts[3*BSD + base + tid];
    float c1 = w0 * experts[0*BSD + base + t2]  + w1 * experts[1*BSD + base + t2]
             + w2 * experts[2*BSD + base + t2]  + w3 * experts[3*BSD + base + t2];

    float s = c0 + c1, q = c0 * c0 + c1 * c1;
    #pragma unroll
    for (int o = 16; o > 0; o >>= 1) {
        s += __shfl_xor_sync(0xffffffffu, s, o);
        q += __shfl_xor_sync(0xffffffffu, q, o);
    }
    if ((tid & 31) == 0) { r1[tid >> 5] = s; r2[tid >> 5] = q; }
    __syncthreads();
    float ts = 0, tq = 0;
    #pragma unroll
    for (int w = 0; w < 8; w++) { ts += r1[w]; tq += r2[w]; }
    float mu = ts * (1.f / 512.f);
    float var = tq * (1.f / 512.f) - mu * mu;
    float rstd = rsqrtf(var + 1e-5f);

    x[base + tid] = (c0 - mu) * rstd * lng[tid] + lnb[tid] + pe[s_idx * D_ + tid];
    x[base + t2]  = (c1 - mu) * rstd * lng[t2]  + lnb[t2]  + pe[s_idx * D_ + t2];
}

// ---------------- LayerNorm ----------------
__global__ __launch_bounds__(256) void ln_kernel(
    const float* __restrict__ in, const float* __restrict__ g,
    const float* __restrict__ b, float* __restrict__ out)
{
    __shared__ float r1[8], r2[8];
    const int row = blockIdx.x, tid = threadIdx.x;
    const long long base = (long long)row * D_;
    float v0 = in[base + tid], v1 = in[base + tid + 256];
    float s = v0 + v1, q = v0 * v0 + v1 * v1;
    #pragma unroll
    for (int o = 16; o > 0; o >>= 1) {
        s += __shfl_xor_sync(0xffffffffu, s, o);
        q += __shfl_xor_sync(0xffffffffu, q, o);
    }
    if ((tid & 31) == 0) { r1[tid >> 5] = s; r2[tid >> 5] = q; }
    __syncthreads();
    float ts = 0, tq = 0;
    #pragma unroll
    for (int w = 0; w < 8; w++) { ts += r1[w]; tq += r2[w]; }
    float mu = ts * (1.f / 512.f);
    float var = tq * (1.f / 512.f) - mu * mu;
    float rstd = rsqrtf(var + 1e-5f);
    out[base + tid]       = (v0 - mu) * rstd * g[tid]       + b[tid];
    out[base + tid + 256] = (v1 - mu) * rstd * g[tid + 256] + b[tid + 256];
}

// ---------------- flash attention (strict causal, Q == K) ----------------
__global__ __launch_bounds__(128) void attn_kernel(
    const float* __restrict__ Kg, const float* __restrict__ Vg,
    float* __restrict__ Og)
{
    __shared__ float Ks[64][64];
    __shared__ float Vs[64][64];

    const int m0 = blockIdx.x * 128;
    const int h  = blockIdx.y;
    const int b  = blockIdx.z;
    const int tid = threadIdx.x;
    const int row = m0 + tid;

    const float* Kbh = Kg + ((long long)b * S_) * D_ + h * DK_;
    const float* Vbh = Vg + ((long long)b * S_) * D_ + h * DK_;

    float4 q[16], acc[16];
    {
        const float4* qp = (const float4*)(Kbh + (long long)row * D_);
        #pragma unroll
        for (int i = 0; i < 16; i++) { q[i] = qp[i]; acc[i] = make_float4(0.f,0.f,0.f,0.f); }
    }
    float mmax = -INFINITY, lsum = 0.f;

    const int ntiles = (m0 + 190) / 64;
    for (int t = 0; t < ntiles; t++) {
        __syncthreads();
        #pragma unroll
        for (int i = 0; i < 8; i++) {
            int idx = tid + i * 128;
            int r = idx >> 4, c = (idx & 15) * 4;
            *(float4*)&Ks[r][c] = *(const float4*)(Kbh + (long long)(t*64 + r) * D_ + c);
            *(float4*)&Vs[r][c] = *(const float4*)(Vbh + (long long)(t*64 + r) * D_ + c);
        }
        __syncthreads();

        const int kbase = t * 64;
        #pragma unroll 1
        for (int c0 = 0; c0 < 64; c0 += 16) {
            float sc[16];
            float cmax = -INFINITY;
            #pragma unroll
            for (int jj = 0; jj < 16; jj++) {
                const float4* kr = (const float4*)(&Ks[c0 + jj][0]);
                float d0 = 0, d1 = 0, d2 = 0, d3 = 0;
                #pragma unroll
                for (int d4 = 0; d4 < 16; d4++) {
                    float4 kv = kr[d4];
                    d0 += q[d4].x * kv.x; d1 += q[d4].y * kv.y;
                    d2 += q[d4].z * kv.z; d3 += q[d4].w * kv.w;
                }
                float dot = (d0 + d1) + (d2 + d3);
                sc[jj] = (kbase + c0 + jj < row) ? dot * 0.125f : -INFINITY;
                cmax = fmaxf(cmax, sc[jj]);
            }
            if (cmax == -INFINITY) continue;
            float mnew = fmaxf(mmax, cmax);
            float corr = __expf(mmax - mnew);
            lsum *= corr;
            #pragma unroll
            for (int i = 0; i < 16; i++) {
                acc[i].x *= corr; acc[i].y *= corr; acc[i].z *= corr; acc[i].w *= corr;
            }
            mmax = mnew;
            #pragma unroll
            for (int jj = 0; jj < 16; jj++) {
                float p = __expf(sc[jj] - mnew);
                lsum += p;
                const float4* vr = (const float4*)(&Vs[c0 + jj][0]);
                #pragma unroll
                for (int d4 = 0; d4 < 16; d4++) {
                    float4 vv = vr[d4];
                    acc[d4].x += p * vv.x; acc[d4].y += p * vv.y;
                    acc[d4].z += p * vv.z; acc[d4].w += p * vv.w;
                }
            }
        }
    }

    float inv = (lsum > 0.f) ? 1.f / lsum : 0.f;
    float4* op = (float4*)(Og + ((long long)b * S_ + row) * D_ + h * DK_);
    #pragma unroll
    for (int i = 0; i < 16; i++) {
        op[i] = make_float4(acc[i].x * inv, acc[i].y * inv, acc[i].z * inv, acc[i].w * inv);
    }
}

// ================= host-side GEMM wrapper ====================================
static void gemm_bf3(const float* A, int rowStride, long long zOffA, int M, int K,
                     const float* Bw, long long sBz, int N, int nz,
                     const float* bias, int sBias, const float* res,
                     float* C, long long sC, int relu,
                     __nv_bfloat16* abf, __nv_bfloat16* bbf, int shareA)
{
    int kq = K >> 2;
    int blocksA = (M * kq + 255) / 256;
    convA_kernel<<<dim3(blocksA, 1, shareA ? 1 : nz), 256>>>(A, rowStride, zOffA, K, abf, M);
    convB_kernel<<<dim3(K/32, N/32, nz), dim3(32, 8)>>>(Bw, sBz, K, N, bbf);
    long long sA = shareA ? 0LL : (long long)M * 3LL * K;
    gemm_bf3_kernel<<<dim3(N/128, M/128, nz), 256, G_SMEM_TOTAL>>>(
        abf, sA, bbf, (long long)N * 3LL * K, bias, sBias, res, C, sC, N, 3*K, relu);
}

// ================= launch ====================================================
extern "C" void kernel_launch(void* const* d_in, const int* in_sizes, int n_in,
                              void* d_out, int out_size)
{
    const float* q_raw   = (const float*)d_in[0];
    const float* m_seq   = (const float*)d_in[1];
    const float* qa      = (const float*)d_in[2];
    const float* exp_w1  = (const float*)d_in[3];
    const float* exp_b1  = (const float*)d_in[4];
    const float* exp_w2  = (const float*)d_in[5];
    const float* exp_b2  = (const float*)d_in[6];
    const float* adapt_w = (const float*)d_in[7];
    const float* adapt_b = (const float*)d_in[8];
    const float* gate_w  = (const float*)d_in[9];
    const float* gate_b  = (const float*)d_in[10];
    const float* moe_g   = (const float*)d_in[11];
    const float* moe_b   = (const float*)d_in[12];
    const float* kw      = (const float*)d_in[13];
    const float* kb      = (const float*)d_in[14];
    const float* vw      = (const float*)d_in[15];
    const float* vb      = (const float*)d_in[16];
    const float* ow      = (const float*)d_in[17];
    const float* ob      = (const float*)d_in[18];
    const float* ln1g    = (const float*)d_in[19];
    const float* ln1b    = (const float*)d_in[20];
    const float* fw1     = (const float*)d_in[21];
    const float* fb1     = (const float*)d_in[22];
    const float* fw2     = (const float*)d_in[23];
    const float* fb2     = (const float*)d_in[24];
    const float* ln2g    = (const float*)d_in[25];
    const float* ln2b    = (const float*)d_in[26];

    float *pe, *y, *h1, *experts, *summary, *x, *v, *kk, *ctx, *ffn;
    __nv_bfloat16 *abf, *bbf;
    cudaGetSymbolAddress((void**)&pe, g_pe);
    cudaGetSymbolAddress((void**)&y, g_y);
    cudaGetSymbolAddress((void**)&h1, g_h1);
    cudaGetSymbolAddress((void**)&experts, g_experts);
    cudaGetSymbolAddress((void**)&summary, g_summary);
    cudaGetSymbolAddress((void**)&x, g_x);
    cudaGetSymbolAddress((void**)&v, g_v);
    cudaGetSymbolAddress((void**)&kk, g_k);
    cudaGetSymbolAddress((void**)&ctx, g_ctx);
    cudaGetSymbolAddress((void**)&ffn, g_ffn);
    cudaGetSymbolAddress((void**)&abf, g_abf);
    cudaGetSymbolAddress((void**)&bbf, g_bbf);

    static int smem_set = 0;
    if (!smem_set) {
        cudaFuncSetAttribute(gemm_bf3_kernel,
                             cudaFuncAttributeMaxDynamicSharedMemorySize, G_SMEM_TOTAL);
        smem_set = 1;
    }

    pe_kernel<<<S_, 256>>>(pe);
    add_pe_kernel<<<(int)(BSD / 256), 256>>>(qa, pe, y);

    // MoE experts: h1 = relu(q_raw[z] @ exp_w1[z] + b1)
    gemm_bf3(q_raw, NS_*IN_, IN_, BS, IN_, exp_w1, (long long)IN_*IN_, IN_, NS_,
             exp_b1, IN_, nullptr, h1, (long long)BS*IN_, 1, abf, bbf, 0);
    // experts = h1[z] @ exp_w2[z] + b2
    gemm_bf3(h1, IN_, (long long)BS*IN_, BS, IN_, exp_w2, (long long)IN_*D_, D_, NS_,
             exp_b2, D_, nullptr, experts, BSD, 0, abf, bbf, 0);
    // summary = relu(q_flat @ adapt_w + adapt_b)
    gemm_bf3(q_raw, NS_*IN_, 0, BS, NS_*IN_, adapt_w, 0, D_, 1,
             adapt_b, 0, nullptr, summary, 0, 1, abf, bbf, 0);

    moe_kernel<<<BS, 256>>>(summary, m_seq, gate_w, gate_b, experts,
                            moe_g, moe_b, pe, x);

    // all 4 layers' V = y @ vw[i] + vb[i] (y layer-invariant, A shared across z)
    gemm_bf3(y, D_, 0, BS, D_, vw, (long long)D_*D_, D_, L_,
             vb, D_, nullptr, v, BSD, 0, abf, bbf, 1);

    for (int i = 0; i < L_; i++) {
        gemm_bf3(x, D_, 0, BS, D_, kw + (long long)i*D_*D_, 0, D_, 1,
                 kb + i*D_, 0, nullptr, kk, 0, 0, abf, bbf, 0);
        attn_kernel<<<dim3(S_/128, H_, B_), 128>>>(kk, v + (long long)i*BSD, ctx);
        gemm_bf3(ctx, D_, 0, BS, D_, ow + (long long)i*D_*D_, 0, D_, 1,
                 ob + i*D_, 0, x, x, 0, 0, abf, bbf, 0);
        ln_kernel<<<BS, 256>>>(x, ln1g + i*D_, ln1b + i*D_, x);
        gemm_bf3(x, D_, 0, BS, D_, fw1 + (long long)i*D_*FF_, 0, FF_, 1,
                 fb1 + i*FF_, 0, nullptr, ffn, 0, 1, abf, bbf, 0);
        gemm_bf3(ffn, FF_, 0, BS, FF_, fw2 + (long long)i*FF_*D_, 0, D_, 1,
                 fb2 + i*D_, 0, x, x, 0, 0, abf, bbf, 0);
        ln_kernel<<<BS, 256>>>(x, ln2g + i*D_, ln2b + i*D_,
                               (i == L_-1) ? (float*)d_out : x);
    }
}

// round 4
// speedup vs baseline: 2.9307x; 1.5999x over previous
#include <cuda_runtime.h>
#include <cuda_bf16.h>
#include <cstdint>
#include <math.h>

// Problem dims
#define B_  4
#define S_  1024
#define D_  512
#define H_  8
#define DK_ 64
#define FF_ 2048
#define L_  4
#define IN_ 768
#define NS_ 4
#define SD_ 64

#define BS  (B_*S_)            // 4096
#define BSD ((long long)BS*D_) // 2097152
#define NEG_INF __int_as_float(0xff800000)

// ---------------- scratch (device globals: allocation-free) ----------------
__device__ float g_pe[S_*D_];
__device__ float g_y[BS*D_];
__device__ float g_h1[NS_*BS*IN_];
__device__ float g_experts[NS_*BS*D_];
__device__ float g_summary[BS*D_];
__device__ float g_x[BS*D_];
__device__ float g_v[L_*BS*D_];
__device__ float g_k[BS*D_];
__device__ float g_ctx[BS*D_];
__device__ float g_ffn[BS*FF_];
// bf16 split buffers for GEMM
__device__ __nv_bfloat16 g_abf[37748736];
__device__ __nv_bfloat16 g_bbf[7077888];
// attention bf16 buffers: K hi/lo [32][1024][64], Vt hi/lo [32][64][1024]
__device__ __nv_bfloat16 g_khh[32*1024*64];
__device__ __nv_bfloat16 g_khl[32*1024*64];
__device__ __nv_bfloat16 g_vth[32*64*1024];
__device__ __nv_bfloat16 g_vtl[32*64*1024];

// ================= PTX helpers ===============================================
__device__ __forceinline__ uint32_t smem_u32(const void* p) {
    uint32_t a;
    asm("{ .reg .u64 t; cvta.to.shared.u64 t, %1; cvt.u32.u64 %0, t; }" : "=r"(a) : "l"(p));
    return a;
}

__device__ __forceinline__ void cp_async16(uint32_t dst, const void* src) {
    asm volatile("cp.async.cg.shared.global [%0], [%1], 16;" :: "r"(dst), "l"(src));
}
#define CP_COMMIT() asm volatile("cp.async.commit_group;" ::: "memory")
#define CP_WAIT0()  asm volatile("cp.async.wait_group 0;" ::: "memory")
#define CP_WAIT1()  asm volatile("cp.async.wait_group 1;" ::: "memory")

__device__ __forceinline__ void ldsm_x4(uint32_t& r0, uint32_t& r1, uint32_t& r2,
                                        uint32_t& r3, uint32_t addr) {
    asm volatile("ldmatrix.sync.aligned.m8n8.x4.shared.b16 {%0,%1,%2,%3}, [%4];"
        : "=r"(r0), "=r"(r1), "=r"(r2), "=r"(r3) : "r"(addr));
}

__device__ __forceinline__ void mma16816(float* c, const uint32_t* a, const uint32_t* b) {
    asm volatile(
        "mma.sync.aligned.m16n8k16.row.col.f32.bf16.bf16.f32 "
        "{%0,%1,%2,%3}, {%4,%5,%6,%7}, {%8,%9}, {%0,%1,%2,%3};"
        : "+f"(c[0]), "+f"(c[1]), "+f"(c[2]), "+f"(c[3])
        : "r"(a[0]), "r"(a[1]), "r"(a[2]), "r"(a[3]), "r"(b[0]), "r"(b[1]));
}

__device__ __forceinline__ uint32_t pack_bf2(float lo, float hi) {
    uint32_t d;
    asm("cvt.rn.bf16x2.f32 %0, %1, %2;" : "=r"(d) : "f"(hi), "f"(lo));
    return d;
}
__device__ __forceinline__ float bf_lo(uint32_t p) { return __uint_as_float(p << 16); }
__device__ __forceinline__ float bf_hi(uint32_t p) { return __uint_as_float(p & 0xffff0000u); }

// swizzled smem offset: 128B rows of 8x16B chunks, chunk xor (row&7)
__device__ __forceinline__ uint32_t swz(uint32_t base, int r, int ch) {
    return base + r * 128 + ((ch ^ (r & 7)) << 4);
}

// ================= fp32 -> bf16 hi/lo split conversions ======================
__global__ __launch_bounds__(256) void convA_kernel(
    const float* __restrict__ src, int rowStride, long long zOff,
    int K, __nv_bfloat16* __restrict__ dst, int M)
{
    int idx = blockIdx.x * 256 + threadIdx.x;
    int kq = K >> 2;
    if (idx >= M * kq) return;
    int m = idx / kq;
    int k = (idx - m * kq) * 4;
    int z = blockIdx.z;
    float4 v = *(const float4*)(src + (long long)z * zOff + (long long)m * rowStride + k);
    unsigned short hb[4], lb[4];
    float vv[4] = {v.x, v.y, v.z, v.w};
    #pragma unroll
    for (int i = 0; i < 4; i++) {
        __nv_bfloat16 h = __float2bfloat16_rn(vv[i]);
        __nv_bfloat16 l = __float2bfloat16_rn(vv[i] - __bfloat162float(h));
        hb[i] = __bfloat16_as_ushort(h);
        lb[i] = __bfloat16_as_ushort(l);
    }
    uint2 hv = make_uint2((uint32_t)hb[0] | ((uint32_t)hb[1] << 16),
                          (uint32_t)hb[2] | ((uint32_t)hb[3] << 16));
    uint2 lv = make_uint2((uint32_t)lb[0] | ((uint32_t)lb[1] << 16),
                          (uint32_t)lb[2] | ((uint32_t)lb[3] << 16));
    long long base = ((long long)z * M + m) * (3LL * K);
    *(uint2*)(dst + base + k)          = hv;
    *(uint2*)(dst + base + K + k)      = hv;
    *(uint2*)(dst + base + 2LL*K + k)  = lv;
}

__global__ __launch_bounds__(256) void convB_kernel(
    const float* __restrict__ src, long long sBz, int K, int N,
    __nv_bfloat16* __restrict__ dst)
{
    __shared__ float t[32][33];
    int k0 = blockIdx.x * 32, n0 = blockIdx.y * 32, z = blockIdx.z;
    int tx = threadIdx.x, ty = threadIdx.y;
    const float* s = src + (long long)z * sBz;
    #pragma unroll
    for (int r = ty; r < 32; r += 8)
        t[r][tx] = s[(long long)(k0 + r) * N + n0 + tx];
    __syncthreads();
    #pragma unroll
    for (int r = ty; r < 32; r += 8) {
        float x = t[tx][r];
        __nv_bfloat16 h = __float2bfloat16_rn(x);
        __nv_bfloat16 l = __float2bfloat16_rn(x - __bfloat162float(h));
        long long base = ((long long)z * N + (n0 + r)) * (3LL * K) + k0 + tx;
        dst[base]          = h;
        dst[base + K]      = l;
        dst[base + 2LL*K]  = h;
    }
}

// kh fp32 [4096][512] -> khh/khl [bh][s][64]
__global__ __launch_bounds__(256) void conv_k_kernel(
    const float* __restrict__ kh,
    __nv_bfloat16* __restrict__ khh, __nv_bfloat16* __restrict__ khl)
{
    int idx = blockIdx.x * 256 + threadIdx.x;     // over BS*D/4
    int row = idx >> 7;
    int c4 = (idx & 127) * 4;
    float4 v = *(const float4*)(kh + (long long)row * D_ + c4);
    int h = c4 >> 6, d = c4 & 63;
    int b = row >> 10, s = row & 1023;
    long long o = (((long long)(b*8 + h)) * S_ + s) * 64 + d;
    unsigned short hb[4], lb[4];
    float vv[4] = {v.x, v.y, v.z, v.w};
    #pragma unroll
    for (int i = 0; i < 4; i++) {
        __nv_bfloat16 hh = __float2bfloat16_rn(vv[i]);
        __nv_bfloat16 ll = __float2bfloat16_rn(vv[i] - __bfloat162float(hh));
        hb[i] = __bfloat16_as_ushort(hh);
        lb[i] = __bfloat16_as_ushort(ll);
    }
    *(uint2*)(khh + o) = make_uint2((uint32_t)hb[0] | ((uint32_t)hb[1] << 16),
                                    (uint32_t)hb[2] | ((uint32_t)hb[3] << 16));
    *(uint2*)(khl + o) = make_uint2((uint32_t)lb[0] | ((uint32_t)lb[1] << 16),
                                    (uint32_t)lb[2] | ((uint32_t)lb[3] << 16));
}

// v fp32 slice [4096][512] -> vth/vtl [bh][64][1024] (transposed per head)
__global__ __launch_bounds__(256) void conv_vt_kernel(
    const float* __restrict__ v,
    __nv_bfloat16* __restrict__ vth, __nv_bfloat16* __restrict__ vtl)
{
    __shared__ float t[32][33];
    int s0 = blockIdx.x * 32, d0 = blockIdx.y * 32, bh = blockIdx.z;
    int b = bh >> 3, h = bh & 7;
    int tx = threadIdx.x, ty = threadIdx.y;
    #pragma unroll
    for (int r = ty; r < 32; r += 8)
        t[r][tx] = v[((long long)(b*S_ + s0 + r)) * D_ + h*64 + d0 + tx];
    __syncthreads();
    #pragma unroll
    for (int r = ty; r < 32; r += 8) {
        float x = t[tx][r];
        __nv_bfloat16 hh = __float2bfloat16_rn(x);
        __nv_bfloat16 ll = __float2bfloat16_rn(x - __bfloat162float(hh));
        long long o = ((long long)bh * 64 + d0 + r) * S_ + s0 + tx;
        vth[o] = hh;
        vtl[o] = ll;
    }
}

// ================= mma.sync bf16 GEMM, 128x128 tile, BK=64, K'=3K ============
#define G_SMEM_TOTAL 65536

__global__ __launch_bounds__(256) void gemm_bf3_kernel(
    const __nv_bfloat16* __restrict__ A, long long sA,
    const __nv_bfloat16* __restrict__ Bt, long long sB,
    const float* __restrict__ bias, int sBias,
    const float* __restrict__ res,
    float* __restrict__ C, long long sC,
    int N, int K3, int relu)
{
    extern __shared__ __align__(1024) char smem[];

    const int tid = threadIdx.x;
    const int wid = tid >> 5, lane = tid & 31;
    const int wy = wid >> 2, wx = wid & 3;
    const int z = blockIdx.z;
    const int brow = blockIdx.y * 128, bcol = blockIdx.x * 128;

    A  += (long long)z * sA + (long long)brow * K3;
    Bt += (long long)z * sB + (long long)bcol * K3;
    C  += (long long)z * sC;
    if (bias) bias += (long long)z * sBias;

    const uint32_t sb = smem_u32(smem);

    float acc[4][4][4] = {};
    const int NC = K3 >> 6;

    auto load_tile = [&](int c, int s) {
        const long long kc = (long long)c * 64;
        const uint32_t baseA = sb + s * 16384;
        const uint32_t baseB = sb + 32768 + s * 16384;
        #pragma unroll
        for (int i = 0; i < 4; i++) {
            int idx = tid + i * 256;
            int r = idx >> 3, ch = idx & 7;
            cp_async16(swz(baseA, r, ch),
                       (const char*)(A + (long long)r * K3 + kc) + ch * 16);
            cp_async16(swz(baseB, r, ch),
                       (const char*)(Bt + (long long)r * K3 + kc) + ch * 16);
        }
        CP_COMMIT();
    };

    load_tile(0, 0);

    for (int c = 0; c < NC; c++) {
        const int s = c & 1;
        CP_WAIT0();
        __syncthreads();
        if (c + 1 < NC) load_tile(c + 1, s ^ 1);

        const uint32_t baseA = sb + s * 16384;
        const uint32_t baseB = sb + 32768 + s * 16384;

        #pragma unroll
        for (int ks = 0; ks < 4; ks++) {
            const int cb = ks * 2;
            uint32_t af[4][4];
            #pragma unroll
            for (int ms = 0; ms < 4; ms++) {
                int r = wy * 64 + ms * 16 + (lane & 15);
                ldsm_x4(af[ms][0], af[ms][1], af[ms][2], af[ms][3],
                        swz(baseA, r, cb + (lane >> 4)));
            }
            uint32_t bf[4][2];
            #pragma unroll
            for (int nh = 0; nh < 2; nh++) {
                int g = lane >> 3;
                int r = wx * 32 + nh * 16 + ((g & 2) << 2) + (lane & 7);
                uint32_t r0, r1, r2, r3;
                ldsm_x4(r0, r1, r2, r3, swz(baseB, r, cb + (g & 1)));
                bf[nh*2][0] = r0; bf[nh*2][1] = r1;
                bf[nh*2+1][0] = r2; bf[nh*2+1][1] = r3;
            }
            #pragma unroll
            for (int ms = 0; ms < 4; ms++)
                #pragma unroll
                for (int ns = 0; ns < 4; ns++)
                    mma16816(acc[ms][ns], af[ms], bf[ns]);
        }
        __syncthreads();
    }

    const int qrow = lane >> 2, qcol = (lane & 3) * 2;
    #pragma unroll
    for (int ms = 0; ms < 4; ms++) {
        #pragma unroll
        for (int ns = 0; ns < 4; ns++) {
            int m = brow + wy * 64 + ms * 16 + qrow;
            int n = bcol + wx * 32 + ns * 8 + qcol;
            float2 v0 = make_float2(acc[ms][ns][0], acc[ms][ns][1]);
            float2 v1 = make_float2(acc[ms][ns][2], acc[ms][ns][3]);
            if (bias) {
                float b0 = bias[n], b1 = bias[n + 1];
                v0.x += b0; v0.y += b1; v1.x += b0; v1.y += b1;
            }
            if (res) {
                float2 r0 = *(const float2*)(res + (long long)m * N + n);
                float2 r1 = *(const float2*)(res + (long long)(m + 8) * N + n);
                v0.x += r0.x; v0.y += r0.y; v1.x += r1.x; v1.y += r1.y;
            }
            if (relu) {
                v0.x = fmaxf(v0.x, 0.f); v0.y = fmaxf(v0.y, 0.f);
                v1.x = fmaxf(v1.x, 0.f); v1.y = fmaxf(v1.y, 0.f);
            }
            *(float2*)(C + (long long)m * N + n)       = v0;
            *(float2*)(C + (long long)(m + 8) * N + n) = v1;
        }
    }
}

// ================= tensor-core flash attention ===============================
// grid (16, 32): qb = 15 - bx (64 q-rows), bh. 4 warps x 16 rows.
// smem: Qhi @0 (8K), Qlo @8K; KV buffers @16K + s*32K:
//       {Khi 0, Klo 8K, Vthi 16K, Vtlo 24K}, each 64 rows x 128B swizzled.
#define ATTN_SMEM 81920

__global__ __launch_bounds__(128) void attn_mma_kernel(
    const __nv_bfloat16* __restrict__ khh, const __nv_bfloat16* __restrict__ khl,
    const __nv_bfloat16* __restrict__ vth, const __nv_bfloat16* __restrict__ vtl,
    float* __restrict__ Og)
{
    extern __shared__ __align__(1024) char smem[];
    const uint32_t sb = smem_u32(smem);
    const int tid = threadIdx.x, wid = tid >> 5, lane = tid & 31;
    const int qb = 15 - blockIdx.x;
    const int bh = blockIdx.y;
    const int q0 = qb * 64;

    const __nv_bfloat16* Kh = khh + (long long)bh * S_ * 64;
    const __nv_bfloat16* Kl = khl + (long long)bh * S_ * 64;
    const __nv_bfloat16* Vh = vth + (long long)bh * 64 * S_;
    const __nv_bfloat16* Vl = vtl + (long long)bh * 64 * S_;

    auto load_kv = [&](int jt, int s) {
        const int j0 = jt * 64;
        const uint32_t base = sb + 16384 + s * 32768;
        #pragma unroll
        for (int i = 0; i < 4; i++) {
            int idx = tid + i * 128;
            int r = idx >> 3, ch = idx & 7;
            cp_async16(swz(base, r, ch),
                       (const char*)(Kh + (long long)(j0 + r) * 64) + ch * 16);
            cp_async16(swz(base + 8192, r, ch),
                       (const char*)(Kl + (long long)(j0 + r) * 64) + ch * 16);
            cp_async16(swz(base + 16384, r, ch),
                       (const char*)(Vh + (long long)r * S_ + j0) + ch * 16);
            cp_async16(swz(base + 24576, r, ch),
                       (const char*)(Vl + (long long)r * S_ + j0) + ch * 16);
        }
        CP_COMMIT();
    };

    // preload Q (= K rows q0..q0+63) and KV tile 0 in one group
    #pragma unroll
    for (int i = 0; i < 4; i++) {
        int idx = tid + i * 128;
        int r = idx >> 3, ch = idx & 7;
        cp_async16(swz(sb, r, ch),
                   (const char*)(Kh + (long long)(q0 + r) * 64) + ch * 16);
        cp_async16(swz(sb + 8192, r, ch),
                   (const char*)(Kl + (long long)(q0 + r) * 64) + ch * 16);
    }
    load_kv(0, 0);
    CP_WAIT0();
    __syncthreads();

    // extract Q fragments (m16k16 per k-step)
    uint32_t qh[4][4], ql[4][4];
    #pragma unroll
    for (int ks = 0; ks < 4; ks++) {
        int r = wid * 16 + (lane & 15);
        int ch = 2 * ks + (lane >> 4);
        ldsm_x4(qh[ks][0], qh[ks][1], qh[ks][2], qh[ks][3], swz(sb, r, ch));
        ldsm_x4(ql[ks][0], ql[ks][1], ql[ks][2], ql[ks][3], swz(sb + 8192, r, ch));
    }

    float ctx[8][4] = {};
    float m0 = NEG_INF, m1 = NEG_INF, l0 = 0.f, l1 = 0.f;
    const int rg0 = q0 + wid * 16 + (lane >> 2);     // global row (half 0)

    for (int jt = 0; jt <= qb; jt++) {
        const int s = jt & 1;
        if (jt < qb) { load_kv(jt + 1, s ^ 1); CP_WAIT1(); }
        else if (jt > 0) { CP_WAIT0(); }
        __syncthreads();

        const uint32_t bK = sb + 16384 + s * 32768;

        // ---- scores: Qh·Kh + Qh·Kl + Ql·Kh ----
        float sc[8][4] = {};
        #pragma unroll
        for (int ks = 0; ks < 4; ks++) {
            uint32_t bh_[8][2], bl_[8][2];
            #pragma unroll
            for (int ng = 0; ng < 4; ng++) {
                int g = lane >> 3;
                int r = ng * 16 + ((g & 2) << 2) + (lane & 7);
                int ch = 2 * ks + (g & 1);
                uint32_t a0, a1, a2, a3;
                ldsm_x4(a0, a1, a2, a3, swz(bK, r, ch));
                bh_[2*ng][0] = a0; bh_[2*ng][1] = a1;
                bh_[2*ng+1][0] = a2; bh_[2*ng+1][1] = a3;
                ldsm_x4(a0, a1, a2, a3, swz(bK + 8192, r, ch));
                bl_[2*ng][0] = a0; bl_[2*ng][1] = a1;
                bl_[2*ng+1][0] = a2; bl_[2*ng+1][1] = a3;
            }
            #pragma unroll
            for (int nt = 0; nt < 8; nt++) {
                mma16816(sc[nt], qh[ks], bh_[nt]);
                mma16816(sc[nt], qh[ks], bl_[nt]);
                mma16816(sc[nt], ql[ks], bh_[nt]);
            }
        }

        // ---- online softmax ----
        const int j0 = jt * 64;
        const bool diag = (jt == qb);
        const int cb0 = j0 + (lane & 3) * 2;
        float rm0 = NEG_INF, rm1 = NEG_INF;
        #pragma unroll
        for (int nt = 0; nt < 8; nt++) {
            int c0 = cb0 + nt * 8, c1 = c0 + 1;
            float s0 = sc[nt][0] * 0.125f, s1 = sc[nt][1] * 0.125f;
            float s2 = sc[nt][2] * 0.125f, s3 = sc[nt][3] * 0.125f;
            if (diag) {
                if (c0 >= rg0)     s0 = NEG_INF;
                if (c1 >= rg0)     s1 = NEG_INF;
                if (c0 >= rg0 + 8) s2 = NEG_INF;
                if (c1 >= rg0 + 8) s3 = NEG_INF;
            }
            sc[nt][0] = s0; sc[nt][1] = s1; sc[nt][2] = s2; sc[nt][3] = s3;
            rm0 = fmaxf(rm0, fmaxf(s0, s1));
            rm1 = fmaxf(rm1, fmaxf(s2, s3));
        }
        #pragma unroll
        for (int o = 1; o <= 2; o <<= 1) {
            rm0 = fmaxf(rm0, __shfl_xor_sync(0xffffffffu, rm0, o));
            rm1 = fmaxf(rm1, __shfl_xor_sync(0xffffffffu, rm1, o));
        }
        float mn0 = fmaxf(m0, rm0), mn1 = fmaxf(m1, rm1);
        float ms0 = (mn0 == NEG_INF) ? 0.f : mn0;
        float ms1 = (mn1 == NEG_INF) ? 0.f : mn1;
        float cr0 = __expf(m0 - ms0), cr1 = __expf(m1 - ms1);
        float rs0 = 0.f, rs1 = 0.f;
        #pragma unroll
        for (int nt = 0; nt < 8; nt++) {
            sc[nt][0] = __expf(sc[nt][0] - ms0); rs0 += sc[nt][0];
            sc[nt][1] = __expf(sc[nt][1] - ms0); rs0 += sc[nt][1];
            sc[nt][2] = __expf(sc[nt][2] - ms1); rs1 += sc[nt][2];
            sc[nt][3] = __expf(sc[nt][3] - ms1); rs1 += sc[nt][3];
        }
        #pragma unroll
        for (int o = 1; o <= 2; o <<= 1) {
            rs0 += __shfl_xor_sync(0xffffffffu, rs0, o);
            rs1 += __shfl_xor_sync(0xffffffffu, rs1, o);
        }
        l0 = l0 * cr0 + rs0; l1 = l1 * cr1 + rs1;
        m0 = mn0; m1 = mn1;
        #pragma unroll
        for (int nt = 0; nt < 8; nt++) {
            ctx[nt][0] *= cr0; ctx[nt][1] *= cr0;
            ctx[nt][2] *= cr1; ctx[nt][3] *= cr1;
        }

        // ---- pack P into hi/lo A-fragments (C-frag -> A-frag identity) ----
        uint32_t ph[4][4], pl[4][4];
        #pragma unroll
        for (int kj = 0; kj < 4; kj++) {
            const int t0 = 2 * kj, t1 = 2 * kj + 1;
            ph[kj][0] = pack_bf2(sc[t0][0], sc[t0][1]);
            ph[kj][1] = pack_bf2(sc[t0][2], sc[t0][3]);
            ph[kj][2] = pack_bf2(sc[t1][0], sc[t1][1]);
            ph[kj][3] = pack_bf2(sc[t1][2], sc[t1][3]);
            pl[kj][0] = pack_bf2(sc[t0][0] - bf_lo(ph[kj][0]), sc[t0][1] - bf_hi(ph[kj][0]));
            pl[kj][1] = pack_bf2(sc[t0][2] - bf_lo(ph[kj][1]), sc[t0][3] - bf_hi(ph[kj][1]));
            pl[kj][2] = pack_bf2(sc[t1][0] - bf_lo(ph[kj][2]), sc[t1][1] - bf_hi(ph[kj][2]));
            pl[kj][3] = pack_bf2(sc[t1][2] - bf_lo(ph[kj][3]), sc[t1][3] - bf_hi(ph[kj][3]));
        }

        // ---- ctx += Ph·Vh + Ph·Vl + Pl·Vh ----
        const uint32_t bV = bK + 16384;
        #pragma unroll
        for (int kj = 0; kj < 4; kj++) {
            uint32_t vh_[8][2], vl_[8][2];
            #pragma unroll
            for (int dg = 0; dg < 4; dg++) {
                int g = lane >> 3;
                int r = dg * 16 + ((g & 2) << 2) + (lane & 7);
                int ch = 2 * kj + (g & 1);
                uint32_t a0, a1, a2, a3;
                ldsm_x4(a0, a1, a2, a3, swz(bV, r, ch));
                vh_[2*dg][0] = a0; vh_[2*dg][1] = a1;
                vh_[2*dg+1][0] = a2; vh_[2*dg+1][1] = a3;
                ldsm_x4(a0, a1, a2, a3, swz(bV + 8192, r, ch));
                vl_[2*dg][0] = a0; vl_[2*dg][1] = a1;
                vl_[2*dg+1][0] = a2; vl_[2*dg+1][1] = a3;
            }
            #pragma unroll
            for (int nt = 0; nt < 8; nt++) {
                mma16816(ctx[nt], ph[kj], vh_[nt]);
                mma16816(ctx[nt], ph[kj], vl_[nt]);
                mma16816(ctx[nt], pl[kj], vh_[nt]);
            }
        }
        __syncthreads();
    }

    // ---- epilogue: normalize and write ----
    float inv0 = (l0 > 0.f) ? 1.f / l0 : 0.f;
    float inv1 = (l1 > 0.f) ? 1.f / l1 : 0.f;
    const int b = bh >> 3, h = bh & 7;
    const int row0 = b * S_ + q0 + wid * 16 + (lane >> 2);
    const int colb = h * 64 + (lane & 3) * 2;
    #pragma unroll
    for (int nt = 0; nt < 8; nt++) {
        *(float2*)(Og + (long long)row0 * D_ + colb + nt * 8) =
            make_float2(ctx[nt][0] * inv0, ctx[nt][1] * inv0);
        *(float2*)(Og + (long long)(row0 + 8) * D_ + colb + nt * 8) =
            make_float2(ctx[nt][2] * inv1, ctx[nt][3] * inv1);
    }
}

// ---------------- positional embedding ----------------
__global__ void pe_kernel(float* __restrict__ pe) {
    int s = blockIdx.x;
    int j = threadIdx.x;
    float div = expf((float)(2*j) * (-9.210340371976184f / (float)D_));
    float arg = (float)s * div;
    pe[s*D_ + 2*j]     = sinf(arg);
    pe[s*D_ + 2*j + 1] = cosf(arg);
}

__global__ void add_pe_kernel(const float* __restrict__ qa,
                              const float* __restrict__ pe,
                              float* __restrict__ y) {
    int i = blockIdx.x * 256 + threadIdx.x;
    y[i] = qa[i] + pe[i & (S_*D_ - 1)];
}

// ---------------- MoE gate + combine + LN + PE -> x ----------------
__global__ __launch_bounds__(256) void moe_kernel(
    const float* __restrict__ summary, const float* __restrict__ m_seq,
    const float* __restrict__ gate_w,  const float* __restrict__ gate_b,
    const float* __restrict__ experts,
    const float* __restrict__ lng, const float* __restrict__ lnb,
    const float* __restrict__ pe, float* __restrict__ x)
{
    __shared__ float red[4][8];
    __shared__ float wgt[4];
    __shared__ float r1[8], r2[8];

    const int row = blockIdx.x;
    const int tid = threadIdx.x;
    const int s_idx = row & (S_ - 1);

    float p0 = 0, p1 = 0, p2 = 0, p3 = 0;
    for (int e = tid; e < D_ + SD_; e += 256) {
        float xv = (e < D_) ? summary[(long long)row * D_ + e]
                            : m_seq[(long long)row * SD_ + (e - D_)];
        float4 w = *(const float4*)(gate_w + e * 4);
        p0 += xv * w.x; p1 += xv * w.y; p2 += xv * w.z; p3 += xv * w.w;
    }
    #pragma unroll
    for (int o = 16; o > 0; o >>= 1) {
        p0 += __shfl_xor_sync(0xffffffffu, p0, o);
        p1 += __shfl_xor_sync(0xffffffffu, p1, o);
        p2 += __shfl_xor_sync(0xffffffffu, p2, o);
        p3 += __shfl_xor_sync(0xffffffffu, p3, o);
    }
    if ((tid & 31) == 0) {
        int w = tid >> 5;
        red[0][w] = p0; red[1][w] = p1; red[2][w] = p2; red[3][w] = p3;
    }
    __syncthreads();

    if (tid == 0) {
        float l[4];
        #pragma unroll
        for (int j = 0; j < 4; j++) {
            float t = gate_b[j];
            #pragma unroll
            for (int w = 0; w < 8; w++) t += red[j][w];
            l[j] = t;
        }
        float m1v = -INFINITY, m2v = -INFINITY;
        #pragma unroll
        for (int j = 0; j < 4; j++) {
            if (l[j] > m1v) { m2v = m1v; m1v = l[j]; }
            else if (l[j] > m2v) { m2v = l[j]; }
        }
        float sum = 0.f, e4[4];
        #pragma unroll
        for (int j = 0; j < 4; j++) {
            e4[j] = (l[j] >= m2v) ? __expf(l[j] - m1v) : 0.f;
            sum += e4[j];
        }
        #pragma unroll
        for (int j = 0; j < 4; j++) wgt[j] = e4[j] / sum;
    }
    __syncthreads();

    const float w0 = wgt[0], w1 = wgt[1], w2 = wgt[2], w3 = wgt[3];
    const long long base = (long long)row * D_;
    const int t2 = tid + 256;
    float c0 = w0 * experts[0*BSD + base + tid] + w1 * experts[1*BSD + base + tid]
             + w2 * experts[2*BSD + base + tid] + w3 * experts[3*BSD + base + tid];
    float c1 = w0 * experts[0*BSD + base + t2]  + w1 * experts[1*BSD + base + t2]
             + w2 * experts[2*BSD + base + t2]  + w3 * experts[3*BSD + base + t2];

    float s = c0 + c1, q = c0 * c0 + c1 * c1;
    #pragma unroll
    for (int o = 16; o > 0; o >>= 1) {
        s += __shfl_xor_sync(0xffffffffu, s, o);
        q += __shfl_xor_sync(0xffffffffu, q, o);
    }
    if ((tid & 31) == 0) { r1[tid >> 5] = s; r2[tid >> 5] = q; }
    __syncthreads();
    float ts = 0, tq = 0;
    #pragma unroll
    for (int w = 0; w < 8; w++) { ts += r1[w]; tq += r2[w]; }
    float mu = ts * (1.f / 512.f);
    float var = tq * (1.f / 512.f) - mu * mu;
    float rstd = rsqrtf(var + 1e-5f);

    x[base + tid] = (c0 - mu) * rstd * lng[tid] + lnb[tid] + pe[s_idx * D_ + tid];
    x[base + t2]  = (c1 - mu) * rstd * lng[t2]  + lnb[t2]  + pe[s_idx * D_ + t2];
}

// ---------------- LayerNorm ----------------
__global__ __launch_bounds__(256) void ln_kernel(
    const float* __restrict__ in, const float* __restrict__ g,
    const float* __restrict__ b, float* __restrict__ out)
{
    __shared__ float r1[8], r2[8];
    const int row = blockIdx.x, tid = threadIdx.x;
    const long long base = (long long)row * D_;
    float v0 = in[base + tid], v1 = in[base + tid + 256];
    float s = v0 + v1, q = v0 * v0 + v1 * v1;
    #pragma unroll
    for (int o = 16; o > 0; o >>= 1) {
        s += __shfl_xor_sync(0xffffffffu, s, o);
        q += __shfl_xor_sync(0xffffffffu, q, o);
    }
    if ((tid & 31) == 0) { r1[tid >> 5] = s; r2[tid >> 5] = q; }
    __syncthreads();
    float ts = 0, tq = 0;
    #pragma unroll
    for (int w = 0; w < 8; w++) { ts += r1[w]; tq += r2[w]; }
    float mu = ts * (1.f / 512.f);
    float var = tq * (1.f / 512.f) - mu * mu;
    float rstd = rsqrtf(var + 1e-5f);
    out[base + tid]       = (v0 - mu) * rstd * g[tid]       + b[tid];
    out[base + tid + 256] = (v1 - mu) * rstd * g[tid + 256] + b[tid + 256];
}

// ================= host-side GEMM wrapper ====================================
static void gemm_bf3(const float* A, int rowStride, long long zOffA, int M, int K,
                     const float* Bw, long long sBz, int N, int nz,
                     const float* bias, int sBias, const float* res,
                     float* C, long long sC, int relu,
                     __nv_bfloat16* abf, __nv_bfloat16* bbf, int shareA)
{
    int kq = K >> 2;
    int blocksA = (M * kq + 255) / 256;
    convA_kernel<<<dim3(blocksA, 1, shareA ? 1 : nz), 256>>>(A, rowStride, zOffA, K, abf, M);
    convB_kernel<<<dim3(K/32, N/32, nz), dim3(32, 8)>>>(Bw, sBz, K, N, bbf);
    long long sA = shareA ? 0LL : (long long)M * 3LL * K;
    gemm_bf3_kernel<<<dim3(N/128, M/128, nz), 256, G_SMEM_TOTAL>>>(
        abf, sA, bbf, (long long)N * 3LL * K, bias, sBias, res, C, sC, N, 3*K, relu);
}

// ================= launch ====================================================
extern "C" void kernel_launch(void* const* d_in, const int* in_sizes, int n_in,
                              void* d_out, int out_size)
{
    const float* q_raw   = (const float*)d_in[0];
    const float* m_seq   = (const float*)d_in[1];
    const float* qa      = (const float*)d_in[2];
    const float* exp_w1  = (const float*)d_in[3];
    const float* exp_b1  = (const float*)d_in[4];
    const float* exp_w2  = (const float*)d_in[5];
    const float* exp_b2  = (const float*)d_in[6];
    const float* adapt_w = (const float*)d_in[7];
    const float* adapt_b = (const float*)d_in[8];
    const float* gate_w  = (const float*)d_in[9];
    const float* gate_b  = (const float*)d_in[10];
    const float* moe_g   = (const float*)d_in[11];
    const float* moe_b   = (const float*)d_in[12];
    const float* kw      = (const float*)d_in[13];
    const float* kb      = (const float*)d_in[14];
    const float* vw      = (const float*)d_in[15];
    const float* vb      = (const float*)d_in[16];
    const float* ow      = (const float*)d_in[17];
    const float* ob      = (const float*)d_in[18];
    const float* ln1g    = (const float*)d_in[19];
    const float* ln1b    = (const float*)d_in[20];
    const float* fw1     = (const float*)d_in[21];
    const float* fb1     = (const float*)d_in[22];
    const float* fw2     = (const float*)d_in[23];
    const float* fb2     = (const float*)d_in[24];
    const float* ln2g    = (const float*)d_in[25];
    const float* ln2b    = (const float*)d_in[26];

    float *pe, *y, *h1, *experts, *summary, *x, *v, *kk, *ctx, *ffn;
    __nv_bfloat16 *abf, *bbf, *khh, *khl, *vth, *vtl;
    cudaGetSymbolAddress((void**)&pe, g_pe);
    cudaGetSymbolAddress((void**)&y, g_y);
    cudaGetSymbolAddress((void**)&h1, g_h1);
    cudaGetSymbolAddress((void**)&experts, g_experts);
    cudaGetSymbolAddress((void**)&summary, g_summary);
    cudaGetSymbolAddress((void**)&x, g_x);
    cudaGetSymbolAddress((void**)&v, g_v);
    cudaGetSymbolAddress((void**)&kk, g_k);
    cudaGetSymbolAddress((void**)&ctx, g_ctx);
    cudaGetSymbolAddress((void**)&ffn, g_ffn);
    cudaGetSymbolAddress((void**)&abf, g_abf);
    cudaGetSymbolAddress((void**)&bbf, g_bbf);
    cudaGetSymbolAddress((void**)&khh, g_khh);
    cudaGetSymbolAddress((void**)&khl, g_khl);
    cudaGetSymbolAddress((void**)&vth, g_vth);
    cudaGetSymbolAddress((void**)&vtl, g_vtl);

    static int attr_set = 0;
    if (!attr_set) {
        cudaFuncSetAttribute(gemm_bf3_kernel,
                             cudaFuncAttributeMaxDynamicSharedMemorySize, G_SMEM_TOTAL);
        cudaFuncSetAttribute(attn_mma_kernel,
                             cudaFuncAttributeMaxDynamicSharedMemorySize, ATTN_SMEM);
        attr_set = 1;
    }

    pe_kernel<<<S_, 256>>>(pe);
    add_pe_kernel<<<(int)(BSD / 256), 256>>>(qa, pe, y);

    // MoE experts
    gemm_bf3(q_raw, NS_*IN_, IN_, BS, IN_, exp_w1, (long long)IN_*IN_, IN_, NS_,
             exp_b1, IN_, nullptr, h1, (long long)BS*IN_, 1, abf, bbf, 0);
    gemm_bf3(h1, IN_, (long long)BS*IN_, BS, IN_, exp_w2, (long long)IN_*D_, D_, NS_,
             exp_b2, D_, nullptr, experts, BSD, 0, abf, bbf, 0);
    gemm_bf3(q_raw, NS_*IN_, 0, BS, NS_*IN_, adapt_w, 0, D_, 1,
             adapt_b, 0, nullptr, summary, 0, 1, abf, bbf, 0);

    moe_kernel<<<BS, 256>>>(summary, m_seq, gate_w, gate_b, experts,
                            moe_g, moe_b, pe, x);

    // all 4 layers' V = y @ vw[i] + vb[i]
    gemm_bf3(y, D_, 0, BS, D_, vw, (long long)D_*D_, D_, L_,
             vb, D_, nullptr, v, BSD, 0, abf, bbf, 1);

    for (int i = 0; i < L_; i++) {
        gemm_bf3(x, D_, 0, BS, D_, kw + (long long)i*D_*D_, 0, D_, 1,
                 kb + i*D_, 0, nullptr, kk, 0, 0, abf, bbf, 0);
        conv_k_kernel<<<2048, 256>>>(kk, khh, khl);
        conv_vt_kernel<<<dim3(S_/32, 2, 32), dim3(32, 8)>>>(v + (long long)i*BSD, vth, vtl);
        attn_mma_kernel<<<dim3(16, 32), 128, ATTN_SMEM>>>(khh, khl, vth, vtl, ctx);
        gemm_bf3(ctx, D_, 0, BS, D_, ow + (long long)i*D_*D_, 0, D_, 1,
                 ob + i*D_, 0, x, x, 0, 0, abf, bbf, 0);
        ln_kernel<<<BS, 256>>>(x, ln1g + i*D_, ln1b + i*D_, x);
        gemm_bf3(x, D_, 0, BS, D_, fw1 + (long long)i*D_*FF_, 0, FF_, 1,
                 fb1 + i*FF_, 0, nullptr, ffn, 0, 1, abf, bbf, 0);
        gemm_bf3(ffn, FF_, 0, BS, FF_, fw2 + (long long)i*FF_*D_, 0, D_, 1,
                 fb2 + i*D_, 0, x, x, 0, 0, abf, bbf, 0);
        ln_kernel<<<BS, 256>>>(x, ln2g + i*D_, ln2b + i*D_,
                               (i == L_-1) ? (float*)d_out : x);
    }
}

// round 6
// speedup vs baseline: 3.3277x; 1.1355x over previous
#include <cuda_runtime.h>
#include <cuda_bf16.h>
#include <cstdint>
#include <math.h>

// Problem dims
#define B_  4
#define S_  1024
#define D_  512
#define H_  8
#define DK_ 64
#define FF_ 2048
#define L_  4
#define IN_ 768
#define NS_ 4
#define SD_ 64

#define BS  (B_*S_)            // 4096
#define BSD ((long long)BS*D_) // 2097152
#define NEG_INF __int_as_float(0xff800000)

// ---------------- scratch (device globals: allocation-free) ----------------
__device__ float g_pe[S_*D_];
__device__ float g_x[BS*D_];
__device__ float g_experts[NS_*BS*D_];
__device__ float g_summary[BS*D_];
// split bf16 buffers, layout [m][hi K | lo K]
__device__ __nv_bfloat16 g_qbf[25165824];    // q_raw' [4096][6144]
__device__ __nv_bfloat16 g_h1bf[25165824];   // h1'   [4][4096][1536]
__device__ __nv_bfloat16 g_ybf[4194304];     // y'    [4096][1024]
__device__ __nv_bfloat16 g_xbf[4194304];     // x'    [4096][1024]
__device__ __nv_bfloat16 g_ctxbf[4194304];   // ctx'  [4096][1024]
__device__ __nv_bfloat16 g_ffnbf[16777216];  // ffn'  [4096][4096]
__device__ __nv_bfloat16 g_bbf[7077888];     // weight B' [n][2K]
__device__ __nv_bfloat16 g_khh[2097152];     // K hi [32][1024][64]
__device__ __nv_bfloat16 g_khl[2097152];
__device__ __nv_bfloat16 g_vth[8388608];     // Vt hi [4][32][64][1024]
__device__ __nv_bfloat16 g_vtl[8388608];

// ================= PTX helpers ===============================================
__device__ __forceinline__ uint32_t smem_u32(const void* p) {
    uint32_t a;
    asm("{ .reg .u64 t; cvta.to.shared.u64 t, %1; cvt.u32.u64 %0, t; }" : "=r"(a) : "l"(p));
    return a;
}
__device__ __forceinline__ void cp_async16(uint32_t dst, const void* src) {
    asm volatile("cp.async.cg.shared.global [%0], [%1], 16;" :: "r"(dst), "l"(src));
}
#define CP_COMMIT() asm volatile("cp.async.commit_group;" ::: "memory")
#define CP_WAIT0()  asm volatile("cp.async.wait_group 0;" ::: "memory")
#define CP_WAIT1()  asm volatile("cp.async.wait_group 1;" ::: "memory")

__device__ __forceinline__ void ldsm_x4(uint32_t& r0, uint32_t& r1, uint32_t& r2,
                                        uint32_t& r3, uint32_t addr) {
    asm volatile("ldmatrix.sync.aligned.m8n8.x4.shared.b16 {%0,%1,%2,%3}, [%4];"
        : "=r"(r0), "=r"(r1), "=r"(r2), "=r"(r3) : "r"(addr));
}
__device__ __forceinline__ void mma16816(float* c, const uint32_t* a, const uint32_t* b) {
    asm volatile(
        "mma.sync.aligned.m16n8k16.row.col.f32.bf16.bf16.f32 "
        "{%0,%1,%2,%3}, {%4,%5,%6,%7}, {%8,%9}, {%0,%1,%2,%3};"
        : "+f"(c[0]), "+f"(c[1]), "+f"(c[2]), "+f"(c[3])
        : "r"(a[0]), "r"(a[1]), "r"(a[2]), "r"(a[3]), "r"(b[0]), "r"(b[1]));
}
__device__ __forceinline__ uint32_t pack_bf2(float lo, float hi) {
    uint32_t d;
    asm("cvt.rn.bf16x2.f32 %0, %1, %2;" : "=r"(d) : "f"(hi), "f"(lo));
    return d;
}
__device__ __forceinline__ float bf_lo(uint32_t p) { return __uint_as_float(p << 16); }
__device__ __forceinline__ float bf_hi(uint32_t p) { return __uint_as_float(p & 0xffff0000u); }

__device__ __forceinline__ uint32_t swz(uint32_t base, int r, int ch) {
    return base + r * 128 + ((ch ^ (r & 7)) << 4);
}

// ================= conversions ==============================================
// q_raw [4096][3072] fp32 -> q' [4096][6144] = [hi 3072 | lo 3072]
__global__ __launch_bounds__(256) void conv_qraw_kernel(
    const float* __restrict__ src, __nv_bfloat16* __restrict__ dst)
{
    int idx = blockIdx.x * 256 + threadIdx.x;   // over 4096*768 float4s
    int m = idx / 768;
    int k = (idx - m * 768) * 4;
    float4 v = *(const float4*)(src + (long long)m * 3072 + k);
    unsigned short hb[4], lb[4];
    float vv[4] = {v.x, v.y, v.z, v.w};
    #pragma unroll
    for (int i = 0; i < 4; i++) {
        __nv_bfloat16 h = __float2bfloat16_rn(vv[i]);
        __nv_bfloat16 l = __float2bfloat16_rn(vv[i] - __bfloat162float(h));
        hb[i] = __bfloat16_as_ushort(h);
        lb[i] = __bfloat16_as_ushort(l);
    }
    long long base = (long long)m * 6144;
    *(uint2*)(dst + base + k) = make_uint2((uint32_t)hb[0] | ((uint32_t)hb[1] << 16),
                                           (uint32_t)hb[2] | ((uint32_t)hb[3] << 16));
    *(uint2*)(dst + base + 3072 + k) = make_uint2((uint32_t)lb[0] | ((uint32_t)lb[1] << 16),
                                                  (uint32_t)lb[2] | ((uint32_t)lb[3] << 16));
}

// W [z][K][N] fp32 -> B' [z][n][2K] = [hi K | lo K]
__global__ __launch_bounds__(256) void convB_kernel(
    const float* __restrict__ src, long long sBz, int K, int N,
    __nv_bfloat16* __restrict__ dst)
{
    __shared__ float t[32][33];
    int k0 = blockIdx.x * 32, n0 = blockIdx.y * 32, z = blockIdx.z;
    int tx = threadIdx.x, ty = threadIdx.y;
    const float* s = src + (long long)z * sBz;
    #pragma unroll
    for (int r = ty; r < 32; r += 8)
        t[r][tx] = s[(long long)(k0 + r) * N + n0 + tx];
    __syncthreads();
    #pragma unroll
    for (int r = ty; r < 32; r += 8) {
        float x = t[tx][r];
        __nv_bfloat16 h = __float2bfloat16_rn(x);
        __nv_bfloat16 l = __float2bfloat16_rn(x - __bfloat162float(h));
        long long base = ((long long)z * N + (n0 + r)) * (2LL * K) + k0 + tx;
        dst[base]     = h;
        dst[base + K] = l;
    }
}

// ================= unified split GEMM (mma.sync bf16 x3 terms) ===============
// acc = sum_k Ah*Bh + Ah*Bl + Al*Bh over real K. M=4096 fixed.
#define G2_STAGE 65536
#define G2_SMEM  196608

__global__ __launch_bounds__(256, 1) void gemm2_kernel(
    const __nv_bfloat16* __restrict__ Ah0, int loA, int ldA, long long zA,
    const __nv_bfloat16* __restrict__ Bt0, long long zB, int K,
    const float* __restrict__ bias, int sBias,
    const float* __restrict__ res,
    float* __restrict__ C, long long sC,
    __nv_bfloat16* __restrict__ Sp, long long zSp,
    __nv_bfloat16* __restrict__ KH, __nv_bfloat16* __restrict__ KL,
    __nv_bfloat16* __restrict__ VH, __nv_bfloat16* __restrict__ VL,
    int N, int relu)
{
    extern __shared__ __align__(1024) char smem[];
    const int tid = threadIdx.x, wid = tid >> 5, lane = tid & 31;
    const int wy = wid >> 2, wx = wid & 3;
    const int z = blockIdx.z;
    const int brow = blockIdx.y * 128, bcol = blockIdx.x * 128;

    const __nv_bfloat16* Ah = Ah0 + (long long)z * zA + (long long)brow * ldA;
    const __nv_bfloat16* Al = Ah + loA;
    const __nv_bfloat16* Bh = Bt0 + (long long)z * zB + (long long)bcol * (2LL * K);
    const __nv_bfloat16* Bl = Bh + K;
    if (bias) bias += (long long)z * sBias;
    if (C) C += (long long)z * sC;
    if (Sp) Sp += (long long)z * zSp;

    const uint32_t sb = smem_u32(smem);
    const int NC = K >> 6;

    auto load_tile = [&](int c, int s) {
        const int kc = c * 64;
        const uint32_t st = sb + s * G2_STAGE;
        #pragma unroll
        for (int i = 0; i < 4; i++) {
            int idx = tid + i * 256;
            int r = idx >> 3, ch = idx & 7;
            cp_async16(swz(st, r, ch),
                       (const char*)(Ah + (long long)r * ldA + kc) + ch * 16);
            cp_async16(swz(st + 16384, r, ch),
                       (const char*)(Al + (long long)r * ldA + kc) + ch * 16);
            cp_async16(swz(st + 32768, r, ch),
                       (const char*)(Bh + (long long)r * 2 * K + kc) + ch * 16);
            cp_async16(swz(st + 49152, r, ch),
                       (const char*)(Bl + (long long)r * 2 * K + kc) + ch * 16);
        }
        CP_COMMIT();
    };

    float acc[4][4][4] = {};
    load_tile(0, 0);
    load_tile(1, 1);

    int s = 0;
    for (int c = 0; c < NC; c++) {
        if (c + 1 < NC) { CP_WAIT1(); } else { CP_WAIT0(); }
        __syncthreads();
        if (c + 2 < NC) {
            int s2 = s + 2;
            if (s2 >= 3) s2 -= 3;          // (s+2)%3 — FIXED stage index
            load_tile(c + 2, s2);
        }
        const uint32_t stA = sb + s * G2_STAGE;

        #pragma unroll
        for (int ks = 0; ks < 4; ks++) {
            const int cb = ks * 2;
            uint32_t ah[4][4], al[4][4];
            #pragma unroll
            for (int ms = 0; ms < 4; ms++) {
                int r = wy * 64 + ms * 16 + (lane & 15);
                int ch = cb + (lane >> 4);
                ldsm_x4(ah[ms][0], ah[ms][1], ah[ms][2], ah[ms][3], swz(stA, r, ch));
                ldsm_x4(al[ms][0], al[ms][1], al[ms][2], al[ms][3], swz(stA + 16384, r, ch));
            }
            uint32_t bh[4][2], bl[4][2];
            #pragma unroll
            for (int nh = 0; nh < 2; nh++) {
                int g = lane >> 3;
                int r = wx * 32 + nh * 16 + ((g & 2) << 2) + (lane & 7);
                int ch = cb + (g & 1);
                uint32_t r0, r1, r2, r3;
                ldsm_x4(r0, r1, r2, r3, swz(stA + 32768, r, ch));
                bh[nh*2][0] = r0; bh[nh*2][1] = r1;
                bh[nh*2+1][0] = r2; bh[nh*2+1][1] = r3;
                ldsm_x4(r0, r1, r2, r3, swz(stA + 49152, r, ch));
                bl[nh*2][0] = r0; bl[nh*2][1] = r1;
                bl[nh*2+1][0] = r2; bl[nh*2+1][1] = r3;
            }
            #pragma unroll
            for (int ms = 0; ms < 4; ms++)
                #pragma unroll
                for (int ns = 0; ns < 4; ns++) {
                    mma16816(acc[ms][ns], ah[ms], bh[ns]);
                    mma16816(acc[ms][ns], ah[ms], bl[ns]);
                    mma16816(acc[ms][ns], al[ms], bh[ns]);
                }
        }
        __syncthreads();
        s = (s == 2) ? 0 : s + 1;
    }

    // ---- epilogue ----
    const int qrow = lane >> 2, qcol = (lane & 3) * 2;
    #pragma unroll
    for (int ms = 0; ms < 4; ms++) {
        #pragma unroll
        for (int ns = 0; ns < 4; ns++) {
            int m = brow + wy * 64 + ms * 16 + qrow;
            int n = bcol + wx * 32 + ns * 8 + qcol;
            float2 v0 = make_float2(acc[ms][ns][0], acc[ms][ns][1]);
            float2 v1 = make_float2(acc[ms][ns][2], acc[ms][ns][3]);
            if (bias) {
                float b0 = bias[n], b1 = bias[n + 1];
                v0.x += b0; v0.y += b1; v1.x += b0; v1.y += b1;
            }
            if (res) {
                float2 r0 = *(const float2*)(res + (long long)m * N + n);
                float2 r1 = *(const float2*)(res + (long long)(m + 8) * N + n);
                v0.x += r0.x; v0.y += r0.y; v1.x += r1.x; v1.y += r1.y;
            }
            if (relu) {
                v0.x = fmaxf(v0.x, 0.f); v0.y = fmaxf(v0.y, 0.f);
                v1.x = fmaxf(v1.x, 0.f); v1.y = fmaxf(v1.y, 0.f);
            }
            if (C) {
                *(float2*)(C + (long long)m * N + n)       = v0;
                *(float2*)(C + (long long)(m + 8) * N + n) = v1;
            }
            uint32_t hp0 = pack_bf2(v0.x, v0.y);
            uint32_t hp1 = pack_bf2(v1.x, v1.y);
            uint32_t lp0 = pack_bf2(v0.x - bf_lo(hp0), v0.y - bf_hi(hp0));
            uint32_t lp1 = pack_bf2(v1.x - bf_lo(hp1), v1.y - bf_hi(hp1));
            if (Sp) {
                long long r0 = (long long)m * 2 * N, r1 = (long long)(m + 8) * 2 * N;
                *(uint32_t*)(Sp + r0 + n)     = hp0;
                *(uint32_t*)(Sp + r0 + N + n) = lp0;
                *(uint32_t*)(Sp + r1 + n)     = hp1;
                *(uint32_t*)(Sp + r1 + N + n) = lp1;
            }
            if (KH) {
                long long a0 = (((long long)((m >> 10) * 8 + (n >> 6))) * 1024 + (m & 1023)) * 64 + (n & 63);
                long long a1 = a0 + 8LL * 64;
                *(uint32_t*)(KH + a0) = hp0;  *(uint32_t*)(KL + a0) = lp0;
                *(uint32_t*)(KH + a1) = hp1;  *(uint32_t*)(KL + a1) = lp1;
            }
            if (VH) {
                int b = m >> 10, h = n >> 6, d = n & 63, si = m & 1023;
                long long base = (((long long)(z * 32 + b * 8 + h)) * 64 + d) * 1024 + si;
                unsigned short* vh = (unsigned short*)VH;
                unsigned short* vl = (unsigned short*)VL;
                vh[base]            = (unsigned short)(hp0 & 0xffff);
                vh[base + 1024]     = (unsigned short)(hp0 >> 16);
                vh[base + 8]        = (unsigned short)(hp1 & 0xffff);
                vh[base + 1024 + 8] = (unsigned short)(hp1 >> 16);
                vl[base]            = (unsigned short)(lp0 & 0xffff);
                vl[base + 1024]     = (unsigned short)(lp0 >> 16);
                vl[base + 8]        = (unsigned short)(lp1 & 0xffff);
                vl[base + 1024 + 8] = (unsigned short)(lp1 >> 16);
            }
        }
    }
}

// ================= tensor-core flash attention ===============================
#define ATTN_SMEM 81920

__global__ __launch_bounds__(128) void attn_mma_kernel(
    const __nv_bfloat16* __restrict__ khh, const __nv_bfloat16* __restrict__ khl,
    const __nv_bfloat16* __restrict__ vth, const __nv_bfloat16* __restrict__ vtl,
    __nv_bfloat16* __restrict__ Cx)
{
    extern __shared__ __align__(1024) char smem[];
    const uint32_t sb = smem_u32(smem);
    const int tid = threadIdx.x, wid = tid >> 5, lane = tid & 31;
    const int qb = 15 - blockIdx.x;
    const int bh = blockIdx.y;
    const int q0 = qb * 64;

    const __nv_bfloat16* Kh = khh + (long long)bh * S_ * 64;
    const __nv_bfloat16* Kl = khl + (long long)bh * S_ * 64;
    const __nv_bfloat16* Vh = vth + (long long)bh * 64 * S_;
    const __nv_bfloat16* Vl = vtl + (long long)bh * 64 * S_;

    auto load_kv = [&](int jt, int s) {
        const int j0 = jt * 64;
        const uint32_t base = sb + 16384 + s * 32768;
        #pragma unroll
        for (int i = 0; i < 4; i++) {
            int idx = tid + i * 128;
            int r = idx >> 3, ch = idx & 7;
            cp_async16(swz(base, r, ch),
                       (const char*)(Kh + (long long)(j0 + r) * 64) + ch * 16);
            cp_async16(swz(base + 8192, r, ch),
                       (const char*)(Kl + (long long)(j0 + r) * 64) + ch * 16);
            cp_async16(swz(base + 16384, r, ch),
                       (const char*)(Vh + (long long)r * S_ + j0) + ch * 16);
            cp_async16(swz(base + 24576, r, ch),
                       (const char*)(Vl + (long long)r * S_ + j0) + ch * 16);
        }
        CP_COMMIT();
    };

    #pragma unroll
    for (int i = 0; i < 4; i++) {
        int idx = tid + i * 128;
        int r = idx >> 3, ch = idx & 7;
        cp_async16(swz(sb, r, ch),
                   (const char*)(Kh + (long long)(q0 + r) * 64) + ch * 16);
        cp_async16(swz(sb + 8192, r, ch),
                   (const char*)(Kl + (long long)(q0 + r) * 64) + ch * 16);
    }
    load_kv(0, 0);
    CP_WAIT0();
    __syncthreads();

    uint32_t qh[4][4], ql[4][4];
    #pragma unroll
    for (int ks = 0; ks < 4; ks++) {
        int r = wid * 16 + (lane & 15);
        int ch = 2 * ks + (lane >> 4);
        ldsm_x4(qh[ks][0], qh[ks][1], qh[ks][2], qh[ks][3], swz(sb, r, ch));
        ldsm_x4(ql[ks][0], ql[ks][1], ql[ks][2], ql[ks][3], swz(sb + 8192, r, ch));
    }

    float ctx[8][4] = {};
    float m0 = NEG_INF, m1 = NEG_INF, l0 = 0.f, l1 = 0.f;
    const int rg0 = q0 + wid * 16 + (lane >> 2);

    for (int jt = 0; jt <= qb; jt++) {
        const int s = jt & 1;
        if (jt < qb) { load_kv(jt + 1, s ^ 1); CP_WAIT1(); }
        else if (jt > 0) { CP_WAIT0(); }
        __syncthreads();

        const uint32_t bK = sb + 16384 + s * 32768;

        float sc[8][4] = {};
        #pragma unroll
        for (int ks = 0; ks < 4; ks++) {
            uint32_t bh_[8][2], bl_[8][2];
            #pragma unroll
            for (int ng = 0; ng < 4; ng++) {
                int g = lane >> 3;
                int r = ng * 16 + ((g & 2) << 2) + (lane & 7);
                int ch = 2 * ks + (g & 1);
                uint32_t a0, a1, a2, a3;
                ldsm_x4(a0, a1, a2, a3, swz(bK, r, ch));
                bh_[2*ng][0] = a0; bh_[2*ng][1] = a1;
                bh_[2*ng+1][0] = a2; bh_[2*ng+1][1] = a3;
                ldsm_x4(a0, a1, a2, a3, swz(bK + 8192, r, ch));
                bl_[2*ng][0] = a0; bl_[2*ng][1] = a1;
                bl_[2*ng+1][0] = a2; bl_[2*ng+1][1] = a3;
            }
            #pragma unroll
            for (int nt = 0; nt < 8; nt++) {
                mma16816(sc[nt], qh[ks], bh_[nt]);
                mma16816(sc[nt], qh[ks], bl_[nt]);
                mma16816(sc[nt], ql[ks], bh_[nt]);
            }
        }

        const int j0 = jt * 64;
        const bool diag = (jt == qb);
        const int cb0 = j0 + (lane & 3) * 2;
        float rm0 = NEG_INF, rm1 = NEG_INF;
        #pragma unroll
        for (int nt = 0; nt < 8; nt++) {
            int c0 = cb0 + nt * 8, c1 = c0 + 1;
            float s0 = sc[nt][0] * 0.125f, s1 = sc[nt][1] * 0.125f;
            float s2 = sc[nt][2] * 0.125f, s3 = sc[nt][3] * 0.125f;
            if (diag) {
                if (c0 >= rg0)     s0 = NEG_INF;
                if (c1 >= rg0)     s1 = NEG_INF;
                if (c0 >= rg0 + 8) s2 = NEG_INF;
                if (c1 >= rg0 + 8) s3 = NEG_INF;
            }
            sc[nt][0] = s0; sc[nt][1] = s1; sc[nt][2] = s2; sc[nt][3] = s3;
            rm0 = fmaxf(rm0, fmaxf(s0, s1));
            rm1 = fmaxf(rm1, fmaxf(s2, s3));
        }
        #pragma unroll
        for (int o = 1; o <= 2; o <<= 1) {
            rm0 = fmaxf(rm0, __shfl_xor_sync(0xffffffffu, rm0, o));
            rm1 = fmaxf(rm1, __shfl_xor_sync(0xffffffffu, rm1, o));
        }
        float mn0 = fmaxf(m0, rm0), mn1 = fmaxf(m1, rm1);
        float ms0 = (mn0 == NEG_INF) ? 0.f : mn0;
        float ms1 = (mn1 == NEG_INF) ? 0.f : mn1;
        float cr0 = __expf(m0 - ms0), cr1 = __expf(m1 - ms1);
        float rs0 = 0.f, rs1 = 0.f;
        #pragma unroll
        for (int nt = 0; nt < 8; nt++) {
            sc[nt][0] = __expf(sc[nt][0] - ms0); rs0 += sc[nt][0];
            sc[nt][1] = __expf(sc[nt][1] - ms0); rs0 += sc[nt][1];
            sc[nt][2] = __expf(sc[nt][2] - ms1); rs1 += sc[nt][2];
            sc[nt][3] = __expf(sc[nt][3] - ms1); rs1 += sc[nt][3];
        }
        #pragma unroll
        for (int o = 1; o <= 2; o <<= 1) {
            rs0 += __shfl_xor_sync(0xffffffffu, rs0, o);
            rs1 += __shfl_xor_sync(0xffffffffu, rs1, o);
        }
        l0 = l0 * cr0 + rs0; l1 = l1 * cr1 + rs1;
        m0 = mn0; m1 = mn1;
        #pragma unroll
        for (int nt = 0; nt < 8; nt++) {
            ctx[nt][0] *= cr0; ctx[nt][1] *= cr0;
            ctx[nt][2] *= cr1; ctx[nt][3] *= cr1;
        }

        uint32_t ph[4][4], pl[4][4];
        #pragma unroll
        for (int kj = 0; kj < 4; kj++) {
            const int t0 = 2 * kj, t1 = 2 * kj + 1;
            ph[kj][0] = pack_bf2(sc[t0][0], sc[t0][1]);
            ph[kj][1] = pack_bf2(sc[t0][2], sc[t0][3]);
            ph[kj][2] = pack_bf2(sc[t1][0], sc[t1][1]);
            ph[kj][3] = pack_bf2(sc[t1][2], sc[t1][3]);
            pl[kj][0] = pack_bf2(sc[t0][0] - bf_lo(ph[kj][0]), sc[t0][1] - bf_hi(ph[kj][0]));
            pl[kj][1] = pack_bf2(sc[t0][2] - bf_lo(ph[kj][1]), sc[t0][3] - bf_hi(ph[kj][1]));
            pl[kj][2] = pack_bf2(sc[t1][0] - bf_lo(ph[kj][2]), sc[t1][1] - bf_hi(ph[kj][2]));
            pl[kj][3] = pack_bf2(sc[t1][2] - bf_lo(ph[kj][3]), sc[t1][3] - bf_hi(ph[kj][3]));
        }

        const uint32_t bV = bK + 16384;
        #pragma unroll
        for (int kj = 0; kj < 4; kj++) {
            uint32_t vh_[8][2], vl_[8][2];
            #pragma unroll
            for (int dg = 0; dg < 4; dg++) {
                int g = lane >> 3;
                int r = dg * 16 + ((g & 2) << 2) + (lane & 7);
                int ch = 2 * kj + (g & 1);
                uint32_t a0, a1, a2, a3;
                ldsm_x4(a0, a1, a2, a3, swz(bV, r, ch));
                vh_[2*dg][0] = a0; vh_[2*dg][1] = a1;
                vh_[2*dg+1][0] = a2; vh_[2*dg+1][1] = a3;
                ldsm_x4(a0, a1, a2, a3, swz(bV + 8192, r, ch));
                vl_[2*dg][0] = a0; vl_[2*dg][1] = a1;
                vl_[2*dg+1][0] = a2; vl_[2*dg+1][1] = a3;
            }
            #pragma unroll
            for (int nt = 0; nt < 8; nt++) {
                mma16816(ctx[nt], ph[kj], vh_[nt]);
                mma16816(ctx[nt], ph[kj], vl_[nt]);
                mma16816(ctx[nt], pl[kj], vh_[nt]);
            }
        }
        __syncthreads();
    }

    // epilogue: normalize, split, write ctx'
    float inv0 = (l0 > 0.f) ? 1.f / l0 : 0.f;
    float inv1 = (l1 > 0.f) ? 1.f / l1 : 0.f;
    const int b = bh >> 3, h = bh & 7;
    const int row0 = b * S_ + q0 + wid * 16 + (lane >> 2);
    const int colb = h * 64 + (lane & 3) * 2;
    #pragma unroll
    for (int nt = 0; nt < 8; nt++) {
        float a0 = ctx[nt][0] * inv0, a1 = ctx[nt][1] * inv0;
        float a2 = ctx[nt][2] * inv1, a3 = ctx[nt][3] * inv1;
        uint32_t hp0 = pack_bf2(a0, a1);
        uint32_t hp1 = pack_bf2(a2, a3);
        uint32_t lp0 = pack_bf2(a0 - bf_lo(hp0), a1 - bf_hi(hp0));
        uint32_t lp1 = pack_bf2(a2 - bf_lo(hp1), a3 - bf_hi(hp1));
        long long r0 = (long long)row0 * 1024, r1 = (long long)(row0 + 8) * 1024;
        int cc = colb + nt * 8;
        *(uint32_t*)(Cx + r0 + cc)       = hp0;
        *(uint32_t*)(Cx + r0 + 512 + cc) = lp0;
        *(uint32_t*)(Cx + r1 + cc)       = hp1;
        *(uint32_t*)(Cx + r1 + 512 + cc) = lp1;
    }
}

// ---------------- positional embedding + y' -------------------------------
__global__ void pe_kernel(float* __restrict__ pe) {
    int s = blockIdx.x;
    int j = threadIdx.x;
    float div = expf((float)(2*j) * (-9.210340371976184f / (float)D_));
    float arg = (float)s * div;
    pe[s*D_ + 2*j]     = sinf(arg);
    pe[s*D_ + 2*j + 1] = cosf(arg);
}

__global__ __launch_bounds__(256) void add_pe_kernel(
    const float* __restrict__ qa, const float* __restrict__ pe,
    __nv_bfloat16* __restrict__ yb)
{
    int i = blockIdx.x * 256 + threadIdx.x;
    float v = qa[i] + pe[i & (S_*D_ - 1)];
    int m = i >> 9, c = i & 511;
    __nv_bfloat16 h = __float2bfloat16_rn(v);
    yb[(long long)m * 1024 + c]       = h;
    yb[(long long)m * 1024 + 512 + c] = __float2bfloat16_rn(v - __bfloat162float(h));
}

// ---------------- MoE gate + combine + LN + PE -> x (fp32 + split) ---------
__global__ __launch_bounds__(256) void moe_kernel(
    const float* __restrict__ summary, const float* __restrict__ m_seq,
    const float* __restrict__ gate_w,  const float* __restrict__ gate_b,
    const float* __restrict__ experts,
    const float* __restrict__ lng, const float* __restrict__ lnb,
    const float* __restrict__ pe, float* __restrict__ x,
    __nv_bfloat16* __restrict__ xb)
{
    __shared__ float red[4][8];
    __shared__ float wgt[4];
    __shared__ float r1[8], r2[8];

    const int row = blockIdx.x;
    const int tid = threadIdx.x;
    const int s_idx = row & (S_ - 1);

    float p0 = 0, p1 = 0, p2 = 0, p3 = 0;
    for (int e = tid; e < D_ + SD_; e += 256) {
        float xv = (e < D_) ? summary[(long long)row * D_ + e]
                            : m_seq[(long long)row * SD_ + (e - D_)];
        float4 w = *(const float4*)(gate_w + e * 4);
        p0 += xv * w.x; p1 += xv * w.y; p2 += xv * w.z; p3 += xv * w.w;
    }
    #pragma unroll
    for (int o = 16; o > 0; o >>= 1) {
        p0 += __shfl_xor_sync(0xffffffffu, p0, o);
        p1 += __shfl_xor_sync(0xffffffffu, p1, o);
        p2 += __shfl_xor_sync(0xffffffffu, p2, o);
        p3 += __shfl_xor_sync(0xffffffffu, p3, o);
    }
    if ((tid & 31) == 0) {
        int w = tid >> 5;
        red[0][w] = p0; red[1][w] = p1; red[2][w] = p2; red[3][w] = p3;
    }
    __syncthreads();

    if (tid == 0) {
        float l[4];
        #pragma unroll
        for (int j = 0; j < 4; j++) {
            float t = gate_b[j];
            #pragma unroll
            for (int w = 0; w < 8; w++) t += red[j][w];
            l[j] = t;
        }
        float m1v = -INFINITY, m2v = -INFINITY;
        #pragma unroll
        for (int j = 0; j < 4; j++) {
            if (l[j] > m1v) { m2v = m1v; m1v = l[j]; }
            else if (l[j] > m2v) { m2v = l[j]; }
        }
        float sum = 0.f, e4[4];
        #pragma unroll
        for (int j = 0; j < 4; j++) {
            e4[j] = (l[j] >= m2v) ? __expf(l[j] - m1v) : 0.f;
            sum += e4[j];
        }
        #pragma unroll
        for (int j = 0; j < 4; j++) wgt[j] = e4[j] / sum;
    }
    __syncthreads();

    const float w0 = wgt[0], w1 = wgt[1], w2 = wgt[2], w3 = wgt[3];
    const long long base = (long long)row * D_;
    const int t2 = tid + 256;
    float c0 = w0 * experts[0*BSD + base + tid] + w1 * experts[1*BSD + base + tid]
             + w2 * experts[2*BSD + base + tid] + w3 * experts[3*BSD + base + tid];
    float c1 = w0 * experts[0*BSD + base + t2]  + w1 * experts[1*BSD + base + t2]
             + w2 * experts[2*BSD + base + t2]  + w3 * experts[3*BSD + base + t2];

    float s = c0 + c1, q = c0 * c0 + c1 * c1;
    #pragma unroll
    for (int o = 16; o > 0; o >>= 1) {
        s += __shfl_xor_sync(0xffffffffu, s, o);
        q += __shfl_xor_sync(0xffffffffu, q, o);
    }
    if ((tid & 31) == 0) { r1[tid >> 5] = s; r2[tid >> 5] = q; }
    __syncthreads();
    float ts = 0, tq = 0;
    #pragma unroll
    for (int w = 0; w < 8; w++) { ts += r1[w]; tq += r2[w]; }
    float mu = ts * (1.f / 512.f);
    float var = tq * (1.f / 512.f) - mu * mu;
    float rstd = rsqrtf(var + 1e-5f);

    float o0 = (c0 - mu) * rstd * lng[tid] + lnb[tid] + pe[s_idx * D_ + tid];
    float o1 = (c1 - mu) * rstd * lng[t2]  + lnb[t2]  + pe[s_idx * D_ + t2];
    x[base + tid] = o0;
    x[base + t2]  = o1;
    long long b2 = (long long)row * 1024;
    __nv_bfloat16 h0 = __float2bfloat16_rn(o0);
    __nv_bfloat16 h1 = __float2bfloat16_rn(o1);
    xb[b2 + tid]        = h0;
    xb[b2 + t2]         = h1;
    xb[b2 + 512 + tid]  = __float2bfloat16_rn(o0 - __bfloat162float(h0));
    xb[b2 + 512 + t2]   = __float2bfloat16_rn(o1 - __bfloat162float(h1));
}

// ---------------- LayerNorm (fp32 out + optional split) --------------------
__global__ __launch_bounds__(256) void ln_kernel(
    const float* __restrict__ in, const float* __restrict__ g,
    const float* __restrict__ b, float* __restrict__ out,
    __nv_bfloat16* __restrict__ sp)
{
    __shared__ float r1[8], r2[8];
    const int row = blockIdx.x, tid = threadIdx.x;
    const long long base = (long long)row * D_;
    float v0 = in[base + tid], v1 = in[base + tid + 256];
    float s = v0 + v1, q = v0 * v0 + v1 * v1;
    #pragma unroll
    for (int o = 16; o > 0; o >>= 1) {
        s += __shfl_xor_sync(0xffffffffu, s, o);
        q += __shfl_xor_sync(0xffffffffu, q, o);
    }
    if ((tid & 31) == 0) { r1[tid >> 5] = s; r2[tid >> 5] = q; }
    __syncthreads();
    float ts = 0, tq = 0;
    #pragma unroll
    for (int w = 0; w < 8; w++) { ts += r1[w]; tq += r2[w]; }
    float mu = ts * (1.f / 512.f);
    float var = tq * (1.f / 512.f) - mu * mu;
    float rstd = rsqrtf(var + 1e-5f);
    float o0 = (v0 - mu) * rstd * g[tid]       + b[tid];
    float o1 = (v1 - mu) * rstd * g[tid + 256] + b[tid + 256];
    out[base + tid]       = o0;
    out[base + tid + 256] = o1;
    if (sp) {
        long long b2 = (long long)row * 1024;
        __nv_bfloat16 h0 = __float2bfloat16_rn(o0);
        __nv_bfloat16 h1 = __float2bfloat16_rn(o1);
        sp[b2 + tid]       = h0;
        sp[b2 + tid + 256] = h1;
        sp[b2 + 512 + tid]       = __float2bfloat16_rn(o0 - __bfloat162float(h0));
        sp[b2 + 512 + tid + 256] = __float2bfloat16_rn(o1 - __bfloat162float(h1));
    }
}

// ================= host wrapper ==============================================
typedef __nv_bfloat16 bf16;

static void gemm2(const bf16* Ah, int loA, int ldA, long long zA,
                  const float* W, long long sBz, int K, int N, int nz,
                  const float* bias, int sBias, const float* res,
                  float* C, long long sC, bf16* Sp, long long zSp,
                  bf16* KH, bf16* KL, bf16* VH, bf16* VL,
                  int relu, bf16* bbf)
{
    convB_kernel<<<dim3(K/32, N/32, nz), dim3(32, 8)>>>(W, sBz, K, N, bbf);
    gemm2_kernel<<<dim3(N/128, 32, nz), 256, G2_SMEM>>>(
        Ah, loA, ldA, zA, bbf, (long long)N * 2 * K, K,
        bias, sBias, res, C, sC, Sp, zSp, KH, KL, VH, VL, N, relu);
}

extern "C" void kernel_launch(void* const* d_in, const int* in_sizes, int n_in,
                              void* d_out, int out_size)
{
    const float* q_raw   = (const float*)d_in[0];
    const float* m_seq   = (const float*)d_in[1];
    const float* qa      = (const float*)d_in[2];
    const float* exp_w1  = (const float*)d_in[3];
    const float* exp_b1  = (const float*)d_in[4];
    const float* exp_w2  = (const float*)d_in[5];
    const float* exp_b2  = (const float*)d_in[6];
    const float* adapt_w = (const float*)d_in[7];
    const float* adapt_b = (const float*)d_in[8];
    const float* gate_w  = (const float*)d_in[9];
    const float* gate_b  = (const float*)d_in[10];
    const float* moe_g   = (const float*)d_in[11];
    const float* moe_b   = (const float*)d_in[12];
    const float* kw      = (const float*)d_in[13];
    const float* kb      = (const float*)d_in[14];
    const float* vw      = (const float*)d_in[15];
    const float* vb      = (const float*)d_in[16];
    const float* ow      = (const float*)d_in[17];
    const float* ob      = (const float*)d_in[18];
    const float* ln1g    = (const float*)d_in[19];
    const float* ln1b    = (const float*)d_in[20];
    const float* fw1     = (const float*)d_in[21];
    const float* fb1     = (const float*)d_in[22];
    const float* fw2     = (const float*)d_in[23];
    const float* fb2     = (const float*)d_in[24];
    const float* ln2g    = (const float*)d_in[25];
    const float* ln2b    = (const float*)d_in[26];

    float *pe, *x, *experts, *summary;
    bf16 *qbf, *h1bf, *ybf, *xbf, *ctxbf, *ffnbf, *bbf, *khh, *khl, *vth, *vtl;
    cudaGetSymbolAddress((void**)&pe, g_pe);
    cudaGetSymbolAddress((void**)&x, g_x);
    cudaGetSymbolAddress((void**)&experts, g_experts);
    cudaGetSymbolAddress((void**)&summary, g_summary);
    cudaGetSymbolAddress((void**)&qbf, g_qbf);
    cudaGetSymbolAddress((void**)&h1bf, g_h1bf);
    cudaGetSymbolAddress((void**)&ybf, g_ybf);
    cudaGetSymbolAddress((void**)&xbf, g_xbf);
    cudaGetSymbolAddress((void**)&ctxbf, g_ctxbf);
    cudaGetSymbolAddress((void**)&ffnbf, g_ffnbf);
    cudaGetSymbolAddress((void**)&bbf, g_bbf);
    cudaGetSymbolAddress((void**)&khh, g_khh);
    cudaGetSymbolAddress((void**)&khl, g_khl);
    cudaGetSymbolAddress((void**)&vth, g_vth);
    cudaGetSymbolAddress((void**)&vtl, g_vtl);

    static int attr_set = 0;
    if (!attr_set) {
        cudaFuncSetAttribute(gemm2_kernel,
                             cudaFuncAttributeMaxDynamicSharedMemorySize, G2_SMEM);
        cudaFuncSetAttribute(attn_mma_kernel,
                             cudaFuncAttributeMaxDynamicSharedMemorySize, ATTN_SMEM);
        attr_set = 1;
    }

    pe_kernel<<<S_, 256>>>(pe);
    add_pe_kernel<<<(int)(BSD / 256), 256>>>(qa, pe, ybf);
    conv_qraw_kernel<<<4096 * 768 / 256, 256>>>(q_raw, qbf);

    // h1 = relu(q_raw[z] @ exp_w1[z] + b1)  -> split only
    gemm2(qbf, 3072, 6144, 768, exp_w1, (long long)IN_*IN_, IN_, IN_, NS_,
          exp_b1, IN_, nullptr, nullptr, 0,
          h1bf, (long long)BS * 1536, nullptr, nullptr, nullptr, nullptr, 1, bbf);
    // experts = h1[z] @ exp_w2[z] + b2  -> fp32
    gemm2(h1bf, 768, 1536, (long long)BS * 1536, exp_w2, (long long)IN_*D_, IN_, D_, NS_,
          exp_b2, D_, nullptr, experts, BSD,
          nullptr, 0, nullptr, nullptr, nullptr, nullptr, 0, bbf);
    // summary = relu(q_flat @ adapt_w + b)  -> fp32
    gemm2(qbf, 3072, 6144, 0, adapt_w, 0, NS_*IN_, D_, 1,
          adapt_b, 0, nullptr, summary, 0,
          nullptr, 0, nullptr, nullptr, nullptr, nullptr, 1, bbf);

    moe_kernel<<<BS, 256>>>(summary, m_seq, gate_w, gate_b, experts,
                            moe_g, moe_b, pe, x, xbf);

    // V for all 4 layers -> transposed split vth/vtl
    gemm2(ybf, 512, 1024, 0, vw, (long long)D_*D_, D_, D_, L_,
          vb, D_, nullptr, nullptr, 0,
          nullptr, 0, nullptr, nullptr, vth, vtl, 0, bbf);

    for (int i = 0; i < L_; i++) {
        // K-projection -> khh/khl (attention layout)
        gemm2(xbf, 512, 1024, 0, kw + (long long)i*D_*D_, 0, D_, D_, 1,
              kb + i*D_, 0, nullptr, nullptr, 0,
              nullptr, 0, khh, khl, nullptr, nullptr, 0, bbf);
        attn_mma_kernel<<<dim3(16, 32), 128, ATTN_SMEM>>>(
            khh, khl, vth + (long long)i * 2097152, vtl + (long long)i * 2097152, ctxbf);
        // O-projection + residual -> x fp32
        gemm2(ctxbf, 512, 1024, 0, ow + (long long)i*D_*D_, 0, D_, D_, 1,
              ob + i*D_, 0, x, x, 0,
              nullptr, 0, nullptr, nullptr, nullptr, nullptr, 0, bbf);
        ln_kernel<<<BS, 256>>>(x, ln1g + i*D_, ln1b + i*D_, x, xbf);
        // FFN1 -> split only (relu)
        gemm2(xbf, 512, 1024, 0, fw1 + (long long)i*D_*FF_, 0, D_, FF_, 1,
              fb1 + i*FF_, 0, nullptr, nullptr, 0,
              ffnbf, 0, nullptr, nullptr, nullptr, nullptr, 1, bbf);
        // FFN2 + residual -> x fp32
        gemm2(ffnbf, 2048, 4096, 0, fw2 + (long long)i*FF_*D_, 0, FF_, D_, 1,
              fb2 + i*D_, 0, x, x, 0,
              nullptr, 0, nullptr, nullptr, nullptr, nullptr, 0, bbf);
        ln_kernel<<<BS, 256>>>(x, ln2g + i*D_, ln2b + i*D_,
                               (i == L_-1) ? (float*)d_out : x,
                               (i == L_-1) ? nullptr : xbf);
    }
}

// round 7
// speedup vs baseline: 3.5381x; 1.0632x over previous
#include <cuda_runtime.h>
#include <cuda_bf16.h>
#include <cstdint>
#include <math.h>

// Problem dims
#define B_  4
#define S_  1024
#define D_  512
#define H_  8
#define DK_ 64
#define FF_ 2048
#define L_  4
#define IN_ 768
#define NS_ 4
#define SD_ 64

#define BS  (B_*S_)            // 4096
#define BSD ((long long)BS*D_) // 2097152
#define NEG_INF __int_as_float(0xff800000)

// ---------------- scratch (device globals: allocation-free) ----------------
__device__ float g_pe[S_*D_];
__device__ float g_x[BS*D_];
__device__ float g_experts[NS_*BS*D_];
__device__ float g_summary[BS*D_];
__device__ float g_wgt[BS*4];
__device__ int   g_cnt[4];
__device__ int   g_list[4*BS];
// split bf16 buffers, layout [m][hi K | lo K]
__device__ __nv_bfloat16 g_qbf[25165824];    // q_raw' [4096][6144]
__device__ __nv_bfloat16 g_h1bf[25165824];   // h1'   [4][4096][1536] (compacted slots)
__device__ __nv_bfloat16 g_ybf[4194304];     // y'    [4096][1024]
__device__ __nv_bfloat16 g_xbf[4194304];     // x'    [4096][1024]
__device__ __nv_bfloat16 g_ctxbf[4194304];   // ctx'  [4096][1024]
__device__ __nv_bfloat16 g_ffnbf[16777216];  // ffn'  [4096][4096]
__device__ __nv_bfloat16 g_khh[2097152];     // K hi [32][1024][64]
__device__ __nv_bfloat16 g_khl[2097152];
__device__ __nv_bfloat16 g_vth[8388608];     // Vt hi [4][32][64][1024]
__device__ __nv_bfloat16 g_vtl[8388608];
// all weights, split bf16 [n][hiK|loK]
__device__ __nv_bfloat16 g_wbf[34078720];

// weight buffer offsets (bf16 elements)
#define W_EXPW1 0LL
#define W_EXPW2 4718592LL
#define W_ADAPT 7864320LL
#define W_KW    11010048LL
#define W_VW    13107200LL
#define W_OW    15204352LL
#define W_FW1   17301504LL
#define W_FW2   25690112LL

// ================= PTX helpers ===============================================
__device__ __forceinline__ uint32_t smem_u32(const void* p) {
    uint32_t a;
    asm("{ .reg .u64 t; cvta.to.shared.u64 t, %1; cvt.u32.u64 %0, t; }" : "=r"(a) : "l"(p));
    return a;
}
__device__ __forceinline__ void cp_async16(uint32_t dst, const void* src) {
    asm volatile("cp.async.cg.shared.global [%0], [%1], 16;" :: "r"(dst), "l"(src));
}
#define CP_COMMIT() asm volatile("cp.async.commit_group;" ::: "memory")
#define CP_WAIT0()  asm volatile("cp.async.wait_group 0;" ::: "memory")
#define CP_WAIT1()  asm volatile("cp.async.wait_group 1;" ::: "memory")

__device__ __forceinline__ void ldsm_x4(uint32_t& r0, uint32_t& r1, uint32_t& r2,
                                        uint32_t& r3, uint32_t addr) {
    asm volatile("ldmatrix.sync.aligned.m8n8.x4.shared.b16 {%0,%1,%2,%3}, [%4];"
        : "=r"(r0), "=r"(r1), "=r"(r2), "=r"(r3) : "r"(addr));
}
__device__ __forceinline__ void mma16816(float* c, const uint32_t* a, const uint32_t* b) {
    asm volatile(
        "mma.sync.aligned.m16n8k16.row.col.f32.bf16.bf16.f32 "
        "{%0,%1,%2,%3}, {%4,%5,%6,%7}, {%8,%9}, {%0,%1,%2,%3};"
        : "+f"(c[0]), "+f"(c[1]), "+f"(c[2]), "+f"(c[3])
        : "r"(a[0]), "r"(a[1]), "r"(a[2]), "r"(a[3]), "r"(b[0]), "r"(b[1]));
}
__device__ __forceinline__ uint32_t pack_bf2(float lo, float hi) {
    uint32_t d;
    asm("cvt.rn.bf16x2.f32 %0, %1, %2;" : "=r"(d) : "f"(hi), "f"(lo));
    return d;
}
__device__ __forceinline__ float bf_lo(uint32_t p) { return __uint_as_float(p << 16); }
__device__ __forceinline__ float bf_hi(uint32_t p) { return __uint_as_float(p & 0xffff0000u); }

__device__ __forceinline__ uint32_t swz(uint32_t base, int r, int ch) {
    return base + r * 128 + ((ch ^ (r & 7)) << 4);
}

// ================= conversions ==============================================
// q_raw [4096][3072] fp32 -> q' [4096][6144] = [hi 3072 | lo 3072]
__global__ __launch_bounds__(256) void conv_qraw_kernel(
    const float* __restrict__ src, __nv_bfloat16* __restrict__ dst)
{
    int idx = blockIdx.x * 256 + threadIdx.x;
    int m = idx / 768;
    int k = (idx - m * 768) * 4;
    float4 v = *(const float4*)(src + (long long)m * 3072 + k);
    unsigned short hb[4], lb[4];
    float vv[4] = {v.x, v.y, v.z, v.w};
    #pragma unroll
    for (int i = 0; i < 4; i++) {
        __nv_bfloat16 h = __float2bfloat16_rn(vv[i]);
        __nv_bfloat16 l = __float2bfloat16_rn(vv[i] - __bfloat162float(h));
        hb[i] = __bfloat16_as_ushort(h);
        lb[i] = __bfloat16_as_ushort(l);
    }
    long long base = (long long)m * 6144;
    *(uint2*)(dst + base + k) = make_uint2((uint32_t)hb[0] | ((uint32_t)hb[1] << 16),
                                           (uint32_t)hb[2] | ((uint32_t)hb[3] << 16));
    *(uint2*)(dst + base + 3072 + k) = make_uint2((uint32_t)lb[0] | ((uint32_t)lb[1] << 16),
                                                  (uint32_t)lb[2] | ((uint32_t)lb[3] << 16));
}

// all weights W [z][K][N] fp32 -> W' [z][n][2K] = [hi K | lo K], one launch
struct ConvSegs {
    const float* src[8];
    long long dstOff[8];
    int K[8], N[8], tOff[8];
};

__global__ void convB_all_kernel(ConvSegs segs, __nv_bfloat16* __restrict__ wb)
{
    __shared__ float t[32][33];
    int bx = blockIdx.x;
    int seg = 0;
    #pragma unroll
    for (int i = 7; i >= 1; i--) if (bx >= segs.tOff[i]) { seg = i; break; }
    const int K = segs.K[seg], N = segs.N[seg];
    int tl = bx - segs.tOff[seg];
    int tz = (K >> 5) * (N >> 5);
    int z = tl / tz, rr = tl - z * tz;
    int k0 = (rr % (K >> 5)) * 32, n0 = (rr / (K >> 5)) * 32;
    const float* s = segs.src[seg] + (long long)z * K * N;
    __nv_bfloat16* dstz = wb + segs.dstOff[seg] + (long long)z * N * 2 * K;
    int tx = threadIdx.x, ty = threadIdx.y;
    #pragma unroll
    for (int r = ty; r < 32; r += 8)
        t[r][tx] = s[(long long)(k0 + r) * N + n0 + tx];
    __syncthreads();
    #pragma unroll
    for (int r = ty; r < 32; r += 8) {
        float x = t[tx][r];
        __nv_bfloat16 h = __float2bfloat16_rn(x);
        __nv_bfloat16 l = __float2bfloat16_rn(x - __bfloat162float(h));
        long long base = (long long)(n0 + r) * 2 * K + k0 + tx;
        dstz[base]     = h;
        dstz[base + K] = l;
    }
}

// ================= unified split GEMM (mma.sync bf16 x3 terms) ===============
// gmode: 0 = dense, 1 = gather-A rows via list (Sp at slots), 2 = scatter-C rows
#define G2_STAGE 65536
#define G2_SMEM  196608

__global__ __launch_bounds__(256, 1) void gemm2_kernel(
    const __nv_bfloat16* __restrict__ Ah0, int loA, int ldA, long long zA,
    const __nv_bfloat16* __restrict__ Bt0, long long zB, int K,
    const float* __restrict__ bias, int sBias,
    const float* __restrict__ res,
    float* __restrict__ C, long long sC,
    __nv_bfloat16* __restrict__ Sp, long long zSp,
    __nv_bfloat16* __restrict__ KH, __nv_bfloat16* __restrict__ KL,
    __nv_bfloat16* __restrict__ VH, __nv_bfloat16* __restrict__ VL,
    const int* __restrict__ glist, const int* __restrict__ gcnt,
    int gmode, int N, int relu)
{
    extern __shared__ __align__(1024) char smem[];
    __shared__ int slist[128];
    const int tid = threadIdx.x, wid = tid >> 5, lane = tid & 31;
    const int wy = wid >> 2, wx = wid & 3;
    const int z = blockIdx.z;
    const int brow = blockIdx.y * 128, bcol = blockIdx.x * 128;

    int cnt = 0;
    if (gmode) {
        cnt = gcnt[z];
        if (brow >= cnt) return;
        if (tid < 128) {
            int i = brow + tid;
            slist[tid] = glist[z * BS + (i < cnt ? i : cnt - 1)];
        }
    }

    const __nv_bfloat16* Ahz = Ah0 + (long long)z * zA;
    const __nv_bfloat16* Bh = Bt0 + (long long)z * zB + (long long)bcol * (2LL * K);
    const __nv_bfloat16* Bl = Bh + K;
    if (bias) bias += (long long)z * sBias;
    if (C) C += (long long)z * sC;
    if (Sp) Sp += (long long)z * zSp;

    if (gmode) __syncthreads();

    const uint32_t sb = smem_u32(smem);
    const int NC = K >> 6;

    auto load_tile = [&](int c, int s) {
        const int kc = c * 64;
        const uint32_t st = sb + s * G2_STAGE;
        #pragma unroll
        for (int i = 0; i < 4; i++) {
            int idx = tid + i * 256;
            int r = idx >> 3, ch = idx & 7;
            int rowA = (gmode == 1) ? slist[r] : (brow + r);
            cp_async16(swz(st, r, ch),
                       (const char*)(Ahz + (long long)rowA * ldA + kc) + ch * 16);
            cp_async16(swz(st + 16384, r, ch),
                       (const char*)(Ahz + loA + (long long)rowA * ldA + kc) + ch * 16);
            cp_async16(swz(st + 32768, r, ch),
                       (const char*)(Bh + (long long)r * 2 * K + kc) + ch * 16);
            cp_async16(swz(st + 49152, r, ch),
                       (const char*)(Bl + (long long)r * 2 * K + kc) + ch * 16);
        }
        CP_COMMIT();
    };

    float acc[4][4][4] = {};
    load_tile(0, 0);
    load_tile(1, 1);

    int s = 0;
    for (int c = 0; c < NC; c++) {
        if (c + 1 < NC) { CP_WAIT1(); } else { CP_WAIT0(); }
        __syncthreads();
        if (c + 2 < NC) {
            int s2 = s + 2;
            if (s2 >= 3) s2 -= 3;
            load_tile(c + 2, s2);
        }
        const uint32_t stA = sb + s * G2_STAGE;

        #pragma unroll
        for (int ks = 0; ks < 4; ks++) {
            const int cb = ks * 2;
            uint32_t ah[4][4], al[4][4];
            #pragma unroll
            for (int ms = 0; ms < 4; ms++) {
                int r = wy * 64 + ms * 16 + (lane & 15);
                int ch = cb + (lane >> 4);
                ldsm_x4(ah[ms][0], ah[ms][1], ah[ms][2], ah[ms][3], swz(stA, r, ch));
                ldsm_x4(al[ms][0], al[ms][1], al[ms][2], al[ms][3], swz(stA + 16384, r, ch));
            }
            uint32_t bh[4][2], bl[4][2];
            #pragma unroll
            for (int nh = 0; nh < 2; nh++) {
                int g = lane >> 3;
                int r = wx * 32 + nh * 16 + ((g & 2) << 2) + (lane & 7);
                int ch = cb + (g & 1);
                uint32_t r0, r1, r2, r3;
                ldsm_x4(r0, r1, r2, r3, swz(stA + 32768, r, ch));
                bh[nh*2][0] = r0; bh[nh*2][1] = r1;
                bh[nh*2+1][0] = r2; bh[nh*2+1][1] = r3;
                ldsm_x4(r0, r1, r2, r3, swz(stA + 49152, r, ch));
                bl[nh*2][0] = r0; bl[nh*2][1] = r1;
                bl[nh*2+1][0] = r2; bl[nh*2+1][1] = r3;
            }
            #pragma unroll
            for (int ms = 0; ms < 4; ms++)
                #pragma unroll
                for (int ns = 0; ns < 4; ns++) {
                    mma16816(acc[ms][ns], ah[ms], bh[ns]);
                    mma16816(acc[ms][ns], ah[ms], bl[ns]);
                    mma16816(acc[ms][ns], al[ms], bh[ns]);
                }
        }
        __syncthreads();
        s = (s == 2) ? 0 : s + 1;
    }

    // ---- epilogue ----
    const int qrow = lane >> 2, qcol = (lane & 3) * 2;
    #pragma unroll
    for (int ms = 0; ms < 4; ms++) {
        int m = brow + wy * 64 + ms * 16 + qrow;
        bool ok0 = !gmode || (m < cnt);
        bool ok1 = !gmode || (m + 8 < cnt);
        int crow0 = (gmode == 2 && ok0) ? slist[m - brow] : m;
        int crow1 = (gmode == 2 && ok1) ? slist[m + 8 - brow] : m + 8;
        #pragma unroll
        for (int ns = 0; ns < 4; ns++) {
            int n = bcol + wx * 32 + ns * 8 + qcol;
            float2 v0 = make_float2(acc[ms][ns][0], acc[ms][ns][1]);
            float2 v1 = make_float2(acc[ms][ns][2], acc[ms][ns][3]);
            if (bias) {
                float b0 = bias[n], b1 = bias[n + 1];
                v0.x += b0; v0.y += b1; v1.x += b0; v1.y += b1;
            }
            if (res) {
                float2 r0 = *(const float2*)(res + (long long)m * N + n);
                float2 r1 = *(const float2*)(res + (long long)(m + 8) * N + n);
                v0.x += r0.x; v0.y += r0.y; v1.x += r1.x; v1.y += r1.y;
            }
            if (relu) {
                v0.x = fmaxf(v0.x, 0.f); v0.y = fmaxf(v0.y, 0.f);
                v1.x = fmaxf(v1.x, 0.f); v1.y = fmaxf(v1.y, 0.f);
            }
            if (C) {
                if (ok0) *(float2*)(C + (long long)crow0 * N + n) = v0;
                if (ok1) *(float2*)(C + (long long)crow1 * N + n) = v1;
            }
            uint32_t hp0 = pack_bf2(v0.x, v0.y);
            uint32_t hp1 = pack_bf2(v1.x, v1.y);
            uint32_t lp0 = pack_bf2(v0.x - bf_lo(hp0), v0.y - bf_hi(hp0));
            uint32_t lp1 = pack_bf2(v1.x - bf_lo(hp1), v1.y - bf_hi(hp1));
            if (Sp) {
                long long r0 = (long long)m * 2 * N, r1 = (long long)(m + 8) * 2 * N;
                if (ok0) {
                    *(uint32_t*)(Sp + r0 + n)     = hp0;
                    *(uint32_t*)(Sp + r0 + N + n) = lp0;
                }
                if (ok1) {
                    *(uint32_t*)(Sp + r1 + n)     = hp1;
                    *(uint32_t*)(Sp + r1 + N + n) = lp1;
                }
            }
            if (KH) {
                long long a0 = (((long long)((m >> 10) * 8 + (n >> 6))) * 1024 + (m & 1023)) * 64 + (n & 63);
                long long a1 = a0 + 8LL * 64;
                *(uint32_t*)(KH + a0) = hp0;  *(uint32_t*)(KL + a0) = lp0;
                *(uint32_t*)(KH + a1) = hp1;  *(uint32_t*)(KL + a1) = lp1;
            }
            if (VH) {
                int b = m >> 10, h = n >> 6, d = n & 63, si = m & 1023;
                long long base = (((long long)(z * 32 + b * 8 + h)) * 64 + d) * 1024 + si;
                unsigned short* vh = (unsigned short*)VH;
                unsigned short* vl = (unsigned short*)VL;
                vh[base]            = (unsigned short)(hp0 & 0xffff);
                vh[base + 1024]     = (unsigned short)(hp0 >> 16);
                vh[base + 8]        = (unsigned short)(hp1 & 0xffff);
                vh[base + 1024 + 8] = (unsigned short)(hp1 >> 16);
                vl[base]            = (unsigned short)(lp0 & 0xffff);
                vl[base + 1024]     = (unsigned short)(lp0 >> 16);
                vl[base + 8]        = (unsigned short)(lp1 & 0xffff);
                vl[base + 1024 + 8] = (unsigned short)(lp1 >> 16);
            }
        }
    }
}

// ================= tensor-core flash attention ===============================
#define ATTN_SMEM 81920

__global__ __launch_bounds__(128) void attn_mma_kernel(
    const __nv_bfloat16* __restrict__ khh, const __nv_bfloat16* __restrict__ khl,
    const __nv_bfloat16* __restrict__ vth, const __nv_bfloat16* __restrict__ vtl,
    __nv_bfloat16* __restrict__ Cx)
{
    extern __shared__ __align__(1024) char smem[];
    const uint32_t sb = smem_u32(smem);
    const int tid = threadIdx.x, wid = tid >> 5, lane = tid & 31;
    const int qb = 15 - blockIdx.x;
    const int bh = blockIdx.y;
    const int q0 = qb * 64;

    const __nv_bfloat16* Kh = khh + (long long)bh * S_ * 64;
    const __nv_bfloat16* Kl = khl + (long long)bh * S_ * 64;
    const __nv_bfloat16* Vh = vth + (long long)bh * 64 * S_;
    const __nv_bfloat16* Vl = vtl + (long long)bh * 64 * S_;

    auto load_kv = [&](int jt, int s) {
        const int j0 = jt * 64;
        const uint32_t base = sb + 16384 + s * 32768;
        #pragma unroll
        for (int i = 0; i < 4; i++) {
            int idx = tid + i * 128;
            int r = idx >> 3, ch = idx & 7;
            cp_async16(swz(base, r, ch),
                       (const char*)(Kh + (long long)(j0 + r) * 64) + ch * 16);
            cp_async16(swz(base + 8192, r, ch),
                       (const char*)(Kl + (long long)(j0 + r) * 64) + ch * 16);
            cp_async16(swz(base + 16384, r, ch),
                       (const char*)(Vh + (long long)r * S_ + j0) + ch * 16);
            cp_async16(swz(base + 24576, r, ch),
                       (const char*)(Vl + (long long)r * S_ + j0) + ch * 16);
        }
        CP_COMMIT();
    };

    #pragma unroll
    for (int i = 0; i < 4; i++) {
        int idx = tid + i * 128;
        int r = idx >> 3, ch = idx & 7;
        cp_async16(swz(sb, r, ch),
                   (const char*)(Kh + (long long)(q0 + r) * 64) + ch * 16);
        cp_async16(swz(sb + 8192, r, ch),
                   (const char*)(Kl + (long long)(q0 + r) * 64) + ch * 16);
    }
    load_kv(0, 0);
    CP_WAIT0();
    __syncthreads();

    uint32_t qh[4][4], ql[4][4];
    #pragma unroll
    for (int ks = 0; ks < 4; ks++) {
        int r = wid * 16 + (lane & 15);
        int ch = 2 * ks + (lane >> 4);
        ldsm_x4(qh[ks][0], qh[ks][1], qh[ks][2], qh[ks][3], swz(sb, r, ch));
        ldsm_x4(ql[ks][0], ql[ks][1], ql[ks][2], ql[ks][3], swz(sb + 8192, r, ch));
    }

    float ctx[8][4] = {};
    float m0 = NEG_INF, m1 = NEG_INF, l0 = 0.f, l1 = 0.f;
    const int rg0 = q0 + wid * 16 + (lane >> 2);

    for (int jt = 0; jt <= qb; jt++) {
        const int s = jt & 1;
        if (jt < qb) { load_kv(jt + 1, s ^ 1); CP_WAIT1(); }
        else if (jt > 0) { CP_WAIT0(); }
        __syncthreads();

        const uint32_t bK = sb + 16384 + s * 32768;

        float sc[8][4] = {};
        #pragma unroll
        for (int ks = 0; ks < 4; ks++) {
            uint32_t bh_[8][2], bl_[8][2];
            #pragma unroll
            for (int ng = 0; ng < 4; ng++) {
                int g = lane >> 3;
                int r = ng * 16 + ((g & 2) << 2) + (lane & 7);
                int ch = 2 * ks + (g & 1);
                uint32_t a0, a1, a2, a3;
                ldsm_x4(a0, a1, a2, a3, swz(bK, r, ch));
                bh_[2*ng][0] = a0; bh_[2*ng][1] = a1;
                bh_[2*ng+1][0] = a2; bh_[2*ng+1][1] = a3;
                ldsm_x4(a0, a1, a2, a3, swz(bK + 8192, r, ch));
                bl_[2*ng][0] = a0; bl_[2*ng][1] = a1;
                bl_[2*ng+1][0] = a2; bl_[2*ng+1][1] = a3;
            }
            #pragma unroll
            for (int nt = 0; nt < 8; nt++) {
                mma16816(sc[nt], qh[ks], bh_[nt]);
                mma16816(sc[nt], qh[ks], bl_[nt]);
                mma16816(sc[nt], ql[ks], bh_[nt]);
            }
        }

        const int j0 = jt * 64;
        const bool diag = (jt == qb);
        const int cb0 = j0 + (lane & 3) * 2;
        float rm0 = NEG_INF, rm1 = NEG_INF;
        #pragma unroll
        for (int nt = 0; nt < 8; nt++) {
            int c0 = cb0 + nt * 8, c1 = c0 + 1;
            float s0 = sc[nt][0] * 0.125f, s1 = sc[nt][1] * 0.125f;
            float s2 = sc[nt][2] * 0.125f, s3 = sc[nt][3] * 0.125f;
            if (diag) {
                if (c0 >= rg0)     s0 = NEG_INF;
                if (c1 >= rg0)     s1 = NEG_INF;
                if (c0 >= rg0 + 8) s2 = NEG_INF;
                if (c1 >= rg0 + 8) s3 = NEG_INF;
            }
            sc[nt][0] = s0; sc[nt][1] = s1; sc[nt][2] = s2; sc[nt][3] = s3;
            rm0 = fmaxf(rm0, fmaxf(s0, s1));
            rm1 = fmaxf(rm1, fmaxf(s2, s3));
        }
        #pragma unroll
        for (int o = 1; o <= 2; o <<= 1) {
            rm0 = fmaxf(rm0, __shfl_xor_sync(0xffffffffu, rm0, o));
            rm1 = fmaxf(rm1, __shfl_xor_sync(0xffffffffu, rm1, o));
        }
        float mn0 = fmaxf(m0, rm0), mn1 = fmaxf(m1, rm1);
        float ms0 = (mn0 == NEG_INF) ? 0.f : mn0;
        float ms1 = (mn1 == NEG_INF) ? 0.f : mn1;
        float cr0 = __expf(m0 - ms0), cr1 = __expf(m1 - ms1);
        float rs0 = 0.f, rs1 = 0.f;
        #pragma unroll
        for (int nt = 0; nt < 8; nt++) {
            sc[nt][0] = __expf(sc[nt][0] - ms0); rs0 += sc[nt][0];
            sc[nt][1] = __expf(sc[nt][1] - ms0); rs0 += sc[nt][1];
            sc[nt][2] = __expf(sc[nt][2] - ms1); rs1 += sc[nt][2];
            sc[nt][3] = __expf(sc[nt][3] - ms1); rs1 += sc[nt][3];
        }
        #pragma unroll
        for (int o = 1; o <= 2; o <<= 1) {
            rs0 += __shfl_xor_sync(0xffffffffu, rs0, o);
            rs1 += __shfl_xor_sync(0xffffffffu, rs1, o);
        }
        l0 = l0 * cr0 + rs0; l1 = l1 * cr1 + rs1;
        m0 = mn0; m1 = mn1;
        #pragma unroll
        for (int nt = 0; nt < 8; nt++) {
            ctx[nt][0] *= cr0; ctx[nt][1] *= cr0;
            ctx[nt][2] *= cr1; ctx[nt][3] *= cr1;
        }

        uint32_t ph[4][4], pl[4][4];
        #pragma unroll
        for (int kj = 0; kj < 4; kj++) {
            const int t0 = 2 * kj, t1 = 2 * kj + 1;
            ph[kj][0] = pack_bf2(sc[t0][0], sc[t0][1]);
            ph[kj][1] = pack_bf2(sc[t0][2], sc[t0][3]);
            ph[kj][2] = pack_bf2(sc[t1][0], sc[t1][1]);
            ph[kj][3] = pack_bf2(sc[t1][2], sc[t1][3]);
            pl[kj][0] = pack_bf2(sc[t0][0] - bf_lo(ph[kj][0]), sc[t0][1] - bf_hi(ph[kj][0]));
            pl[kj][1] = pack_bf2(sc[t0][2] - bf_lo(ph[kj][1]), sc[t0][3] - bf_hi(ph[kj][1]));
            pl[kj][2] = pack_bf2(sc[t1][0] - bf_lo(ph[kj][2]), sc[t1][1] - bf_hi(ph[kj][2]));
            pl[kj][3] = pack_bf2(sc[t1][2] - bf_lo(ph[kj][3]), sc[t1][3] - bf_hi(ph[kj][3]));
        }

        const uint32_t bV = bK + 16384;
        #pragma unroll
        for (int kj = 0; kj < 4; kj++) {
            uint32_t vh_[8][2], vl_[8][2];
            #pragma unroll
            for (int dg = 0; dg < 4; dg++) {
                int g = lane >> 3;
                int r = dg * 16 + ((g & 2) << 2) + (lane & 7);
                int ch = 2 * kj + (g & 1);
                uint32_t a0, a1, a2, a3;
                ldsm_x4(a0, a1, a2, a3, swz(bV, r, ch));
                vh_[2*dg][0] = a0; vh_[2*dg][1] = a1;
                vh_[2*dg+1][0] = a2; vh_[2*dg+1][1] = a3;
                ldsm_x4(a0, a1, a2, a3, swz(bV + 8192, r, ch));
                vl_[2*dg][0] = a0; vl_[2*dg][1] = a1;
                vl_[2*dg+1][0] = a2; vl_[2*dg+1][1] = a3;
            }
            #pragma unroll
            for (int nt = 0; nt < 8; nt++) {
                mma16816(ctx[nt], ph[kj], vh_[nt]);
                mma16816(ctx[nt], ph[kj], vl_[nt]);
                mma16816(ctx[nt], pl[kj], vh_[nt]);
            }
        }
        __syncthreads();
    }

    float inv0 = (l0 > 0.f) ? 1.f / l0 : 0.f;
    float inv1 = (l1 > 0.f) ? 1.f / l1 : 0.f;
    const int b = bh >> 3, h = bh & 7;
    const int row0 = b * S_ + q0 + wid * 16 + (lane >> 2);
    const int colb = h * 64 + (lane & 3) * 2;
    #pragma unroll
    for (int nt = 0; nt < 8; nt++) {
        float a0 = ctx[nt][0] * inv0, a1 = ctx[nt][1] * inv0;
        float a2 = ctx[nt][2] * inv1, a3 = ctx[nt][3] * inv1;
        uint32_t hp0 = pack_bf2(a0, a1);
        uint32_t hp1 = pack_bf2(a2, a3);
        uint32_t lp0 = pack_bf2(a0 - bf_lo(hp0), a1 - bf_hi(hp0));
        uint32_t lp1 = pack_bf2(a2 - bf_lo(hp1), a3 - bf_hi(hp1));
        long long r0 = (long long)row0 * 1024, r1 = (long long)(row0 + 8) * 1024;
        int cc = colb + nt * 8;
        *(uint32_t*)(Cx + r0 + cc)       = hp0;
        *(uint32_t*)(Cx + r0 + 512 + cc) = lp0;
        *(uint32_t*)(Cx + r1 + cc)       = hp1;
        *(uint32_t*)(Cx + r1 + 512 + cc) = lp1;
    }
}

// ---------------- positional embedding (also zero gate counters) -----------
__global__ void pe_kernel(float* __restrict__ pe) {
    if (blockIdx.x == 0 && threadIdx.x < 4) g_cnt[threadIdx.x] = 0;
    int s = blockIdx.x;
    int j = threadIdx.x;
    float div = expf((float)(2*j) * (-9.210340371976184f / (float)D_));
    float arg = (float)s * div;
    pe[s*D_ + 2*j]     = sinf(arg);
    pe[s*D_ + 2*j + 1] = cosf(arg);
}

__global__ __launch_bounds__(256) void add_pe_kernel(
    const float* __restrict__ qa, const float* __restrict__ pe,
    __nv_bfloat16* __restrict__ yb)
{
    int i = blockIdx.x * 256 + threadIdx.x;
    float v = qa[i] + pe[i & (S_*D_ - 1)];
    int m = i >> 9, c = i & 511;
    __nv_bfloat16 h = __float2bfloat16_rn(v);
    yb[(long long)m * 1024 + c]       = h;
    yb[(long long)m * 1024 + 512 + c] = __float2bfloat16_rn(v - __bfloat162float(h));
}

// ---------------- gate: logits -> top-2 weights + expert row lists ----------
__global__ __launch_bounds__(256) void gate_kernel(
    const float* __restrict__ summary, const float* __restrict__ m_seq,
    const float* __restrict__ gate_w,  const float* __restrict__ gate_b,
    float* __restrict__ wgt, int* __restrict__ cnt, int* __restrict__ list)
{
    __shared__ float red[4][8];
    const int row = blockIdx.x;
    const int tid = threadIdx.x;

    float p0 = 0, p1 = 0, p2 = 0, p3 = 0;
    for (int e = tid; e < D_ + SD_; e += 256) {
        float xv = (e < D_) ? summary[(long long)row * D_ + e]
                            : m_seq[(long long)row * SD_ + (e - D_)];
        float4 w = *(const float4*)(gate_w + e * 4);
        p0 += xv * w.x; p1 += xv * w.y; p2 += xv * w.z; p3 += xv * w.w;
    }
    #pragma unroll
    for (int o = 16; o > 0; o >>= 1) {
        p0 += __shfl_xor_sync(0xffffffffu, p0, o);
        p1 += __shfl_xor_sync(0xffffffffu, p1, o);
        p2 += __shfl_xor_sync(0xffffffffu, p2, o);
        p3 += __shfl_xor_sync(0xffffffffu, p3, o);
    }
    if ((tid & 31) == 0) {
        int w = tid >> 5;
        red[0][w] = p0; red[1][w] = p1; red[2][w] = p2; red[3][w] = p3;
    }
    __syncthreads();

    if (tid == 0) {
        float l[4];
        #pragma unroll
        for (int j = 0; j < 4; j++) {
            float t = gate_b[j];
            #pragma unroll
            for (int w = 0; w < 8; w++) t += red[j][w];
            l[j] = t;
        }
        float m1v = -INFINITY, m2v = -INFINITY;
        #pragma unroll
        for (int j = 0; j < 4; j++) {
            if (l[j] > m1v) { m2v = m1v; m1v = l[j]; }
            else if (l[j] > m2v) { m2v = l[j]; }
        }
        float sum = 0.f, e4[4];
        #pragma unroll
        for (int j = 0; j < 4; j++) {
            e4[j] = (l[j] >= m2v) ? __expf(l[j] - m1v) : 0.f;
            sum += e4[j];
        }
        #pragma unroll
        for (int j = 0; j < 4; j++) {
            wgt[row * 4 + j] = e4[j] / sum;
            if (l[j] >= m2v) {
                int p = atomicAdd(&cnt[j], 1);
                list[j * BS + p] = row;
            }
        }
    }
}

// ---------------- MoE combine + LN + PE -> x (fp32 + split) ----------------
__global__ __launch_bounds__(256) void moe_kernel(
    const float* __restrict__ wgt, const float* __restrict__ experts,
    const float* __restrict__ lng, const float* __restrict__ lnb,
    const float* __restrict__ pe, float* __restrict__ x,
    __nv_bfloat16* __restrict__ xb)
{
    __shared__ float r1[8], r2[8];
    const int row = blockIdx.x;
    const int tid = threadIdx.x;
    const int s_idx = row & (S_ - 1);

    const float w0 = wgt[row*4], w1 = wgt[row*4+1], w2 = wgt[row*4+2], w3 = wgt[row*4+3];
    const long long base = (long long)row * D_;
    const int t2 = tid + 256;
    float c0 = w0 * experts[0*BSD + base + tid] + w1 * experts[1*BSD + base + tid]
             + w2 * experts[2*BSD + base + tid] + w3 * experts[3*BSD + base + tid];
    float c1 = w0 * experts[0*BSD + base + t2]  + w1 * experts[1*BSD + base + t2]
             + w2 * experts[2*BSD + base + t2]  + w3 * experts[3*BSD + base + t2];

    float s = c0 + c1, q = c0 * c0 + c1 * c1;
    #pragma unroll
    for (int o = 16; o > 0; o >>= 1) {
        s += __shfl_xor_sync(0xffffffffu, s, o);
        q += __shfl_xor_sync(0xffffffffu, q, o);
    }
    if ((tid & 31) == 0) { r1[tid >> 5] = s; r2[tid >> 5] = q; }
    __syncthreads();
    float ts = 0, tq = 0;
    #pragma unroll
    for (int w = 0; w < 8; w++) { ts += r1[w]; tq += r2[w]; }
    float mu = ts * (1.f / 512.f);
    float var = tq * (1.f / 512.f) - mu * mu;
    float rstd = rsqrtf(var + 1e-5f);

    float o0 = (c0 - mu) * rstd * lng[tid] + lnb[tid] + pe[s_idx * D_ + tid];
    float o1 = (c1 - mu) * rstd * lng[t2]  + lnb[t2]  + pe[s_idx * D_ + t2];
    x[base + tid] = o0;
    x[base + t2]  = o1;
    long long b2 = (long long)row * 1024;
    __nv_bfloat16 h0 = __float2bfloat16_rn(o0);
    __nv_bfloat16 h1 = __float2bfloat16_rn(o1);
    xb[b2 + tid]        = h0;
    xb[b2 + t2]         = h1;
    xb[b2 + 512 + tid]  = __float2bfloat16_rn(o0 - __bfloat162float(h0));
    xb[b2 + 512 + t2]   = __float2bfloat16_rn(o1 - __bfloat162float(h1));
}

// ---------------- LayerNorm (fp32 out + optional split) --------------------
__global__ __launch_bounds__(256) void ln_kernel(
    const float* __restrict__ in, const float* __restrict__ g,
    const float* __restrict__ b, float* __restrict__ out,
    __nv_bfloat16* __restrict__ sp)
{
    __shared__ float r1[8], r2[8];
    const int row = blockIdx.x, tid = threadIdx.x;
    const long long base = (long long)row * D_;
    float v0 = in[base + tid], v1 = in[base + tid + 256];
    float s = v0 + v1, q = v0 * v0 + v1 * v1;
    #pragma unroll
    for (int o = 16; o > 0; o >>= 1) {
        s += __shfl_xor_sync(0xffffffffu, s, o);
        q += __shfl_xor_sync(0xffffffffu, q, o);
    }
    if ((tid & 31) == 0) { r1[tid >> 5] = s; r2[tid >> 5] = q; }
    __syncthreads();
    float ts = 0, tq = 0;
    #pragma unroll
    for (int w = 0; w < 8; w++) { ts += r1[w]; tq += r2[w]; }
    float mu = ts * (1.f / 512.f);
    float var = tq * (1.f / 512.f) - mu * mu;
    float rstd = rsqrtf(var + 1e-5f);
    float o0 = (v0 - mu) * rstd * g[tid]       + b[tid];
    float o1 = (v1 - mu) * rstd * g[tid + 256] + b[tid + 256];
    out[base + tid]       = o0;
    out[base + tid + 256] = o1;
    if (sp) {
        long long b2 = (long long)row * 1024;
        __nv_bfloat16 h0 = __float2bfloat16_rn(o0);
        __nv_bfloat16 h1 = __float2bfloat16_rn(o1);
        sp[b2 + tid]       = h0;
        sp[b2 + tid + 256] = h1;
        sp[b2 + 512 + tid]       = __float2bfloat16_rn(o0 - __bfloat162float(h0));
        sp[b2 + 512 + tid + 256] = __float2bfloat16_rn(o1 - __bfloat162float(h1));
    }
}

// ================= host wrapper ==============================================
typedef __nv_bfloat16 bf16;

static void gemmL(const bf16* Ah, int loA, int ldA, long long zA,
                  const bf16* Bt, long long zB, int K,
                  const float* bias, int sBias, const float* res,
                  float* C, long long sC, bf16* Sp, long long zSp,
                  bf16* KH, bf16* KL, bf16* VH, bf16* VL,
                  const int* glist, const int* gcnt, int gmode,
                  int N, int nz, int relu)
{
    gemm2_kernel<<<dim3(N/128, 32, nz), 256, G2_SMEM>>>(
        Ah, loA, ldA, zA, Bt, zB, K, bias, sBias, res, C, sC,
        Sp, zSp, KH, KL, VH, VL, glist, gcnt, gmode, N, relu);
}

extern "C" void kernel_launch(void* const* d_in, const int* in_sizes, int n_in,
                              void* d_out, int out_size)
{
    const float* q_raw   = (const float*)d_in[0];
    const float* m_seq   = (const float*)d_in[1];
    const float* qa      = (const float*)d_in[2];
    const float* exp_w1  = (const float*)d_in[3];
    const float* exp_b1  = (const float*)d_in[4];
    const float* exp_w2  = (const float*)d_in[5];
    const float* exp_b2  = (const float*)d_in[6];
    const float* adapt_w = (const float*)d_in[7];
    const float* adapt_b = (const float*)d_in[8];
    const float* gate_w  = (const float*)d_in[9];
    const float* gate_b  = (const float*)d_in[10];
    const float* kw      = (const float*)d_in[13];
    const float* kb      = (const float*)d_in[14];
    const float* vw      = (const float*)d_in[15];
    const float* vb      = (const float*)d_in[16];
    const float* ow      = (const float*)d_in[17];
    const float* ob      = (const float*)d_in[18];
    const float* ln1g    = (const float*)d_in[19];
    const float* ln1b    = (const float*)d_in[20];
    const float* fw1     = (const float*)d_in[21];
    const float* fb1     = (const float*)d_in[22];
    const float* fw2     = (const float*)d_in[23];
    const float* fb2     = (const float*)d_in[24];
    const float* ln2g    = (const float*)d_in[25];
    const float* ln2b    = (const float*)d_in[26];
    const float* moe_g   = (const float*)d_in[11];
    const float* moe_b   = (const float*)d_in[12];

    float *pe, *x, *experts, *summary, *wgtp;
    int *cntp, *listp;
    bf16 *qbf, *h1bf, *ybf, *xbf, *ctxbf, *ffnbf, *wbf, *khh, *khl, *vth, *vtl;
    cudaGetSymbolAddress((void**)&pe, g_pe);
    cudaGetSymbolAddress((void**)&x, g_x);
    cudaGetSymbolAddress((void**)&experts, g_experts);
    cudaGetSymbolAddress((void**)&summary, g_summary);
    cudaGetSymbolAddress((void**)&wgtp, g_wgt);
    cudaGetSymbolAddress((void**)&cntp, g_cnt);
    cudaGetSymbolAddress((void**)&listp, g_list);
    cudaGetSymbolAddress((void**)&qbf, g_qbf);
    cudaGetSymbolAddress((void**)&h1bf, g_h1bf);
    cudaGetSymbolAddress((void**)&ybf, g_ybf);
    cudaGetSymbolAddress((void**)&xbf, g_xbf);
    cudaGetSymbolAddress((void**)&ctxbf, g_ctxbf);
    cudaGetSymbolAddress((void**)&ffnbf, g_ffnbf);
    cudaGetSymbolAddress((void**)&wbf, g_wbf);
    cudaGetSymbolAddress((void**)&khh, g_khh);
    cudaGetSymbolAddress((void**)&khl, g_khl);
    cudaGetSymbolAddress((void**)&vth, g_vth);
    cudaGetSymbolAddress((void**)&vtl, g_vtl);

    static int attr_set = 0;
    if (!attr_set) {
        cudaFuncSetAttribute(gemm2_kernel,
                             cudaFuncAttributeMaxDynamicSharedMemorySize, G2_SMEM);
        cudaFuncSetAttribute(attn_mma_kernel,
                             cudaFuncAttributeMaxDynamicSharedMemorySize, ATTN_SMEM);
        attr_set = 1;
    }

    // 0: pe (+ zero gate counters)
    pe_kernel<<<S_, 256>>>(pe);
    // 1: q_raw split
    conv_qraw_kernel<<<4096 * 768 / 256, 256>>>(q_raw, qbf);
    // 2: ALL weights -> split bf16, one launch
    {
        ConvSegs cs;
        cs.src[0] = exp_w1;  cs.dstOff[0] = W_EXPW1; cs.K[0] = 768;  cs.N[0] = 768;  cs.tOff[0] = 0;
        cs.src[1] = exp_w2;  cs.dstOff[1] = W_EXPW2; cs.K[1] = 768;  cs.N[1] = 512;  cs.tOff[1] = 2304;
        cs.src[2] = adapt_w; cs.dstOff[2] = W_ADAPT; cs.K[2] = 3072; cs.N[2] = 512;  cs.tOff[2] = 3840;
        cs.src[3] = kw;      cs.dstOff[3] = W_KW;    cs.K[3] = 512;  cs.N[3] = 512;  cs.tOff[3] = 5376;
        cs.src[4] = vw;      cs.dstOff[4] = W_VW;    cs.K[4] = 512;  cs.N[4] = 512;  cs.tOff[4] = 6400;
        cs.src[5] = ow;      cs.dstOff[5] = W_OW;    cs.K[5] = 512;  cs.N[5] = 512;  cs.tOff[5] = 7424;
        cs.src[6] = fw1;     cs.dstOff[6] = W_FW1;   cs.K[6] = 512;  cs.N[6] = 2048; cs.tOff[6] = 8448;
        cs.src[7] = fw2;     cs.dstOff[7] = W_FW2;   cs.K[7] = 2048; cs.N[7] = 512;  cs.tOff[7] = 12544;
        convB_all_kernel<<<16640, dim3(32, 8)>>>(cs, wbf);
    }
    // 3: summary = relu(q_flat @ adapt_w + b)
    gemmL(qbf, 3072, 6144, 0, wbf + W_ADAPT, 0, 3072, adapt_b, 0, nullptr,
          summary, 0, nullptr, 0, nullptr, nullptr, nullptr, nullptr,
          nullptr, nullptr, 0, 512, 1, 1);
    // 4: gate -> weights + expert row lists
    gate_kernel<<<BS, 256>>>(summary, m_seq, gate_w, gate_b, wgtp, cntp, listp);
    // 5: h1 = relu(gathered q_raw @ exp_w1 + b1) -> compacted split   [ncu capture]
    gemmL(qbf, 3072, 6144, 768, wbf + W_EXPW1, 768LL*1536, 768, exp_b1, IN_, nullptr,
          nullptr, 0, h1bf, (long long)BS * 1536, nullptr, nullptr, nullptr, nullptr,
          listp, cntp, 1, 768, NS_, 1);
    // 6: experts = compacted h1 @ exp_w2 + b2 -> scattered fp32
    gemmL(h1bf, 768, 1536, (long long)BS * 1536, wbf + W_EXPW2, 512LL*1536, 768,
          exp_b2, D_, nullptr, experts, BSD, nullptr, 0,
          nullptr, nullptr, nullptr, nullptr, listp, cntp, 2, 512, NS_, 0);
    // 7: combine + moe LN + pe
    moe_kernel<<<BS, 256>>>(wgtp, experts, moe_g, moe_b, pe, x, xbf);
    // 8: y' = qa + pe split
    add_pe_kernel<<<(int)(BSD / 256), 256>>>(qa, pe, ybf);
    // 9: V for all layers -> transposed split
    gemmL(ybf, 512, 1024, 0, wbf + W_VW, 512LL*1024, 512, vb, D_, nullptr,
          nullptr, 0, nullptr, 0, nullptr, nullptr, vth, vtl,
          nullptr, nullptr, 0, 512, L_, 0);

    for (int i = 0; i < L_; i++) {
        gemmL(xbf, 512, 1024, 0, wbf + W_KW + (long long)i * 524288, 0, 512,
              kb + i*D_, 0, nullptr, nullptr, 0, nullptr, 0,
              khh, khl, nullptr, nullptr, nullptr, nullptr, 0, 512, 1, 0);
        attn_mma_kernel<<<dim3(16, 32), 128, ATTN_SMEM>>>(
            khh, khl, vth + (long long)i * 2097152, vtl + (long long)i * 2097152, ctxbf);
        gemmL(ctxbf, 512, 1024, 0, wbf + W_OW + (long long)i * 524288, 0, 512,
              ob + i*D_, 0, x, x, 0, nullptr, 0,
              nullptr, nullptr, nullptr, nullptr, nullptr, nullptr, 0, 512, 1, 0);
        ln_kernel<<<BS, 256>>>(x, ln1g + i*D_, ln1b + i*D_, x, xbf);
        gemmL(xbf, 512, 1024, 0, wbf + W_FW1 + (long long)i * 2097152, 0, 512,
              fb1 + i*FF_, 0, nullptr, nullptr, 0, ffnbf, 0,
              nullptr, nullptr, nullptr, nullptr, nullptr, nullptr, 0, 2048, 1, 1);
        gemmL(ffnbf, 2048, 4096, 0, wbf + W_FW2 + (long long)i * 2097152, 0, 2048,
              fb2 + i*D_, 0, x, x, 0, nullptr, 0,
              nullptr, nullptr, nullptr, nullptr, nullptr, nullptr, 0, 512, 1, 0);
        ln_kernel<<<BS, 256>>>(x, ln2g + i*D_, ln2b + i*D_,
                               (i == L_-1) ? (float*)d_out : x,
                               (i == L_-1) ? nullptr : xbf);
    }
}

// round 9
// speedup vs baseline: 3.5733x; 1.0100x over previous
#include <cuda_runtime.h>
#include <cuda_bf16.h>
#include <cstdint>
#include <math.h>

// Problem dims
#define B_  4
#define S_  1024
#define D_  512
#define H_  8
#define DK_ 64
#define FF_ 2048
#define L_  4
#define IN_ 768
#define NS_ 4
#define SD_ 64

#define BS  (B_*S_)            // 4096
#define BSD ((long long)BS*D_) // 2097152
#define NEG_INF __int_as_float(0xff800000)

// ---------------- scratch (device globals: allocation-free) ----------------
__device__ float g_pe[S_*D_];
__device__ float g_x[BS*D_];
__device__ float g_experts[NS_*BS*D_];
__device__ float g_summary[BS*D_];
__device__ float g_wgt[BS*4];
__device__ int   g_cnt[4];
__device__ int   g_list[4*BS];
// split bf16 buffers, layout [m][hi K | lo K]
__device__ __nv_bfloat16 g_qbf[25165824];    // q_raw' [4096][6144]
__device__ __nv_bfloat16 g_h1bf[25165824];   // h1'   [4][4096][1536] (compacted slots)
__device__ __nv_bfloat16 g_ybf[4194304];     // y'    [4096][1024]
__device__ __nv_bfloat16 g_xbf[4194304];     // x'    [4096][1024]
__device__ __nv_bfloat16 g_ctxbf[4194304];   // ctx'  [4096][1024]
__device__ __nv_bfloat16 g_ffnbf[16777216];  // ffn'  [4096][4096]
__device__ __nv_bfloat16 g_khh[2097152];     // K hi [32][1024][64]
__device__ __nv_bfloat16 g_khl[2097152];
__device__ __nv_bfloat16 g_vth[8388608];     // Vt hi [4][32][64][1024]
__device__ __nv_bfloat16 g_vtl[8388608];
// all weights, split bf16 [n][hiK|loK]
__device__ __nv_bfloat16 g_wbf[34078720];

// weight buffer offsets (bf16 elements)
#define W_EXPW1 0LL
#define W_EXPW2 4718592LL
#define W_ADAPT 7864320LL
#define W_KW    11010048LL
#define W_VW    13107200LL
#define W_OW    15204352LL
#define W_FW1   17301504LL
#define W_FW2   25690112LL

// ================= PTX helpers ===============================================
__device__ __forceinline__ uint32_t smem_u32(const void* p) {
    uint32_t a;
    asm("{ .reg .u64 t; cvta.to.shared.u64 t, %1; cvt.u32.u64 %0, t; }" : "=r"(a) : "l"(p));
    return a;
}
__device__ __forceinline__ void cp_async16(uint32_t dst, const void* src) {
    asm volatile("cp.async.cg.shared.global [%0], [%1], 16;" :: "r"(dst), "l"(src));
}
#define CP_COMMIT() asm volatile("cp.async.commit_group;" ::: "memory")
#define CP_WAIT0()  asm volatile("cp.async.wait_group 0;" ::: "memory")
#define CP_WAIT1()  asm volatile("cp.async.wait_group 1;" ::: "memory")

__device__ __forceinline__ void ldsm_x4(uint32_t& r0, uint32_t& r1, uint32_t& r2,
                                        uint32_t& r3, uint32_t addr) {
    asm volatile("ldmatrix.sync.aligned.m8n8.x4.shared.b16 {%0,%1,%2,%3}, [%4];"
        : "=r"(r0), "=r"(r1), "=r"(r2), "=r"(r3) : "r"(addr));
}
__device__ __forceinline__ void mma16816(float* c, const uint32_t* a, const uint32_t* b) {
    asm volatile(
        "mma.sync.aligned.m16n8k16.row.col.f32.bf16.bf16.f32 "
        "{%0,%1,%2,%3}, {%4,%5,%6,%7}, {%8,%9}, {%0,%1,%2,%3};"
        : "+f"(c[0]), "+f"(c[1]), "+f"(c[2]), "+f"(c[3])
        : "r"(a[0]), "r"(a[1]), "r"(a[2]), "r"(a[3]), "r"(b[0]), "r"(b[1]));
}
__device__ __forceinline__ uint32_t pack_bf2(float lo, float hi) {
    uint32_t d;
    asm("cvt.rn.bf16x2.f32 %0, %1, %2;" : "=r"(d) : "f"(hi), "f"(lo));
    return d;
}
__device__ __forceinline__ float bf_lo(uint32_t p) { return __uint_as_float(p << 16); }
__device__ __forceinline__ float bf_hi(uint32_t p) { return __uint_as_float(p & 0xffff0000u); }

__device__ __forceinline__ uint32_t swz(uint32_t base, int r, int ch) {
    return base + r * 128 + ((ch ^ (r & 7)) << 4);
}

// ================= conversions ==============================================
// q_raw [4096][3072] fp32 -> q' [4096][6144] = [hi 3072 | lo 3072]
__global__ __launch_bounds__(256) void conv_qraw_kernel(
    const float* __restrict__ src, __nv_bfloat16* __restrict__ dst)
{
    int idx = blockIdx.x * 256 + threadIdx.x;
    int m = idx / 768;
    int k = (idx - m * 768) * 4;
    float4 v = *(const float4*)(src + (long long)m * 3072 + k);
    unsigned short hb[4], lb[4];
    float vv[4] = {v.x, v.y, v.z, v.w};
    #pragma unroll
    for (int i = 0; i < 4; i++) {
        __nv_bfloat16 h = __float2bfloat16_rn(vv[i]);
        __nv_bfloat16 l = __float2bfloat16_rn(vv[i] - __bfloat162float(h));
        hb[i] = __bfloat16_as_ushort(h);
        lb[i] = __bfloat16_as_ushort(l);
    }
    long long base = (long long)m * 6144;
    *(uint2*)(dst + base + k) = make_uint2((uint32_t)hb[0] | ((uint32_t)hb[1] << 16),
                                           (uint32_t)hb[2] | ((uint32_t)hb[3] << 16));
    *(uint2*)(dst + base + 3072 + k) = make_uint2((uint32_t)lb[0] | ((uint32_t)lb[1] << 16),
                                                  (uint32_t)lb[2] | ((uint32_t)lb[3] << 16));
}

// all weights W [z][K][N] fp32 -> W' [z][n][2K] = [hi K | lo K], one launch
struct ConvSegs {
    const float* src[8];
    long long dstOff[8];
    int K[8], N[8], tOff[8];
};

__global__ void convB_all_kernel(ConvSegs segs, __nv_bfloat16* __restrict__ wb)
{
    __shared__ float t[32][33];
    int bx = blockIdx.x;
    int seg = 0;
    #pragma unroll
    for (int i = 7; i >= 1; i--) if (bx >= segs.tOff[i]) { seg = i; break; }
    const int K = segs.K[seg], N = segs.N[seg];
    int tl = bx - segs.tOff[seg];
    int tz = (K >> 5) * (N >> 5);
    int z = tl / tz, rr = tl - z * tz;
    int k0 = (rr % (K >> 5)) * 32, n0 = (rr / (K >> 5)) * 32;
    const float* s = segs.src[seg] + (long long)z * K * N;
    __nv_bfloat16* dstz = wb + segs.dstOff[seg] + (long long)z * N * 2 * K;
    int tx = threadIdx.x, ty = threadIdx.y;
    #pragma unroll
    for (int r = ty; r < 32; r += 8)
        t[r][tx] = s[(long long)(k0 + r) * N + n0 + tx];
    __syncthreads();
    #pragma unroll
    for (int r = ty; r < 32; r += 8) {
        float x = t[tx][r];
        __nv_bfloat16 h = __float2bfloat16_rn(x);
        __nv_bfloat16 l = __float2bfloat16_rn(x - __bfloat162float(h));
        long long base = (long long)(n0 + r) * 2 * K + k0 + tx;
        dstz[base]     = h;
        dstz[base + K] = l;
    }
}

// ================= unified split GEMM (mma.sync bf16 x3 terms) ===============
// 512 threads, 16 warps, warp tile 32x32 over 128x128 CTA tile.
// gmode: 0 = dense, 1 = gather-A rows via list (Sp at slots), 2 = scatter-C rows
#define G2_STAGE 65536
#define G2_SMEM  196608

__global__ __launch_bounds__(512, 1) void gemm2_kernel(
    const __nv_bfloat16* __restrict__ Ah0, int loA, int ldA, long long zA,
    const __nv_bfloat16* __restrict__ Bt0, long long zB, int K,
    const float* __restrict__ bias, int sBias,
    const float* __restrict__ res,
    float* __restrict__ C, long long sC,
    __nv_bfloat16* __restrict__ Sp, long long zSp,
    __nv_bfloat16* __restrict__ KH, __nv_bfloat16* __restrict__ KL,
    __nv_bfloat16* __restrict__ VH, __nv_bfloat16* __restrict__ VL,
    const int* __restrict__ glist, const int* __restrict__ gcnt,
    int gmode, int N, int relu)
{
    extern __shared__ __align__(1024) char smem[];
    __shared__ int slist[128];
    const int tid = threadIdx.x, wid = tid >> 5, lane = tid & 31;
    const int wy = wid >> 2, wx = wid & 3;       // 4x4 warps, 32x32 each
    const int z = blockIdx.z;
    const int brow = blockIdx.y * 128, bcol = blockIdx.x * 128;

    int cnt = 0;
    if (gmode) {
        cnt = gcnt[z];
        if (brow >= cnt) return;
        if (tid < 128) {
            int i = brow + tid;
            slist[tid] = glist[z * BS + (i < cnt ? i : cnt - 1)];
        }
    }

    const __nv_bfloat16* Ahz = Ah0 + (long long)z * zA;
    const __nv_bfloat16* Bh = Bt0 + (long long)z * zB + (long long)bcol * (2LL * K);
    const __nv_bfloat16* Bl = Bh + K;
    if (bias) bias += (long long)z * sBias;
    if (C) C += (long long)z * sC;
    if (Sp) Sp += (long long)z * zSp;

    if (gmode) __syncthreads();

    const uint32_t sb = smem_u32(smem);
    const int NC = K >> 6;

    auto load_tile = [&](int c, int s) {
        const int kc = c * 64;
        const uint32_t st = sb + s * G2_STAGE;
        #pragma unroll
        for (int i = 0; i < 2; i++) {
            int idx = tid + i * 512;
            int r = idx >> 3, ch = idx & 7;
            int rowA = (gmode == 1) ? slist[r] : (brow + r);
            cp_async16(swz(st, r, ch),
                       (const char*)(Ahz + (long long)rowA * ldA + kc) + ch * 16);
            cp_async16(swz(st + 16384, r, ch),
                       (const char*)(Ahz + loA + (long long)rowA * ldA + kc) + ch * 16);
            cp_async16(swz(st + 32768, r, ch),
                       (const char*)(Bh + (long long)r * 2 * K + kc) + ch * 16);
            cp_async16(swz(st + 49152, r, ch),
                       (const char*)(Bl + (long long)r * 2 * K + kc) + ch * 16);
        }
        CP_COMMIT();
    };

    float acc[2][4][4] = {};
    load_tile(0, 0);
    load_tile(1, 1);

    int s = 0;
    for (int c = 0; c < NC; c++) {
        if (c + 1 < NC) { CP_WAIT1(); } else { CP_WAIT0(); }
        __syncthreads();
        if (c + 2 < NC) {
            int s2 = s + 2;
            if (s2 >= 3) s2 -= 3;
            load_tile(c + 2, s2);
        }
        const uint32_t stA = sb + s * G2_STAGE;

        #pragma unroll
        for (int ks = 0; ks < 4; ks++) {
            const int cb = ks * 2;
            uint32_t ah[2][4], al[2][4];
            #pragma unroll
            for (int ms = 0; ms < 2; ms++) {
                int r = wy * 32 + ms * 16 + (lane & 15);
                int ch = cb + (lane >> 4);
                ldsm_x4(ah[ms][0], ah[ms][1], ah[ms][2], ah[ms][3], swz(stA, r, ch));
                ldsm_x4(al[ms][0], al[ms][1], al[ms][2], al[ms][3], swz(stA + 16384, r, ch));
            }
            uint32_t bh[4][2], bl[4][2];
            #pragma unroll
            for (int nh = 0; nh < 2; nh++) {
                int g = lane >> 3;
                int r = wx * 32 + nh * 16 + ((g & 2) << 2) + (lane & 7);
                int ch = cb + (g & 1);
                uint32_t r0, r1, r2, r3;
                ldsm_x4(r0, r1, r2, r3, swz(stA + 32768, r, ch));
                bh[nh*2][0] = r0; bh[nh*2][1] = r1;
                bh[nh*2+1][0] = r2; bh[nh*2+1][1] = r3;
                ldsm_x4(r0, r1, r2, r3, swz(stA + 49152, r, ch));
                bl[nh*2][0] = r0; bl[nh*2][1] = r1;
                bl[nh*2+1][0] = r2; bl[nh*2+1][1] = r3;
            }
            // term-major: 8 independent accumulators between reuses
            #pragma unroll
            for (int ms = 0; ms < 2; ms++)
                #pragma unroll
                for (int ns = 0; ns < 4; ns++)
                    mma16816(acc[ms][ns], ah[ms], bh[ns]);
            #pragma unroll
            for (int ms = 0; ms < 2; ms++)
                #pragma unroll
                for (int ns = 0; ns < 4; ns++)
                    mma16816(acc[ms][ns], ah[ms], bl[ns]);
            #pragma unroll
            for (int ms = 0; ms < 2; ms++)
                #pragma unroll
                for (int ns = 0; ns < 4; ns++)
                    mma16816(acc[ms][ns], al[ms], bh[ns]);
        }
        __syncthreads();
        s = (s == 2) ? 0 : s + 1;
    }

    // ---- epilogue ----
    const int qrow = lane >> 2, qcol = (lane & 3) * 2;
    #pragma unroll
    for (int ms = 0; ms < 2; ms++) {
        int m = brow + wy * 32 + ms * 16 + qrow;
        bool ok0 = !gmode || (m < cnt);
        bool ok1 = !gmode || (m + 8 < cnt);
        int crow0 = (gmode == 2 && ok0) ? slist[m - brow] : m;
        int crow1 = (gmode == 2 && ok1) ? slist[m + 8 - brow] : m + 8;
        #pragma unroll
        for (int ns = 0; ns < 4; ns++) {
            int n = bcol + wx * 32 + ns * 8 + qcol;
            float2 v0 = make_float2(acc[ms][ns][0], acc[ms][ns][1]);
            float2 v1 = make_float2(acc[ms][ns][2], acc[ms][ns][3]);
            if (bias) {
                float b0 = bias[n], b1 = bias[n + 1];
                v0.x += b0; v0.y += b1; v1.x += b0; v1.y += b1;
            }
            if (res) {
                float2 r0 = *(const float2*)(res + (long long)m * N + n);
                float2 r1 = *(const float2*)(res + (long long)(m + 8) * N + n);
                v0.x += r0.x; v0.y += r0.y; v1.x += r1.x; v1.y += r1.y;
            }
            if (relu) {
                v0.x = fmaxf(v0.x, 0.f); v0.y = fmaxf(v0.y, 0.f);
                v1.x = fmaxf(v1.x, 0.f); v1.y = fmaxf(v1.y, 0.f);
            }
            if (C) {
                if (ok0) *(float2*)(C + (long long)crow0 * N + n) = v0;
                if (ok1) *(float2*)(C + (long long)crow1 * N + n) = v1;
            }
            uint32_t hp0 = pack_bf2(v0.x, v0.y);
            uint32_t hp1 = pack_bf2(v1.x, v1.y);
            uint32_t lp0 = pack_bf2(v0.x - bf_lo(hp0), v0.y - bf_hi(hp0));
            uint32_t lp1 = pack_bf2(v1.x - bf_lo(hp1), v1.y - bf_hi(hp1));
            if (Sp) {
                long long r0 = (long long)m * 2 * N, r1 = (long long)(m + 8) * 2 * N;
                if (ok0) {
                    *(uint32_t*)(Sp + r0 + n)     = hp0;
                    *(uint32_t*)(Sp + r0 + N + n) = lp0;
                }
                if (ok1) {
                    *(uint32_t*)(Sp + r1 + n)     = hp1;
                    *(uint32_t*)(Sp + r1 + N + n) = lp1;
                }
            }
            if (KH) {
                long long a0 = (((long long)((m >> 10) * 8 + (n >> 6))) * 1024 + (m & 1023)) * 64 + (n & 63);
                long long a1 = a0 + 8LL * 64;
                *(uint32_t*)(KH + a0) = hp0;  *(uint32_t*)(KL + a0) = lp0;
                *(uint32_t*)(KH + a1) = hp1;  *(uint32_t*)(KL + a1) = lp1;
            }
            if (VH) {
                int b = m >> 10, h = n >> 6, d = n & 63, si = m & 1023;
                long long base = (((long long)(z * 32 + b * 8 + h)) * 64 + d) * 1024 + si;
                unsigned short* vh = (unsigned short*)VH;
                unsigned short* vl = (unsigned short*)VL;
                vh[base]            = (unsigned short)(hp0 & 0xffff);
                vh[base + 1024]     = (unsigned short)(hp0 >> 16);
                vh[base + 8]        = (unsigned short)(hp1 & 0xffff);
                vh[base + 1024 + 8] = (unsigned short)(hp1 >> 16);
                vl[base]            = (unsigned short)(lp0 & 0xffff);
                vl[base + 1024]     = (unsigned short)(lp0 >> 16);
                vl[base + 8]        = (unsigned short)(lp1 & 0xffff);
                vl[base + 1024 + 8] = (unsigned short)(lp1 >> 16);
            }
        }
    }
}

// ================= tensor-core flash attention ===============================
#define ATTN_SMEM 81920

__global__ __launch_bounds__(128) void attn_mma_kernel(
    const __nv_bfloat16* __restrict__ khh, const __nv_bfloat16* __restrict__ khl,
    const __nv_bfloat16* __restrict__ vth, const __nv_bfloat16* __restrict__ vtl,
    __nv_bfloat16* __restrict__ Cx)
{
    extern __shared__ __align__(1024) char smem[];
    const uint32_t sb = smem_u32(smem);
    const int tid = threadIdx.x, wid = tid >> 5, lane = tid & 31;
    const int qb = 15 - blockIdx.x;
    const int bh = blockIdx.y;
    const int q0 = qb * 64;

    const __nv_bfloat16* Kh = khh + (long long)bh * S_ * 64;
    const __nv_bfloat16* Kl = khl + (long long)bh * S_ * 64;
    const __nv_bfloat16* Vh = vth + (long long)bh * 64 * S_;
    const __nv_bfloat16* Vl = vtl + (long long)bh * 64 * S_;

    auto load_kv = [&](int jt, int s) {
        const int j0 = jt * 64;
        const uint32_t base = sb + 16384 + s * 32768;
        #pragma unroll
        for (int i = 0; i < 4; i++) {
            int idx = tid + i * 128;
            int r = idx >> 3, ch = idx & 7;
            cp_async16(swz(base, r, ch),
                       (const char*)(Kh + (long long)(j0 + r) * 64) + ch * 16);
            cp_async16(swz(base + 8192, r, ch),
                       (const char*)(Kl + (long long)(j0 + r) * 64) + ch * 16);
            cp_async16(swz(base + 16384, r, ch),
                       (const char*)(Vh + (long long)r * S_ + j0) + ch * 16);
            cp_async16(swz(base + 24576, r, ch),
                       (const char*)(Vl + (long long)r * S_ + j0) + ch * 16);
        }
        CP_COMMIT();
    };

    #pragma unroll
    for (int i = 0; i < 4; i++) {
        int idx = tid + i * 128;
        int r = idx >> 3, ch = idx & 7;
        cp_async16(swz(sb, r, ch),
                   (const char*)(Kh + (long long)(q0 + r) * 64) + ch * 16);
        cp_async16(swz(sb + 8192, r, ch),
                   (const char*)(Kl + (long long)(q0 + r) * 64) + ch * 16);
    }
    load_kv(0, 0);
    CP_WAIT0();
    __syncthreads();

    uint32_t qh[4][4], ql[4][4];
    #pragma unroll
    for (int ks = 0; ks < 4; ks++) {
        int r = wid * 16 + (lane & 15);
        int ch = 2 * ks + (lane >> 4);
        ldsm_x4(qh[ks][0], qh[ks][1], qh[ks][2], qh[ks][3], swz(sb, r, ch));
        ldsm_x4(ql[ks][0], ql[ks][1], ql[ks][2], ql[ks][3], swz(sb + 8192, r, ch));
    }

    float ctx[8][4] = {};
    float m0 = NEG_INF, m1 = NEG_INF, l0 = 0.f, l1 = 0.f;
    const int rg0 = q0 + wid * 16 + (lane >> 2);

    for (int jt = 0; jt <= qb; jt++) {
        const int s = jt & 1;
        if (jt < qb) { load_kv(jt + 1, s ^ 1); CP_WAIT1(); }
        else if (jt > 0) { CP_WAIT0(); }
        __syncthreads();

        const uint32_t bK = sb + 16384 + s * 32768;

        float sc[8][4] = {};
        #pragma unroll
        for (int ks = 0; ks < 4; ks++) {
            uint32_t bh_[8][2], bl_[8][2];
            #pragma unroll
            for (int ng = 0; ng < 4; ng++) {
                int g = lane >> 3;
                int r = ng * 16 + ((g & 2) << 2) + (lane & 7);
                int ch = 2 * ks + (g & 1);
                uint32_t a0, a1, a2, a3;
                ldsm_x4(a0, a1, a2, a3, swz(bK, r, ch));
                bh_[2*ng][0] = a0; bh_[2*ng][1] = a1;
                bh_[2*ng+1][0] = a2; bh_[2*ng+1][1] = a3;
                ldsm_x4(a0, a1, a2, a3, swz(bK + 8192, r, ch));
                bl_[2*ng][0] = a0; bl_[2*ng][1] = a1;
                bl_[2*ng+1][0] = a2; bl_[2*ng+1][1] = a3;
            }
            #pragma unroll
            for (int nt = 0; nt < 8; nt++) {
                mma16816(sc[nt], qh[ks], bh_[nt]);
                mma16816(sc[nt], qh[ks], bl_[nt]);
                mma16816(sc[nt], ql[ks], bh_[nt]);
            }
        }

        const int j0 = jt * 64;
        const bool diag = (jt == qb);
        const int cb0 = j0 + (lane & 3) * 2;
        float rm0 = NEG_INF, rm1 = NEG_INF;
        #pragma unroll
        for (int nt = 0; nt < 8; nt++) {
            int c0 = cb0 + nt * 8, c1 = c0 + 1;
            float s0 = sc[nt][0] * 0.125f, s1 = sc[nt][1] * 0.125f;
            float s2 = sc[nt][2] * 0.125f, s3 = sc[nt][3] * 0.125f;
            if (diag) {
                if (c0 >= rg0)     s0 = NEG_INF;
                if (c1 >= rg0)     s1 = NEG_INF;
                if (c0 >= rg0 + 8) s2 = NEG_INF;
                if (c1 >= rg0 + 8) s3 = NEG_INF;
            }
            sc[nt][0] = s0; sc[nt][1] = s1; sc[nt][2] = s2; sc[nt][3] = s3;
            rm0 = fmaxf(rm0, fmaxf(s0, s1));
            rm1 = fmaxf(rm1, fmaxf(s2, s3));
        }
        #pragma unroll
        for (int o = 1; o <= 2; o <<= 1) {
            rm0 = fmaxf(rm0, __shfl_xor_sync(0xffffffffu, rm0, o));
            rm1 = fmaxf(rm1, __shfl_xor_sync(0xffffffffu, rm1, o));
        }
        float mn0 = fmaxf(m0, rm0), mn1 = fmaxf(m1, rm1);
        float ms0 = (mn0 == NEG_INF) ? 0.f : mn0;
        float ms1 = (mn1 == NEG_INF) ? 0.f : mn1;
        float cr0 = __expf(m0 - ms0), cr1 = __expf(m1 - ms1);
        float rs0 = 0.f, rs1 = 0.f;
        #pragma unroll
        for (int nt = 0; nt < 8; nt++) {
            sc[nt][0] = __expf(sc[nt][0] - ms0); rs0 += sc[nt][0];
            sc[nt][1] = __expf(sc[nt][1] - ms0); rs0 += sc[nt][1];
            sc[nt][2] = __expf(sc[nt][2] - ms1); rs1 += sc[nt][2];
            sc[nt][3] = __expf(sc[nt][3] - ms1); rs1 += sc[nt][3];
        }
        #pragma unroll
        for (int o = 1; o <= 2; o <<= 1) {
            rs0 += __shfl_xor_sync(0xffffffffu, rs0, o);
            rs1 += __shfl_xor_sync(0xffffffffu, rs1, o);
        }
        l0 = l0 * cr0 + rs0; l1 = l1 * cr1 + rs1;
        m0 = mn0; m1 = mn1;
        #pragma unroll
        for (int nt = 0; nt < 8; nt++) {
            ctx[nt][0] *= cr0; ctx[nt][1] *= cr0;
            ctx[nt][2] *= cr1; ctx[nt][3] *= cr1;
        }

        uint32_t ph[4][4], pl[4][4];
        #pragma unroll
        for (int kj = 0; kj < 4; kj++) {
            const int t0 = 2 * kj, t1 = 2 * kj + 1;
            ph[kj][0] = pack_bf2(sc[t0][0], sc[t0][1]);
            ph[kj][1] = pack_bf2(sc[t0][2], sc[t0][3]);
            ph[kj][2] = pack_bf2(sc[t1][0], sc[t1][1]);
            ph[kj][3] = pack_bf2(sc[t1][2], sc[t1][3]);
            pl[kj][0] = pack_bf2(sc[t0][0] - bf_lo(ph[kj][0]), sc[t0][1] - bf_hi(ph[kj][0]));
            pl[kj][1] = pack_bf2(sc[t0][2] - bf_lo(ph[kj][1]), sc[t0][3] - bf_hi(ph[kj][1]));
            pl[kj][2] = pack_bf2(sc[t1][0] - bf_lo(ph[kj][2]), sc[t1][1] - bf_hi(ph[kj][2]));
            pl[kj][3] = pack_bf2(sc[t1][2] - bf_lo(ph[kj][3]), sc[t1][3] - bf_hi(ph[kj][3]));
        }

        const uint32_t bV = bK + 16384;
        #pragma unroll
        for (int kj = 0; kj < 4; kj++) {
            uint32_t vh_[8][2], vl_[8][2];
            #pragma unroll
            for (int dg = 0; dg < 4; dg++) {
                int g = lane >> 3;
                int r = dg * 16 + ((g & 2) << 2) + (lane & 7);
                int ch = 2 * kj + (g & 1);
                uint32_t a0, a1, a2, a3;
                ldsm_x4(a0, a1, a2, a3, swz(bV, r, ch));
                vh_[2*dg][0] = a0; vh_[2*dg][1] = a1;
                vh_[2*dg+1][0] = a2; vh_[2*dg+1][1] = a3;
                ldsm_x4(a0, a1, a2, a3, swz(bV + 8192, r, ch));
                vl_[2*dg][0] = a0; vl_[2*dg][1] = a1;
                vl_[2*dg+1][0] = a2; vl_[2*dg+1][1] = a3;
            }
            #pragma unroll
            for (int nt = 0; nt < 8; nt++) {
                mma16816(ctx[nt], ph[kj], vh_[nt]);
                mma16816(ctx[nt], ph[kj], vl_[nt]);
                mma16816(ctx[nt], pl[kj], vh_[nt]);
            }
        }
        __syncthreads();
    }

    float inv0 = (l0 > 0.f) ? 1.f / l0 : 0.f;
    float inv1 = (l1 > 0.f) ? 1.f / l1 : 0.f;
    const int b = bh >> 3, h = bh & 7;
    const int row0 = b * S_ + q0 + wid * 16 + (lane >> 2);
    const int colb = h * 64 + (lane & 3) * 2;
    #pragma unroll
    for (int nt = 0; nt < 8; nt++) {
        float a0 = ctx[nt][0] * inv0, a1 = ctx[nt][1] * inv0;
        float a2 = ctx[nt][2] * inv1, a3 = ctx[nt][3] * inv1;
        uint32_t hp0 = pack_bf2(a0, a1);
        uint32_t hp1 = pack_bf2(a2, a3);
        uint32_t lp0 = pack_bf2(a0 - bf_lo(hp0), a1 - bf_hi(hp0));
        uint32_t lp1 = pack_bf2(a2 - bf_lo(hp1), a3 - bf_hi(hp1));
        long long r0 = (long long)row0 * 1024, r1 = (long long)(row0 + 8) * 1024;
        int cc = colb + nt * 8;
        *(uint32_t*)(Cx + r0 + cc)       = hp0;
        *(uint32_t*)(Cx + r0 + 512 + cc) = lp0;
        *(uint32_t*)(Cx + r1 + cc)       = hp1;
        *(uint32_t*)(Cx + r1 + 512 + cc) = lp1;
    }
}

// ---------------- positional embedding (also zero gate counters) -----------
__global__ void pe_kernel(float* __restrict__ pe) {
    if (blockIdx.x == 0 && threadIdx.x < 4) g_cnt[threadIdx.x] = 0;
    int s = blockIdx.x;
    int j = threadIdx.x;
    float div = expf((float)(2*j) * (-9.210340371976184f / (float)D_));
    float arg = (float)s * div;
    pe[s*D_ + 2*j]     = sinf(arg);
    pe[s*D_ + 2*j + 1] = cosf(arg);
}

__global__ __launch_bounds__(256) void add_pe_kernel(
    const float* __restrict__ qa, const float* __restrict__ pe,
    __nv_bfloat16* __restrict__ yb)
{
    int i = blockIdx.x * 256 + threadIdx.x;
    float v = qa[i] + pe[i & (S_*D_ - 1)];
    int m = i >> 9, c = i & 511;
    __nv_bfloat16 h = __float2bfloat16_rn(v);
    yb[(long long)m * 1024 + c]       = h;
    yb[(long long)m * 1024 + 512 + c] = __float2bfloat16_rn(v - __bfloat162float(h));
}

// ---------------- gate: logits -> top-2 weights + expert row lists ----------
__global__ __launch_bounds__(256) void gate_kernel(
    const float* __restrict__ summary, const float* __restrict__ m_seq,
    const float* __restrict__ gate_w,  const float* __restrict__ gate_b,
    float* __restrict__ wgt, int* __restrict__ cnt, int* __restrict__ list)
{
    __shared__ float red[4][8];
    const int row = blockIdx.x;
    const int tid = threadIdx.x;

    float p0 = 0, p1 = 0, p2 = 0, p3 = 0;
    for (int e = tid; e < D_ + SD_; e += 256) {
        float xv = (e < D_) ? summary[(long long)row * D_ + e]
                            : m_seq[(long long)row * SD_ + (e - D_)];
        float4 w = *(const float4*)(gate_w + e * 4);
        p0 += xv * w.x; p1 += xv * w.y; p2 += xv * w.z; p3 += xv * w.w;
    }
    #pragma unroll
    for (int o = 16; o > 0; o >>= 1) {
        p0 += __shfl_xor_sync(0xffffffffu, p0, o);
        p1 += __shfl_xor_sync(0xffffffffu, p1, o);
        p2 += __shfl_xor_sync(0xffffffffu, p2, o);
        p3 += __shfl_xor_sync(0xffffffffu, p3, o);
    }
    if ((tid & 31) == 0) {
        int w = tid >> 5;
        red[0][w] = p0; red[1][w] = p1; red[2][w] = p2; red[3][w] = p3;
    }
    __syncthreads();

    if (tid == 0) {
        float l[4];
        #pragma unroll
        for (int j = 0; j < 4; j++) {
            float t = gate_b[j];
            #pragma unroll
            for (int w = 0; w < 8; w++) t += red[j][w];
            l[j] = t;
        }
        float m1v = -INFINITY, m2v = -INFINITY;
        #pragma unroll
        for (int j = 0; j < 4; j++) {
            if (l[j] > m1v) { m2v = m1v; m1v = l[j]; }
            else if (l[j] > m2v) { m2v = l[j]; }
        }
        float sum = 0.f, e4[4];
        #pragma unroll
        for (int j = 0; j < 4; j++) {
            e4[j] = (l[j] >= m2v) ? __expf(l[j] - m1v) : 0.f;
            sum += e4[j];
        }
        #pragma unroll
        for (int j = 0; j < 4; j++) {
            wgt[row * 4 + j] = e4[j] / sum;
            if (l[j] >= m2v) {
                int p = atomicAdd(&cnt[j], 1);
                list[j * BS + p] = row;
            }
        }
    }
}

// ---------------- MoE combine + LN + PE -> x (fp32 + split) ----------------
__global__ __launch_bounds__(256) void moe_kernel(
    const float* __restrict__ wgt, const float* __restrict__ experts,
    const float* __restrict__ lng, const float* __restrict__ lnb,
    const float* __restrict__ pe, float* __restrict__ x,
    __nv_bfloat16* __restrict__ xb)
{
    __shared__ float r1[8], r2[8];
    const int row = blockIdx.x;
    const int tid = threadIdx.x;
    const int s_idx = row & (S_ - 1);

    const float w0 = wgt[row*4], w1 = wgt[row*4+1], w2 = wgt[row*4+2], w3 = wgt[row*4+3];
    const long long base = (long long)row * D_;
    const int t2 = tid + 256;
    float c0 = w0 * experts[0*BSD + base + tid] + w1 * experts[1*BSD + base + tid]
             + w2 * experts[2*BSD + base + tid] + w3 * experts[3*BSD + base + tid];
    float c1 = w0 * experts[0*BSD + base + t2]  + w1 * experts[1*BSD + base + t2]
             + w2 * experts[2*BSD + base + t2]  + w3 * experts[3*BSD + base + t2];

    float s = c0 + c1, q = c0 * c0 + c1 * c1;
    #pragma unroll
    for (int o = 16; o > 0; o >>= 1) {
        s += __shfl_xor_sync(0xffffffffu, s, o);
        q += __shfl_xor_sync(0xffffffffu, q, o);
    }
    if ((tid & 31) == 0) { r1[tid >> 5] = s; r2[tid >> 5] = q; }
    __syncthreads();
    float ts = 0, tq = 0;
    #pragma unroll
    for (int w = 0; w < 8; w++) { ts += r1[w]; tq += r2[w]; }
    float mu = ts * (1.f / 512.f);
    float var = tq * (1.f / 512.f) - mu * mu;
    float rstd = rsqrtf(var + 1e-5f);

    float o0 = (c0 - mu) * rstd * lng[tid] + lnb[tid] + pe[s_idx * D_ + tid];
    float o1 = (c1 - mu) * rstd * lng[t2]  + lnb[t2]  + pe[s_idx * D_ + t2];
    x[base + tid] = o0;
    x[base + t2]  = o1;
    long long b2 = (long long)row * 1024;
    __nv_bfloat16 h0 = __float2bfloat16_rn(o0);
    __nv_bfloat16 h1 = __float2bfloat16_rn(o1);
    xb[b2 + tid]        = h0;
    xb[b2 + t2]         = h1;
    xb[b2 + 512 + tid]  = __float2bfloat16_rn(o0 - __bfloat162float(h0));
    xb[b2 + 512 + t2]   = __float2bfloat16_rn(o1 - __bfloat162float(h1));
}

// ---------------- LayerNorm (fp32 out + optional split) --------------------
__global__ __launch_bounds__(256) void ln_kernel(
    const float* __restrict__ in, const float* __restrict__ g,
    const float* __restrict__ b, float* __restrict__ out,
    __nv_bfloat16* __restrict__ sp)
{
    __shared__ float r1[8], r2[8];
    const int row = blockIdx.x, tid = threadIdx.x;
    const long long base = (long long)row * D_;
    float v0 = in[base + tid], v1 = in[base + tid + 256];
    float s = v0 + v1, q = v0 * v0 + v1 * v1;
    #pragma unroll
    for (int o = 16; o > 0; o >>= 1) {
        s += __shfl_xor_sync(0xffffffffu, s, o);
        q += __shfl_xor_sync(0xffffffffu, q, o);
    }
    if ((tid & 31) == 0) { r1[tid >> 5] = s; r2[tid >> 5] = q; }
    __syncthreads();
    float ts = 0, tq = 0;
    #pragma unroll
    for (int w = 0; w < 8; w++) { ts += r1[w]; tq += r2[w]; }
    float mu = ts * (1.f / 512.f);
    float var = tq * (1.f / 512.f) - mu * mu;
    float rstd = rsqrtf(var + 1e-5f);
    float o0 = (v0 - mu) * rstd * g[tid]       + b[tid];
    float o1 = (v1 - mu) * rstd * g[tid + 256] + b[tid + 256];
    out[base + tid]       = o0;
    out[base + tid + 256] = o1;
    if (sp) {
        long long b2 = (long long)row * 1024;
        __nv_bfloat16 h0 = __float2bfloat16_rn(o0);
        __nv_bfloat16 h1 = __float2bfloat16_rn(o1);
        sp[b2 + tid]       = h0;
        sp[b2 + tid + 256] = h1;
        sp[b2 + 512 + tid]       = __float2bfloat16_rn(o0 - __bfloat162float(h0));
        sp[b2 + 512 + tid + 256] = __float2bfloat16_rn(o1 - __bfloat162float(h1));
    }
}

// ================= host wrapper ==============================================
typedef __nv_bfloat16 bf16;

static void gemmL(const bf16* Ah, int loA, int ldA, long long zA,
                  const bf16* Bt, long long zB, int K,
                  const float* bias, int sBias, const float* res,
                  float* C, long long sC, bf16* Sp, long long zSp,
                  bf16* KH, bf16* KL, bf16* VH, bf16* VL,
                  const int* glist, const int* gcnt, int gmode,
                  int N, int nz, int relu)
{
    gemm2_kernel<<<dim3(N/128, 32, nz), 512, G2_SMEM>>>(
        Ah, loA, ldA, zA, Bt, zB, K, bias, sBias, res, C, sC,
        Sp, zSp, KH, KL, VH, VL, glist, gcnt, gmode, N, relu);
}

extern "C" void kernel_launch(void* const* d_in, const int* in_sizes, int n_in,
                              void* d_out, int out_size)
{
    const float* q_raw   = (const float*)d_in[0];
    const float* m_seq   = (const float*)d_in[1];
    const float* qa      = (const float*)d_in[2];
    const float* exp_w1  = (const float*)d_in[3];
    const float* exp_b1  = (const float*)d_in[4];
    const float* exp_w2  = (const float*)d_in[5];
    const float* exp_b2  = (const float*)d_in[6];
    const float* adapt_w = (const float*)d_in[7];
    const float* adapt_b = (const float*)d_in[8];
    const float* gate_w  = (const float*)d_in[9];
    const float* gate_b  = (const float*)d_in[10];
    const float* moe_g   = (const float*)d_in[11];
    const float* moe_b   = (const float*)d_in[12];
    const float* kw      = (const float*)d_in[13];
    const float* kb      = (const float*)d_in[14];
    const float* vw      = (const float*)d_in[15];
    const float* vb      = (const float*)d_in[16];
    const float* ow      = (const float*)d_in[17];
    const float* ob      = (const float*)d_in[18];
    const float* ln1g    = (const float*)d_in[19];
    const float* ln1b    = (const float*)d_in[20];
    const float* fw1     = (const float*)d_in[21];
    const float* fb1     = (const float*)d_in[22];
    const float* fw2     = (const float*)d_in[23];
    const float* fb2     = (const float*)d_in[24];
    const float* ln2g    = (const float*)d_in[25];
    const float* ln2b    = (const float*)d_in[26];

    float *pe, *x, *experts, *summary, *wgtp;
    int *cntp, *listp;
    bf16 *qbf, *h1bf, *ybf, *xbf, *ctxbf, *ffnbf, *wbf, *khh, *khl, *vth, *vtl;
    cudaGetSymbolAddress((void**)&pe, g_pe);
    cudaGetSymbolAddress((void**)&x, g_x);
    cudaGetSymbolAddress((void**)&experts, g_experts);
    cudaGetSymbolAddress((void**)&summary, g_summary);
    cudaGetSymbolAddress((void**)&wgtp, g_wgt);
    cudaGetSymbolAddress((void**)&cntp, g_cnt);
    cudaGetSymbolAddress((void**)&listp, g_list);
    cudaGetSymbolAddress((void**)&qbf, g_qbf);
    cudaGetSymbolAddress((void**)&h1bf, g_h1bf);
    cudaGetSymbolAddress((void**)&ybf, g_ybf);
    cudaGetSymbolAddress((void**)&xbf, g_xbf);
    cudaGetSymbolAddress((void**)&ctxbf, g_ctxbf);
    cudaGetSymbolAddress((void**)&ffnbf, g_ffnbf);
    cudaGetSymbolAddress((void**)&wbf, g_wbf);
    cudaGetSymbolAddress((void**)&khh, g_khh);
    cudaGetSymbolAddress((void**)&khl, g_khl);
    cudaGetSymbolAddress((void**)&vth, g_vth);
    cudaGetSymbolAddress((void**)&vtl, g_vtl);

    static int attr_set = 0;
    if (!attr_set) {
        cudaFuncSetAttribute(gemm2_kernel,
                             cudaFuncAttributeMaxDynamicSharedMemorySize, G2_SMEM);
        cudaFuncSetAttribute(attn_mma_kernel,
                             cudaFuncAttributeMaxDynamicSharedMemorySize, ATTN_SMEM);
        attr_set = 1;
    }

    // 0: pe (+ zero gate counters)
    pe_kernel<<<S_, 256>>>(pe);
    // 1: q_raw split
    conv_qraw_kernel<<<4096 * 768 / 256, 256>>>(q_raw, qbf);
    // 2: ALL weights -> split bf16, one launch
    {
        ConvSegs cs;
        cs.src[0] = exp_w1;  cs.dstOff[0] = W_EXPW1; cs.K[0] = 768;  cs.N[0] = 768;  cs.tOff[0] = 0;
        cs.src[1] = exp_w2;  cs.dstOff[1] = W_EXPW2; cs.K[1] = 768;  cs.N[1] = 512;  cs.tOff[1] = 2304;
        cs.src[2] = adapt_w; cs.dstOff[2] = W_ADAPT; cs.K[2] = 3072; cs.N[2] = 512;  cs.tOff[2] = 3840;
        cs.src[3] = kw;      cs.dstOff[3] = W_KW;    cs.K[3] = 512;  cs.N[3] = 512;  cs.tOff[3] = 5376;
        cs.src[4] = vw;      cs.dstOff[4] = W_VW;    cs.K[4] = 512;  cs.N[4] = 512;  cs.tOff[4] = 6400;
        cs.src[5] = ow;      cs.dstOff[5] = W_OW;    cs.K[5] = 512;  cs.N[5] = 512;  cs.tOff[5] = 7424;
        cs.src[6] = fw1;     cs.dstOff[6] = W_FW1;   cs.K[6] = 512;  cs.N[6] = 2048; cs.tOff[6] = 8448;
        cs.src[7] = fw2;     cs.dstOff[7] = W_FW2;   cs.K[7] = 2048; cs.N[7] = 512;  cs.tOff[7] = 12544;
        convB_all_kernel<<<16640, dim3(32, 8)>>>(cs, wbf);
    }
    // 3: summary = relu(q_flat @ adapt_w + b)
    gemmL(qbf, 3072, 6144, 0, wbf + W_ADAPT, 0, 3072, adapt_b, 0, nullptr,
          summary, 0, nullptr, 0, nullptr, nullptr, nullptr, nullptr,
          nullptr, nullptr, 0, 512, 1, 1);
    // 4: gate -> weights + expert row lists
    gate_kernel<<<BS, 256>>>(summary, m_seq, gate_w, gate_b, wgtp, cntp, listp);
    // 5: h1 = relu(gathered q_raw @ exp_w1 + b1) -> compacted split
    gemmL(qbf, 3072, 6144, 768, wbf + W_EXPW1, 768LL*1536, 768, exp_b1, IN_, nullptr,
          nullptr, 0, h1bf, (long long)BS * 1536, nullptr, nullptr, nullptr, nullptr,
          listp, cntp, 1, 768, NS_, 1);
    // 6: experts = compacted h1 @ exp_w2 + b2 -> scattered fp32
    gemmL(h1bf, 768, 1536, (long long)BS * 1536, wbf + W_EXPW2, 512LL*1536, 768,
          exp_b2, D_, nullptr, experts, BSD, nullptr, 0,
          nullptr, nullptr, nullptr, nullptr, listp, cntp, 2, 512, NS_, 0);
    // 7: combine + moe LN + pe
    moe_kernel<<<BS, 256>>>(wgtp, experts, moe_g, moe_b, pe, x, xbf);
    // 8: y' = qa + pe split
    add_pe_kernel<<<(int)(BSD / 256), 256>>>(qa, pe, ybf);
    // 9: V for all layers -> transposed split
    gemmL(ybf, 512, 1024, 0, wbf + W_VW, 512LL*1024, 512, vb, D_, nullptr,
          nullptr, 0, nullptr, 0, nullptr, nullptr, vth, vtl,
          nullptr, nullptr, 0, 512, L_, 0);

    for (int i = 0; i < L_; i++) {
        gemmL(xbf, 512, 1024, 0, wbf + W_KW + (long long)i * 524288, 0, 512,
              kb + i*D_, 0, nullptr, nullptr, 0, nullptr, 0,
              khh, khl, nullptr, nullptr, nullptr, nullptr, 0, 512, 1, 0);
        attn_mma_kernel<<<dim3(16, 32), 128, ATTN_SMEM>>>(
            khh, khl, vth + (long long)i * 2097152, vtl + (long long)i * 2097152, ctxbf);
        gemmL(ctxbf, 512, 1024, 0, wbf + W_OW + (long long)i * 524288, 0, 512,
              ob + i*D_, 0, x, x, 0, nullptr, 0,
              nullptr, nullptr, nullptr, nullptr, nullptr, nullptr, 0, 512, 1, 0);
        ln_kernel<<<BS, 256>>>(x, ln1g + i*D_, ln1b + i*D_, x, xbf);
        gemmL(xbf, 512, 1024, 0, wbf + W_FW1 + (long long)i * 2097152, 0, 512,
              fb1 + i*FF_, 0, nullptr, nullptr, 0, ffnbf, 0,
              nullptr, nullptr, nullptr, nullptr, nullptr, nullptr, 0, 2048, 1, 1);
        gemmL(ffnbf, 2048, 4096, 0, wbf + W_FW2 + (long long)i * 2097152, 0, 2048,
              fb2 + i*D_, 0, x, x, 0, nullptr, 0,
              nullptr, nullptr, nullptr, nullptr, nullptr, nullptr, 0, 512, 1, 0);
        ln_kernel<<<BS, 256>>>(x, ln2g + i*D_, ln2b + i*D_,
                               (i == L_-1) ? (float*)d_out : x,
                               (i == L_-1) ? nullptr : xbf);
    }
}

// round 10
// speedup vs baseline: 4.6353x; 1.2972x over previous
#include <cuda_runtime.h>
#include <cuda_fp16.h>
#include <cstdint>
#include <math.h>

// Problem dims
#define B_  4
#define S_  1024
#define D_  512
#define H_  8
#define DK_ 64
#define FF_ 2048
#define L_  4
#define IN_ 768
#define NS_ 4
#define SD_ 64

#define BS  (B_*S_)            // 4096
#define BSD ((long long)BS*D_) // 2097152
#define NEG_INF __int_as_float(0xff800000)

// ---------------- scratch (device globals: allocation-free) ----------------
__device__ float g_pe[S_*D_];
__device__ float g_x[BS*D_];
__device__ float g_experts[NS_*BS*D_];
__device__ float g_summary[BS*D_];
__device__ float g_wgt[BS*4];
__device__ int   g_cnt[4];
__device__ int   g_list[4*BS];
// split fp16 buffers, layout [m][hi K | lo K]
__device__ __half g_qbf[25165824];    // q_raw' [4096][6144]
__device__ __half g_h1bf[25165824];   // h1'   [4][4096][1536] (compacted slots)
__device__ __half g_ybf[4194304];     // y'    [4096][1024]
__device__ __half g_xbf[4194304];     // x'    [4096][1024]
__device__ __half g_ctxbf[4194304];   // ctx'  [4096][1024]
__device__ __half g_ffnbf[16777216];  // ffn'  [4096][4096]
__device__ __half g_khh[2097152];     // K hi [32][1024][64]
__device__ __half g_khl[2097152];     // K lo
__device__ __half g_vth[8388608];     // Vt hi [4][32][64][1024]
// all weights, SINGLE fp16 [n][K]
__device__ __half g_wbf[17039360];

// weight buffer offsets (fp16 elements)
#define W_EXPW1 0LL
#define W_EXPW2 2359296LL
#define W_ADAPT 3932160LL
#define W_KW    5505024LL
#define W_VW    6553600LL
#define W_OW    7602176LL
#define W_FW1   8650752LL
#define W_FW2   12845056LL

// ================= PTX helpers ===============================================
__device__ __forceinline__ uint32_t smem_u32(const void* p) {
    uint32_t a;
    asm("{ .reg .u64 t; cvta.to.shared.u64 t, %1; cvt.u32.u64 %0, t; }" : "=r"(a) : "l"(p));
    return a;
}
__device__ __forceinline__ void cp_async16(uint32_t dst, const void* src) {
    asm volatile("cp.async.cg.shared.global [%0], [%1], 16;" :: "r"(dst), "l"(src));
}
#define CP_COMMIT() asm volatile("cp.async.commit_group;" ::: "memory")
#define CP_WAIT0()  asm volatile("cp.async.wait_group 0;" ::: "memory")
#define CP_WAIT1()  asm volatile("cp.async.wait_group 1;" ::: "memory")

__device__ __forceinline__ void ldsm_x4(uint32_t& r0, uint32_t& r1, uint32_t& r2,
                                        uint32_t& r3, uint32_t addr) {
    asm volatile("ldmatrix.sync.aligned.m8n8.x4.shared.b16 {%0,%1,%2,%3}, [%4];"
        : "=r"(r0), "=r"(r1), "=r"(r2), "=r"(r3) : "r"(addr));
}
__device__ __forceinline__ void mma16816(float* c, const uint32_t* a, const uint32_t* b) {
    asm volatile(
        "mma.sync.aligned.m16n8k16.row.col.f32.f16.f16.f32 "
        "{%0,%1,%2,%3}, {%4,%5,%6,%7}, {%8,%9}, {%0,%1,%2,%3};"
        : "+f"(c[0]), "+f"(c[1]), "+f"(c[2]), "+f"(c[3])
        : "r"(a[0]), "r"(a[1]), "r"(a[2]), "r"(a[3]), "r"(b[0]), "r"(b[1]));
}
__device__ __forceinline__ uint32_t pack_h2(float lo, float hi) {
    uint32_t d;
    asm("cvt.rn.f16x2.f32 %0, %1, %2;" : "=r"(d) : "f"(hi), "f"(lo));
    return d;
}
__device__ __forceinline__ float h2_lo(uint32_t p) {
    return __half2float(__ushort_as_half((unsigned short)(p & 0xffff)));
}
__device__ __forceinline__ float h2_hi(uint32_t p) {
    return __half2float(__ushort_as_half((unsigned short)(p >> 16)));
}

__device__ __forceinline__ uint32_t swz(uint32_t base, int r, int ch) {
    return base + r * 128 + ((ch ^ (r & 7)) << 4);
}

// ================= conversions ==============================================
// q_raw [4096][3072] fp32 -> q' [4096][6144] = [hi 3072 | lo 3072]
__global__ __launch_bounds__(256) void conv_qraw_kernel(
    const float* __restrict__ src, __half* __restrict__ dst)
{
    int idx = blockIdx.x * 256 + threadIdx.x;
    int m = idx / 768;
    int k = (idx - m * 768) * 4;
    float4 v = *(const float4*)(src + (long long)m * 3072 + k);
    unsigned short hb[4], lb[4];
    float vv[4] = {v.x, v.y, v.z, v.w};
    #pragma unroll
    for (int i = 0; i < 4; i++) {
        __half h = __float2half_rn(vv[i]);
        __half l = __float2half_rn(vv[i] - __half2float(h));
        hb[i] = __half_as_ushort(h);
        lb[i] = __half_as_ushort(l);
    }
    long long base = (long long)m * 6144;
    *(uint2*)(dst + base + k) = make_uint2((uint32_t)hb[0] | ((uint32_t)hb[1] << 16),
                                           (uint32_t)hb[2] | ((uint32_t)hb[3] << 16));
    *(uint2*)(dst + base + 3072 + k) = make_uint2((uint32_t)lb[0] | ((uint32_t)lb[1] << 16),
                                                  (uint32_t)lb[2] | ((uint32_t)lb[3] << 16));
}

// all weights W [z][K][N] fp32 -> W' [z][n][K] single fp16, one launch
struct ConvSegs {
    const float* src[8];
    long long dstOff[8];
    int K[8], N[8], tOff[8];
};

__global__ void convB_all_kernel(ConvSegs segs, __half* __restrict__ wb)
{
    __shared__ float t[32][33];
    int bx = blockIdx.x;
    int seg = 0;
    #pragma unroll
    for (int i = 7; i >= 1; i--) if (bx >= segs.tOff[i]) { seg = i; break; }
    const int K = segs.K[seg], N = segs.N[seg];
    int tl = bx - segs.tOff[seg];
    int tz = (K >> 5) * (N >> 5);
    int z = tl / tz, rr = tl - z * tz;
    int k0 = (rr % (K >> 5)) * 32, n0 = (rr / (K >> 5)) * 32;
    const float* s = segs.src[seg] + (long long)z * K * N;
    __half* dstz = wb + segs.dstOff[seg] + (long long)z * N * K;
    int tx = threadIdx.x, ty = threadIdx.y;
    #pragma unroll
    for (int r = ty; r < 32; r += 8)
        t[r][tx] = s[(long long)(k0 + r) * N + n0 + tx];
    __syncthreads();
    #pragma unroll
    for (int r = ty; r < 32; r += 8) {
        dstz[(long long)(n0 + r) * K + k0 + tx] = __float2half_rn(t[tx][r]);
    }
}

// ================= unified split GEMM (fp16, 2 terms: Xh*W + Xl*W) ==========
// 512 threads, 16 warps, warp tile 32x32 over 128x128 CTA tile.
// gmode: 0 = dense, 1 = gather-A rows via list (Sp at slots), 2 = scatter-C rows
#define G2_STAGE 49152
#define G2_SMEM  147456

__global__ __launch_bounds__(512, 1) void gemm2_kernel(
    const __half* __restrict__ Ah0, int loA, int ldA, long long zA,
    const __half* __restrict__ Bt0, long long zB, int K,
    const float* __restrict__ bias, int sBias,
    const float* __restrict__ res,
    float* __restrict__ C, long long sC,
    __half* __restrict__ Sp, long long zSp,
    __half* __restrict__ KH, __half* __restrict__ KL,
    __half* __restrict__ VH,
    const int* __restrict__ glist, const int* __restrict__ gcnt,
    int gmode, int N, int relu)
{
    extern __shared__ __align__(1024) char smem[];
    __shared__ int slist[128];
    const int tid = threadIdx.x, wid = tid >> 5, lane = tid & 31;
    const int wy = wid >> 2, wx = wid & 3;
    const int z = blockIdx.z;
    const int brow = blockIdx.y * 128, bcol = blockIdx.x * 128;

    int cnt = 0;
    if (gmode) {
        cnt = gcnt[z];
        if (brow >= cnt) return;
        if (tid < 128) {
            int i = brow + tid;
            slist[tid] = glist[z * BS + (i < cnt ? i : cnt - 1)];
        }
    }

    const __half* Ahz = Ah0 + (long long)z * zA;
    const __half* Bh = Bt0 + (long long)z * zB + (long long)bcol * K;
    if (bias) bias += (long long)z * sBias;
    if (C) C += (long long)z * sC;
    if (Sp) Sp += (long long)z * zSp;

    if (gmode) __syncthreads();

    const uint32_t sb = smem_u32(smem);
    const int NC = K >> 6;

    auto load_tile = [&](int c, int s) {
        const int kc = c * 64;
        const uint32_t st = sb + s * G2_STAGE;
        #pragma unroll
        for (int i = 0; i < 2; i++) {
            int idx = tid + i * 512;
            int r = idx >> 3, ch = idx & 7;
            int rowA = (gmode == 1) ? slist[r] : (brow + r);
            cp_async16(swz(st, r, ch),
                       (const char*)(Ahz + (long long)rowA * ldA + kc) + ch * 16);
            cp_async16(swz(st + 16384, r, ch),
                       (const char*)(Ahz + loA + (long long)rowA * ldA + kc) + ch * 16);
            cp_async16(swz(st + 32768, r, ch),
                       (const char*)(Bh + (long long)r * K + kc) + ch * 16);
        }
        CP_COMMIT();
    };

    float acc[2][4][4] = {};
    load_tile(0, 0);
    load_tile(1, 1);

    int s = 0;
    for (int c = 0; c < NC; c++) {
        if (c + 1 < NC) { CP_WAIT1(); } else { CP_WAIT0(); }
        __syncthreads();
        if (c + 2 < NC) {
            int s2 = s + 2;
            if (s2 >= 3) s2 -= 3;
            load_tile(c + 2, s2);
        }
        const uint32_t stA = sb + s * G2_STAGE;

        #pragma unroll
        for (int ks = 0; ks < 4; ks++) {
            const int cb = ks * 2;
            uint32_t ah[2][4], al[2][4];
            #pragma unroll
            for (int ms = 0; ms < 2; ms++) {
                int r = wy * 32 + ms * 16 + (lane & 15);
                int ch = cb + (lane >> 4);
                ldsm_x4(ah[ms][0], ah[ms][1], ah[ms][2], ah[ms][3], swz(stA, r, ch));
                ldsm_x4(al[ms][0], al[ms][1], al[ms][2], al[ms][3], swz(stA + 16384, r, ch));
            }
            uint32_t bh[4][2];
            #pragma unroll
            for (int nh = 0; nh < 2; nh++) {
                int g = lane >> 3;
                int r = wx * 32 + nh * 16 + ((g & 2) << 2) + (lane & 7);
                int ch = cb + (g & 1);
                uint32_t r0, r1, r2, r3;
                ldsm_x4(r0, r1, r2, r3, swz(stA + 32768, r, ch));
                bh[nh*2][0] = r0; bh[nh*2][1] = r1;
                bh[nh*2+1][0] = r2; bh[nh*2+1][1] = r3;
            }
            // term-major: 8 independent accumulators between reuses
            #pragma unroll
            for (int ms = 0; ms < 2; ms++)
                #pragma unroll
                for (int ns = 0; ns < 4; ns++)
                    mma16816(acc[ms][ns], ah[ms], bh[ns]);
            #pragma unroll
            for (int ms = 0; ms < 2; ms++)
                #pragma unroll
                for (int ns = 0; ns < 4; ns++)
                    mma16816(acc[ms][ns], al[ms], bh[ns]);
        }
        __syncthreads();
        s = (s == 2) ? 0 : s + 1;
    }

    // ---- epilogue ----
    const int qrow = lane >> 2, qcol = (lane & 3) * 2;
    #pragma unroll
    for (int ms = 0; ms < 2; ms++) {
        int m = brow + wy * 32 + ms * 16 + qrow;
        bool ok0 = !gmode || (m < cnt);
        bool ok1 = !gmode || (m + 8 < cnt);
        int crow0 = (gmode == 2 && ok0) ? slist[m - brow] : m;
        int crow1 = (gmode == 2 && ok1) ? slist[m + 8 - brow] : m + 8;
        #pragma unroll
        for (int ns = 0; ns < 4; ns++) {
            int n = bcol + wx * 32 + ns * 8 + qcol;
            float2 v0 = make_float2(acc[ms][ns][0], acc[ms][ns][1]);
            float2 v1 = make_float2(acc[ms][ns][2], acc[ms][ns][3]);
            if (bias) {
                float b0 = bias[n], b1 = bias[n + 1];
                v0.x += b0; v0.y += b1; v1.x += b0; v1.y += b1;
            }
            if (res) {
                float2 r0 = *(const float2*)(res + (long long)m * N + n);
                float2 r1 = *(const float2*)(res + (long long)(m + 8) * N + n);
                v0.x += r0.x; v0.y += r0.y; v1.x += r1.x; v1.y += r1.y;
            }
            if (relu) {
                v0.x = fmaxf(v0.x, 0.f); v0.y = fmaxf(v0.y, 0.f);
                v1.x = fmaxf(v1.x, 0.f); v1.y = fmaxf(v1.y, 0.f);
            }
            if (C) {
                if (ok0) *(float2*)(C + (long long)crow0 * N + n) = v0;
                if (ok1) *(float2*)(C + (long long)crow1 * N + n) = v1;
            }
            uint32_t hp0 = pack_h2(v0.x, v0.y);
            uint32_t hp1 = pack_h2(v1.x, v1.y);
            uint32_t lp0 = pack_h2(v0.x - h2_lo(hp0), v0.y - h2_hi(hp0));
            uint32_t lp1 = pack_h2(v1.x - h2_lo(hp1), v1.y - h2_hi(hp1));
            if (Sp) {
                long long r0 = (long long)m * 2 * N, r1 = (long long)(m + 8) * 2 * N;
                if (ok0) {
                    *(uint32_t*)(Sp + r0 + n)     = hp0;
                    *(uint32_t*)(Sp + r0 + N + n) = lp0;
                }
                if (ok1) {
                    *(uint32_t*)(Sp + r1 + n)     = hp1;
                    *(uint32_t*)(Sp + r1 + N + n) = lp1;
                }
            }
            if (KH) {
                long long a0 = (((long long)((m >> 10) * 8 + (n >> 6))) * 1024 + (m & 1023)) * 64 + (n & 63);
                long long a1 = a0 + 8LL * 64;
                *(uint32_t*)(KH + a0) = hp0;  *(uint32_t*)(KL + a0) = lp0;
                *(uint32_t*)(KH + a1) = hp1;  *(uint32_t*)(KL + a1) = lp1;
            }
            if (VH) {
                int b = m >> 10, h = n >> 6, d = n & 63, si = m & 1023;
                long long base = (((long long)(z * 32 + b * 8 + h)) * 64 + d) * 1024 + si;
                unsigned short* vh = (unsigned short*)VH;
                vh[base]            = (unsigned short)(hp0 & 0xffff);
                vh[base + 1024]     = (unsigned short)(hp0 >> 16);
                vh[base + 8]        = (unsigned short)(hp1 & 0xffff);
                vh[base + 1024 + 8] = (unsigned short)(hp1 >> 16);
            }
        }
    }
}

// ================= tensor-core flash attention (fp16 2-term) =================
// smem: Qhi @0 (8K), Qlo @8192; stages @16384 + s*16384: {Khi 8K, Vhi 8K}
#define ATTN_SMEM 49152

__global__ __launch_bounds__(128) void attn_mma_kernel(
    const __half* __restrict__ khh, const __half* __restrict__ khl,
    const __half* __restrict__ vth,
    __half* __restrict__ Cx)
{
    extern __shared__ __align__(1024) char smem[];
    const uint32_t sb = smem_u32(smem);
    const int tid = threadIdx.x, wid = tid >> 5, lane = tid & 31;
    const int qb = 15 - blockIdx.x;
    const int bh = blockIdx.y;
    const int q0 = qb * 64;

    const __half* Kh = khh + (long long)bh * S_ * 64;
    const __half* Kl = khl + (long long)bh * S_ * 64;
    const __half* Vh = vth + (long long)bh * 64 * S_;

    auto load_kv = [&](int jt, int s) {
        const int j0 = jt * 64;
        const uint32_t base = sb + 16384 + s * 16384;
        #pragma unroll
        for (int i = 0; i < 4; i++) {
            int idx = tid + i * 128;
            int r = idx >> 3, ch = idx & 7;
            cp_async16(swz(base, r, ch),
                       (const char*)(Kh + (long long)(j0 + r) * 64) + ch * 16);
            cp_async16(swz(base + 8192, r, ch),
                       (const char*)(Vh + (long long)r * S_ + j0) + ch * 16);
        }
        CP_COMMIT();
    };

    #pragma unroll
    for (int i = 0; i < 4; i++) {
        int idx = tid + i * 128;
        int r = idx >> 3, ch = idx & 7;
        cp_async16(swz(sb, r, ch),
                   (const char*)(Kh + (long long)(q0 + r) * 64) + ch * 16);
        cp_async16(swz(sb + 8192, r, ch),
                   (const char*)(Kl + (long long)(q0 + r) * 64) + ch * 16);
    }
    load_kv(0, 0);
    CP_WAIT0();
    __syncthreads();

    uint32_t qh[4][4], ql[4][4];
    #pragma unroll
    for (int ks = 0; ks < 4; ks++) {
        int r = wid * 16 + (lane & 15);
        int ch = 2 * ks + (lane >> 4);
        ldsm_x4(qh[ks][0], qh[ks][1], qh[ks][2], qh[ks][3], swz(sb, r, ch));
        ldsm_x4(ql[ks][0], ql[ks][1], ql[ks][2], ql[ks][3], swz(sb + 8192, r, ch));
    }

    float ctx[8][4] = {};
    float m0 = NEG_INF, m1 = NEG_INF, l0 = 0.f, l1 = 0.f;
    const int rg0 = q0 + wid * 16 + (lane >> 2);

    for (int jt = 0; jt <= qb; jt++) {
        const int s = jt & 1;
        if (jt < qb) { load_kv(jt + 1, s ^ 1); CP_WAIT1(); }
        else if (jt > 0) { CP_WAIT0(); }
        __syncthreads();

        const uint32_t bK = sb + 16384 + s * 16384;

        float sc[8][4] = {};
        #pragma unroll
        for (int ks = 0; ks < 4; ks++) {
            uint32_t bh_[8][2];
            #pragma unroll
            for (int ng = 0; ng < 4; ng++) {
                int g = lane >> 3;
                int r = ng * 16 + ((g & 2) << 2) + (lane & 7);
                int ch = 2 * ks + (g & 1);
                uint32_t a0, a1, a2, a3;
                ldsm_x4(a0, a1, a2, a3, swz(bK, r, ch));
                bh_[2*ng][0] = a0; bh_[2*ng][1] = a1;
                bh_[2*ng+1][0] = a2; bh_[2*ng+1][1] = a3;
            }
            #pragma unroll
            for (int nt = 0; nt < 8; nt++) {
                mma16816(sc[nt], qh[ks], bh_[nt]);
                mma16816(sc[nt], ql[ks], bh_[nt]);
            }
        }

        const int j0 = jt * 64;
        const bool diag = (jt == qb);
        const int cb0 = j0 + (lane & 3) * 2;
        float rm0 = NEG_INF, rm1 = NEG_INF;
        #pragma unroll
        for (int nt = 0; nt < 8; nt++) {
            int c0 = cb0 + nt * 8, c1 = c0 + 1;
            float s0 = sc[nt][0] * 0.125f, s1 = sc[nt][1] * 0.125f;
            float s2 = sc[nt][2] * 0.125f, s3 = sc[nt][3] * 0.125f;
            if (diag) {
                if (c0 >= rg0)     s0 = NEG_INF;
                if (c1 >= rg0)     s1 = NEG_INF;
                if (c0 >= rg0 + 8) s2 = NEG_INF;
                if (c1 >= rg0 + 8) s3 = NEG_INF;
            }
            sc[nt][0] = s0; sc[nt][1] = s1; sc[nt][2] = s2; sc[nt][3] = s3;
            rm0 = fmaxf(rm0, fmaxf(s0, s1));
            rm1 = fmaxf(rm1, fmaxf(s2, s3));
        }
        #pragma unroll
        for (int o = 1; o <= 2; o <<= 1) {
            rm0 = fmaxf(rm0, __shfl_xor_sync(0xffffffffu, rm0, o));
            rm1 = fmaxf(rm1, __shfl_xor_sync(0xffffffffu, rm1, o));
        }
        float mn0 = fmaxf(m0, rm0), mn1 = fmaxf(m1, rm1);
        float ms0 = (mn0 == NEG_INF) ? 0.f : mn0;
        float ms1 = (mn1 == NEG_INF) ? 0.f : mn1;
        float cr0 = __expf(m0 - ms0), cr1 = __expf(m1 - ms1);
        float rs0 = 0.f, rs1 = 0.f;
        #pragma unroll
        for (int nt = 0; nt < 8; nt++) {
            sc[nt][0] = __expf(sc[nt][0] - ms0); rs0 += sc[nt][0];
            sc[nt][1] = __expf(sc[nt][1] - ms0); rs0 += sc[nt][1];
            sc[nt][2] = __expf(sc[nt][2] - ms1); rs1 += sc[nt][2];
            sc[nt][3] = __expf(sc[nt][3] - ms1); rs1 += sc[nt][3];
        }
        #pragma unroll
        for (int o = 1; o <= 2; o <<= 1) {
            rs0 += __shfl_xor_sync(0xffffffffu, rs0, o);
            rs1 += __shfl_xor_sync(0xffffffffu, rs1, o);
        }
        l0 = l0 * cr0 + rs0; l1 = l1 * cr1 + rs1;
        m0 = mn0; m1 = mn1;
        #pragma unroll
        for (int nt = 0; nt < 8; nt++) {
            ctx[nt][0] *= cr0; ctx[nt][1] *= cr0;
            ctx[nt][2] *= cr1; ctx[nt][3] *= cr1;
        }

        uint32_t ph[4][4], pl[4][4];
        #pragma unroll
        for (int kj = 0; kj < 4; kj++) {
            const int t0 = 2 * kj, t1 = 2 * kj + 1;
            ph[kj][0] = pack_h2(sc[t0][0], sc[t0][1]);
            ph[kj][1] = pack_h2(sc[t0][2], sc[t0][3]);
            ph[kj][2] = pack_h2(sc[t1][0], sc[t1][1]);
            ph[kj][3] = pack_h2(sc[t1][2], sc[t1][3]);
            pl[kj][0] = pack_h2(sc[t0][0] - h2_lo(ph[kj][0]), sc[t0][1] - h2_hi(ph[kj][0]));
            pl[kj][1] = pack_h2(sc[t0][2] - h2_lo(ph[kj][1]), sc[t0][3] - h2_hi(ph[kj][1]));
            pl[kj][2] = pack_h2(sc[t1][0] - h2_lo(ph[kj][2]), sc[t1][1] - h2_hi(ph[kj][2]));
            pl[kj][3] = pack_h2(sc[t1][2] - h2_lo(ph[kj][3]), sc[t1][3] - h2_hi(ph[kj][3]));
        }

        const uint32_t bV = bK + 8192;
        #pragma unroll
        for (int kj = 0; kj < 4; kj++) {
            uint32_t vh_[8][2];
            #pragma unroll
            for (int dg = 0; dg < 4; dg++) {
                int g = lane >> 3;
                int r = dg * 16 + ((g & 2) << 2) + (lane & 7);
                int ch = 2 * kj + (g & 1);
                uint32_t a0, a1, a2, a3;
                ldsm_x4(a0, a1, a2, a3, swz(bV, r, ch));
                vh_[2*dg][0] = a0; vh_[2*dg][1] = a1;
                vh_[2*dg+1][0] = a2; vh_[2*dg+1][1] = a3;
            }
            #pragma unroll
            for (int nt = 0; nt < 8; nt++) {
                mma16816(ctx[nt], ph[kj], vh_[nt]);
                mma16816(ctx[nt], pl[kj], vh_[nt]);
            }
        }
        __syncthreads();
    }

    float inv0 = (l0 > 0.f) ? 1.f / l0 : 0.f;
    float inv1 = (l1 > 0.f) ? 1.f / l1 : 0.f;
    const int b = bh >> 3, h = bh & 7;
    const int row0 = b * S_ + q0 + wid * 16 + (lane >> 2);
    const int colb = h * 64 + (lane & 3) * 2;
    #pragma unroll
    for (int nt = 0; nt < 8; nt++) {
        float a0 = ctx[nt][0] * inv0, a1 = ctx[nt][1] * inv0;
        float a2 = ctx[nt][2] * inv1, a3 = ctx[nt][3] * inv1;
        uint32_t hp0 = pack_h2(a0, a1);
        uint32_t hp1 = pack_h2(a2, a3);
        uint32_t lp0 = pack_h2(a0 - h2_lo(hp0), a1 - h2_hi(hp0));
        uint32_t lp1 = pack_h2(a2 - h2_lo(hp1), a3 - h2_hi(hp1));
        long long r0 = (long long)row0 * 1024, r1 = (long long)(row0 + 8) * 1024;
        int cc = colb + nt * 8;
        *(uint32_t*)(Cx + r0 + cc)       = hp0;
        *(uint32_t*)(Cx + r0 + 512 + cc) = lp0;
        *(uint32_t*)(Cx + r1 + cc)       = hp1;
        *(uint32_t*)(Cx + r1 + 512 + cc) = lp1;
    }
}

// ---------------- positional embedding (also zero gate counters) -----------
__global__ void pe_kernel(float* __restrict__ pe) {
    if (blockIdx.x == 0 && threadIdx.x < 4) g_cnt[threadIdx.x] = 0;
    int s = blockIdx.x;
    int j = threadIdx.x;
    float div = expf((float)(2*j) * (-9.210340371976184f / (float)D_));
    float arg = (float)s * div;
    pe[s*D_ + 2*j]     = sinf(arg);
    pe[s*D_ + 2*j + 1] = cosf(arg);
}

__global__ __launch_bounds__(256) void add_pe_kernel(
    const float* __restrict__ qa, const float* __restrict__ pe,
    __half* __restrict__ yb)
{
    int i = blockIdx.x * 256 + threadIdx.x;
    float v = qa[i] + pe[i & (S_*D_ - 1)];
    int m = i >> 9, c = i & 511;
    __half h = __float2half_rn(v);
    yb[(long long)m * 1024 + c]       = h;
    yb[(long long)m * 1024 + 512 + c] = __float2half_rn(v - __half2float(h));
}

// ---------------- gate: logits -> top-2 weights + expert row lists ----------
__global__ __launch_bounds__(256) void gate_kernel(
    const float* __restrict__ summary, const float* __restrict__ m_seq,
    const float* __restrict__ gate_w,  const float* __restrict__ gate_b,
    float* __restrict__ wgt, int* __restrict__ cnt, int* __restrict__ list)
{
    __shared__ float red[4][8];
    const int row = blockIdx.x;
    const int tid = threadIdx.x;

    float p0 = 0, p1 = 0, p2 = 0, p3 = 0;
    for (int e = tid; e < D_ + SD_; e += 256) {
        float xv = (e < D_) ? summary[(long long)row * D_ + e]
                            : m_seq[(long long)row * SD_ + (e - D_)];
        float4 w = *(const float4*)(gate_w + e * 4);
        p0 += xv * w.x; p1 += xv * w.y; p2 += xv * w.z; p3 += xv * w.w;
    }
    #pragma unroll
    for (int o = 16; o > 0; o >>= 1) {
        p0 += __shfl_xor_sync(0xffffffffu, p0, o);
        p1 += __shfl_xor_sync(0xffffffffu, p1, o);
        p2 += __shfl_xor_sync(0xffffffffu, p2, o);
        p3 += __shfl_xor_sync(0xffffffffu, p3, o);
    }
    if ((tid & 31) == 0) {
        int w = tid >> 5;
        red[0][w] = p0; red[1][w] = p1; red[2][w] = p2; red[3][w] = p3;
    }
    __syncthreads();

    if (tid == 0) {
        float l[4];
        #pragma unroll
        for (int j = 0; j < 4; j++) {
            float t = gate_b[j];
            #pragma unroll
            for (int w = 0; w < 8; w++) t += red[j][w];
            l[j] = t;
        }
        float m1v = -INFINITY, m2v = -INFINITY;
        #pragma unroll
        for (int j = 0; j < 4; j++) {
            if (l[j] > m1v) { m2v = m1v; m1v = l[j]; }
            else if (l[j] > m2v) { m2v = l[j]; }
        }
        float sum = 0.f, e4[4];
        #pragma unroll
        for (int j = 0; j < 4; j++) {
            e4[j] = (l[j] >= m2v) ? __expf(l[j] - m1v) : 0.f;
            sum += e4[j];
        }
        #pragma unroll
        for (int j = 0; j < 4; j++) {
            wgt[row * 4 + j] = e4[j] / sum;
            if (l[j] >= m2v) {
                int p = atomicAdd(&cnt[j], 1);
                list[j * BS + p] = row;
            }
        }
    }
}

// ---------------- MoE combine + LN + PE -> x (fp32 + split) ----------------
__global__ __launch_bounds__(256) void moe_kernel(
    const float* __restrict__ wgt, const float* __restrict__ experts,
    const float* __restrict__ lng, const float* __restrict__ lnb,
    const float* __restrict__ pe, float* __restrict__ x,
    __half* __restrict__ xb)
{
    __shared__ float r1[8], r2[8];
    const int row = blockIdx.x;
    const int tid = threadIdx.x;
    const int s_idx = row & (S_ - 1);

    const float w0 = wgt[row*4], w1 = wgt[row*4+1], w2 = wgt[row*4+2], w3 = wgt[row*4+3];
    const long long base = (long long)row * D_;
    const int t2 = tid + 256;
    float c0 = w0 * experts[0*BSD + base + tid] + w1 * experts[1*BSD + base + tid]
             + w2 * experts[2*BSD + base + tid] + w3 * experts[3*BSD + base + tid];
    float c1 = w0 * experts[0*BSD + base + t2]  + w1 * experts[1*BSD + base + t2]
             + w2 * experts[2*BSD + base + t2]  + w3 * experts[3*BSD + base + t2];

    float s = c0 + c1, q = c0 * c0 + c1 * c1;
    #pragma unroll
    for (int o = 16; o > 0; o >>= 1) {
        s += __shfl_xor_sync(0xffffffffu, s, o);
        q += __shfl_xor_sync(0xffffffffu, q, o);
    }
    if ((tid & 31) == 0) { r1[tid >> 5] = s; r2[tid >> 5] = q; }
    __syncthreads();
    float ts = 0, tq = 0;
    #pragma unroll
    for (int w = 0; w < 8; w++) { ts += r1[w]; tq += r2[w]; }
    float mu = ts * (1.f / 512.f);
    float var = tq * (1.f / 512.f) - mu * mu;
    float rstd = rsqrtf(var + 1e-5f);

    float o0 = (c0 - mu) * rstd * lng[tid] + lnb[tid] + pe[s_idx * D_ + tid];
    float o1 = (c1 - mu) * rstd * lng[t2]  + lnb[t2]  + pe[s_idx * D_ + t2];
    x[base + tid] = o0;
    x[base + t2]  = o1;
    long long b2 = (long long)row * 1024;
    __half h0 = __float2half_rn(o0);
    __half h1 = __float2half_rn(o1);
    xb[b2 + tid]        = h0;
    xb[b2 + t2]         = h1;
    xb[b2 + 512 + tid]  = __float2half_rn(o0 - __half2float(h0));
    xb[b2 + 512 + t2]   = __float2half_rn(o1 - __half2float(h1));
}

// ---------------- LayerNorm (fp32 out + optional split) --------------------
__global__ __launch_bounds__(256) void ln_kernel(
    const float* __restrict__ in, const float* __restrict__ g,
    const float* __restrict__ b, float* __restrict__ out,
    __half* __restrict__ sp)
{
    __shared__ float r1[8], r2[8];
    const int row = blockIdx.x, tid = threadIdx.x;
    const long long base = (long long)row * D_;
    float v0 = in[base + tid], v1 = in[base + tid + 256];
    float s = v0 + v1, q = v0 * v0 + v1 * v1;
    #pragma unroll
    for (int o = 16; o > 0; o >>= 1) {
        s += __shfl_xor_sync(0xffffffffu, s, o);
        q += __shfl_xor_sync(0xffffffffu, q, o);
    }
    if ((tid & 31) == 0) { r1[tid >> 5] = s; r2[tid >> 5] = q; }
    __syncthreads();
    float ts = 0, tq = 0;
    #pragma unroll
    for (int w = 0; w < 8; w++) { ts += r1[w]; tq += r2[w]; }
    float mu = ts * (1.f / 512.f);
    float var = tq * (1.f / 512.f) - mu * mu;
    float rstd = rsqrtf(var + 1e-5f);
    float o0 = (v0 - mu) * rstd * g[tid]       + b[tid];
    float o1 = (v1 - mu) * rstd * g[tid + 256] + b[tid + 256];
    out[base + tid]       = o0;
    out[base + tid + 256] = o1;
    if (sp) {
        long long b2 = (long long)row * 1024;
        __half h0 = __float2half_rn(o0);
        __half h1 = __float2half_rn(o1);
        sp[b2 + tid]       = h0;
        sp[b2 + tid + 256] = h1;
        sp[b2 + 512 + tid]       = __float2half_rn(o0 - __half2float(h0));
        sp[b2 + 512 + tid + 256] = __float2half_rn(o1 - __half2float(h1));
    }
}

// ================= host wrapper ==============================================
typedef __half h16;

static void gemmL(const h16* Ah, int loA, int ldA, long long zA,
                  const h16* Bt, long long zB, int K,
                  const float* bias, int sBias, const float* res,
                  float* C, long long sC, h16* Sp, long long zSp,
                  h16* KH, h16* KL, h16* VH,
                  const int* glist, const int* gcnt, int gmode,
                  int N, int nz, int relu)
{
    gemm2_kernel<<<dim3(N/128, 32, nz), 512, G2_SMEM>>>(
        Ah, loA, ldA, zA, Bt, zB, K, bias, sBias, res, C, sC,
        Sp, zSp, KH, KL, VH, glist, gcnt, gmode, N, relu);
}

extern "C" void kernel_launch(void* const* d_in, const int* in_sizes, int n_in,
                              void* d_out, int out_size)
{
    const float* q_raw   = (const float*)d_in[0];
    const float* m_seq   = (const float*)d_in[1];
    const float* qa      = (const float*)d_in[2];
    const float* exp_w1  = (const float*)d_in[3];
    const float* exp_b1  = (const float*)d_in[4];
    const float* exp_w2  = (const float*)d_in[5];
    const float* exp_b2  = (const float*)d_in[6];
    const float* adapt_w = (const float*)d_in[7];
    const float* adapt_b = (const float*)d_in[8];
    const float* gate_w  = (const float*)d_in[9];
    const float* gate_b  = (const float*)d_in[10];
    const float* moe_g   = (const float*)d_in[11];
    const float* moe_b   = (const float*)d_in[12];
    const float* kw      = (const float*)d_in[13];
    const float* kb      = (const float*)d_in[14];
    const float* vw      = (const float*)d_in[15];
    const float* vb      = (const float*)d_in[16];
    const float* ow      = (const float*)d_in[17];
    const float* ob      = (const float*)d_in[18];
    const float* ln1g    = (const float*)d_in[19];
    const float* ln1b    = (const float*)d_in[20];
    const float* fw1     = (const float*)d_in[21];
    const float* fb1     = (const float*)d_in[22];
    const float* fw2     = (const float*)d_in[23];
    const float* fb2     = (const float*)d_in[24];
    const float* ln2g    = (const float*)d_in[25];
    const float* ln2b    = (const float*)d_in[26];

    float *pe, *x, *experts, *summary, *wgtp;
    int *cntp, *listp;
    h16 *qbf, *h1bf, *ybf, *xbf, *ctxbf, *ffnbf, *wbf, *khh, *khl, *vth;
    cudaGetSymbolAddress((void**)&pe, g_pe);
    cudaGetSymbolAddress((void**)&x, g_x);
    cudaGetSymbolAddress((void**)&experts, g_experts);
    cudaGetSymbolAddress((void**)&summary, g_summary);
    cudaGetSymbolAddress((void**)&wgtp, g_wgt);
    cudaGetSymbolAddress((void**)&cntp, g_cnt);
    cudaGetSymbolAddress((void**)&listp, g_list);
    cudaGetSymbolAddress((void**)&qbf, g_qbf);
    cudaGetSymbolAddress((void**)&h1bf, g_h1bf);
    cudaGetSymbolAddress((void**)&ybf, g_ybf);
    cudaGetSymbolAddress((void**)&xbf, g_xbf);
    cudaGetSymbolAddress((void**)&ctxbf, g_ctxbf);
    cudaGetSymbolAddress((void**)&ffnbf, g_ffnbf);
    cudaGetSymbolAddress((void**)&wbf, g_wbf);
    cudaGetSymbolAddress((void**)&khh, g_khh);
    cudaGetSymbolAddress((void**)&khl, g_khl);
    cudaGetSymbolAddress((void**)&vth, g_vth);

    static int attr_set = 0;
    if (!attr_set) {
        cudaFuncSetAttribute(gemm2_kernel,
                             cudaFuncAttributeMaxDynamicSharedMemorySize, G2_SMEM);
        cudaFuncSetAttribute(attn_mma_kernel,
                             cudaFuncAttributeMaxDynamicSharedMemorySize, ATTN_SMEM);
        attr_set = 1;
    }

    // 0: pe (+ zero gate counters)
    pe_kernel<<<S_, 256>>>(pe);
    // 1: q_raw split
    conv_qraw_kernel<<<4096 * 768 / 256, 256>>>(q_raw, qbf);
    // 2: ALL weights -> single fp16, one launch
    {
        ConvSegs cs;
        cs.src[0] = exp_w1;  cs.dstOff[0] = W_EXPW1; cs.K[0] = 768;  cs.N[0] = 768;  cs.tOff[0] = 0;
        cs.src[1] = exp_w2;  cs.dstOff[1] = W_EXPW2; cs.K[1] = 768;  cs.N[1] = 512;  cs.tOff[1] = 2304;
        cs.src[2] = adapt_w; cs.dstOff[2] = W_ADAPT; cs.K[2] = 3072; cs.N[2] = 512;  cs.tOff[2] = 3840;
        cs.src[3] = kw;      cs.dstOff[3] = W_KW;    cs.K[3] = 512;  cs.N[3] = 512;  cs.tOff[3] = 5376;
        cs.src[4] = vw;      cs.dstOff[4] = W_VW;    cs.K[4] = 512;  cs.N[4] = 512;  cs.tOff[4] = 6400;
        cs.src[5] = ow;      cs.dstOff[5] = W_OW;    cs.K[5] = 512;  cs.N[5] = 512;  cs.tOff[5] = 7424;
        cs.src[6] = fw1;     cs.dstOff[6] = W_FW1;   cs.K[6] = 512;  cs.N[6] = 2048; cs.tOff[6] = 8448;
        cs.src[7] = fw2;     cs.dstOff[7] = W_FW2;   cs.K[7] = 2048; cs.N[7] = 512;  cs.tOff[7] = 12544;
        convB_all_kernel<<<16640, dim3(32, 8)>>>(cs, wbf);
    }
    // 3: summary = relu(q_flat @ adapt_w + b)
    gemmL(qbf, 3072, 6144, 0, wbf + W_ADAPT, 0, 3072, adapt_b, 0, nullptr,
          summary, 0, nullptr, 0, nullptr, nullptr, nullptr,
          nullptr, nullptr, 0, 512, 1, 1);
    // 4: gate -> weights + expert row lists
    gate_kernel<<<BS, 256>>>(summary, m_seq, gate_w, gate_b, wgtp, cntp, listp);
    // 5: h1 = relu(gathered q_raw @ exp_w1 + b1) -> compacted split
    gemmL(qbf, 3072, 6144, 768, wbf + W_EXPW1, 768LL*768, 768, exp_b1, IN_, nullptr,
          nullptr, 0, h1bf, (long long)BS * 1536, nullptr, nullptr, nullptr,
          listp, cntp, 1, 768, NS_, 1);
    // 6: experts = compacted h1 @ exp_w2 + b2 -> scattered fp32
    gemmL(h1bf, 768, 1536, (long long)BS * 1536, wbf + W_EXPW2, 512LL*768, 768,
          exp_b2, D_, nullptr, experts, BSD, nullptr, 0,
          nullptr, nullptr, nullptr, listp, cntp, 2, 512, NS_, 0);
    // 7: combine + moe LN + pe
    moe_kernel<<<BS, 256>>>(wgtp, experts, moe_g, moe_b, pe, x, xbf);
    // 8: y' = qa + pe split
    add_pe_kernel<<<(int)(BSD / 256), 256>>>(qa, pe, ybf);
    // 9: V for all layers -> transposed fp16 (hi only)
    gemmL(ybf, 512, 1024, 0, wbf + W_VW, 512LL*512, 512, vb, D_, nullptr,
          nullptr, 0, nullptr, 0, nullptr, nullptr, vth,
          nullptr, nullptr, 0, 512, L_, 0);

    for (int i = 0; i < L_; i++) {
        gemmL(xbf, 512, 1024, 0, wbf + W_KW + (long long)i * 262144, 0, 512,
              kb + i*D_, 0, nullptr, nullptr, 0, nullptr, 0,
              khh, khl, nullptr, nullptr, nullptr, 0, 512, 1, 0);
        attn_mma_kernel<<<dim3(16, 32), 128, ATTN_SMEM>>>(
            khh, khl, vth + (long long)i * 2097152, ctxbf);
        gemmL(ctxbf, 512, 1024, 0, wbf + W_OW + (long long)i * 262144, 0, 512,
              ob + i*D_, 0, x, x, 0, nullptr, 0,
              nullptr, nullptr, nullptr, nullptr, nullptr, 0, 512, 1, 0);
        ln_kernel<<<BS, 256>>>(x, ln1g + i*D_, ln1b + i*D_, x, xbf);
        gemmL(xbf, 512, 1024, 0, wbf + W_FW1 + (long long)i * 1048576, 0, 512,
              fb1 + i*FF_, 0, nullptr, nullptr, 0, ffnbf, 0,
              nullptr, nullptr, nullptr, nullptr, nullptr, 0, 2048, 1, 1);
        gemmL(ffnbf, 2048, 4096, 0, wbf + W_FW2 + (long long)i * 1048576, 0, 2048,
              fb2 + i*D_, 0, x, x, 0, nullptr, 0,
              nullptr, nullptr, nullptr, nullptr, nullptr, 0, 512, 1, 0);
        ln_kernel<<<BS, 256>>>(x, ln2g + i*D_, ln2b + i*D_,
                               (i == L_-1) ? (float*)d_out : x,
                               (i == L_-1) ? nullptr : xbf);
    }
}

// round 11
// speedup vs baseline: 4.6945x; 1.0128x over previous
#include <cuda_runtime.h>
#include <cuda_fp16.h>
#include <cstdint>
#include <math.h>

// Problem dims
#define B_  4
#define S_  1024
#define D_  512
#define H_  8
#define DK_ 64
#define FF_ 2048
#define L_  4
#define IN_ 768
#define NS_ 4
#define SD_ 64

#define BS  (B_*S_)            // 4096
#define BSD ((long long)BS*D_) // 2097152
#define NEG_INF __int_as_float(0xff800000)

// ---------------- scratch (device globals: allocation-free) ----------------
__device__ float g_pe[S_*D_];
__device__ float g_x[BS*D_];
__device__ float g_experts[NS_*BS*D_];
__device__ float g_summary[BS*D_];
__device__ float g_wgt[BS*4];
__device__ int   g_cnt[4];
__device__ int   g_list[4*BS];
// split fp16 buffers, layout [m][hi K | lo K]
__device__ __half g_qbf[25165824];    // q_raw' [4096][6144]
__device__ __half g_h1bf[25165824];   // h1'   [4][4096][1536] (compacted slots)
__device__ __half g_ybf[4194304];     // y'    [4096][1024]
__device__ __half g_xbf[4194304];     // x'    [4096][1024]
__device__ __half g_ctxbf[4194304];   // ctx'  [4096][1024]
__device__ __half g_ffnbf[16777216];  // ffn'  [4096][4096]
__device__ __half g_khh[2097152];     // K hi [32][1024][64]
__device__ __half g_khl[2097152];     // K lo
__device__ __half g_vth[8388608];     // Vt hi [4][32][64][1024]
// all weights, SINGLE fp16 [n][K]
__device__ __half g_wbf[17039360];

// weight buffer offsets (fp16 elements)
#define W_EXPW1 0LL
#define W_EXPW2 2359296LL
#define W_ADAPT 3932160LL
#define W_KW    5505024LL
#define W_VW    6553600LL
#define W_OW    7602176LL
#define W_FW1   8650752LL
#define W_FW2   12845056LL

// ================= PTX helpers ===============================================
__device__ __forceinline__ uint32_t smem_u32(const void* p) {
    uint32_t a;
    asm("{ .reg .u64 t; cvta.to.shared.u64 t, %1; cvt.u32.u64 %0, t; }" : "=r"(a) : "l"(p));
    return a;
}
__device__ __forceinline__ void cp_async16(uint32_t dst, const void* src) {
    asm volatile("cp.async.cg.shared.global [%0], [%1], 16;" :: "r"(dst), "l"(src));
}
#define CP_COMMIT() asm volatile("cp.async.commit_group;" ::: "memory")
#define CP_WAIT0()  asm volatile("cp.async.wait_group 0;" ::: "memory")
#define CP_WAIT1()  asm volatile("cp.async.wait_group 1;" ::: "memory")

__device__ __forceinline__ void ldsm_x4(uint32_t& r0, uint32_t& r1, uint32_t& r2,
                                        uint32_t& r3, uint32_t addr) {
    asm volatile("ldmatrix.sync.aligned.m8n8.x4.shared.b16 {%0,%1,%2,%3}, [%4];"
        : "=r"(r0), "=r"(r1), "=r"(r2), "=r"(r3) : "r"(addr));
}
__device__ __forceinline__ void mma16816(float* c, const uint32_t* a, const uint32_t* b) {
    asm volatile(
        "mma.sync.aligned.m16n8k16.row.col.f32.f16.f16.f32 "
        "{%0,%1,%2,%3}, {%4,%5,%6,%7}, {%8,%9}, {%0,%1,%2,%3};"
        : "+f"(c[0]), "+f"(c[1]), "+f"(c[2]), "+f"(c[3])
        : "r"(a[0]), "r"(a[1]), "r"(a[2]), "r"(a[3]), "r"(b[0]), "r"(b[1]));
}
__device__ __forceinline__ uint32_t pack_h2(float lo, float hi) {
    uint32_t d;
    asm("cvt.rn.f16x2.f32 %0, %1, %2;" : "=r"(d) : "f"(hi), "f"(lo));
    return d;
}
__device__ __forceinline__ float h2_lo(uint32_t p) {
    return __half2float(__ushort_as_half((unsigned short)(p & 0xffff)));
}
__device__ __forceinline__ float h2_hi(uint32_t p) {
    return __half2float(__ushort_as_half((unsigned short)(p >> 16)));
}

__device__ __forceinline__ uint32_t swz(uint32_t base, int r, int ch) {
    return base + r * 128 + ((ch ^ (r & 7)) << 4);
}

// ================= conversions ==============================================
// q_raw [4096][3072] fp32 -> q' [4096][6144] = [hi 3072 | lo 3072]
__global__ __launch_bounds__(256) void conv_qraw_kernel(
    const float* __restrict__ src, __half* __restrict__ dst)
{
    int idx = blockIdx.x * 256 + threadIdx.x;
    int m = idx / 768;
    int k = (idx - m * 768) * 4;
    float4 v = *(const float4*)(src + (long long)m * 3072 + k);
    unsigned short hb[4], lb[4];
    float vv[4] = {v.x, v.y, v.z, v.w};
    #pragma unroll
    for (int i = 0; i < 4; i++) {
        __half h = __float2half_rn(vv[i]);
        __half l = __float2half_rn(vv[i] - __half2float(h));
        hb[i] = __half_as_ushort(h);
        lb[i] = __half_as_ushort(l);
    }
    long long base = (long long)m * 6144;
    *(uint2*)(dst + base + k) = make_uint2((uint32_t)hb[0] | ((uint32_t)hb[1] << 16),
                                           (uint32_t)hb[2] | ((uint32_t)hb[3] << 16));
    *(uint2*)(dst + base + 3072 + k) = make_uint2((uint32_t)lb[0] | ((uint32_t)lb[1] << 16),
                                                  (uint32_t)lb[2] | ((uint32_t)lb[3] << 16));
}

// all weights W [z][K][N] fp32 -> W' [z][n][K] single fp16, one launch
struct ConvSegs {
    const float* src[8];
    long long dstOff[8];
    int K[8], N[8], tOff[8];
};

__global__ void convB_all_kernel(ConvSegs segs, __half* __restrict__ wb)
{
    __shared__ float t[32][33];
    int bx = blockIdx.x;
    int seg = 0;
    #pragma unroll
    for (int i = 7; i >= 1; i--) if (bx >= segs.tOff[i]) { seg = i; break; }
    const int K = segs.K[seg], N = segs.N[seg];
    int tl = bx - segs.tOff[seg];
    int tz = (K >> 5) * (N >> 5);
    int z = tl / tz, rr = tl - z * tz;
    int k0 = (rr % (K >> 5)) * 32, n0 = (rr / (K >> 5)) * 32;
    const float* s = segs.src[seg] + (long long)z * K * N;
    __half* dstz = wb + segs.dstOff[seg] + (long long)z * N * K;
    int tx = threadIdx.x, ty = threadIdx.y;
    #pragma unroll
    for (int r = ty; r < 32; r += 8)
        t[r][tx] = s[(long long)(k0 + r) * N + n0 + tx];
    __syncthreads();
    #pragma unroll
    for (int r = ty; r < 32; r += 8) {
        dstz[(long long)(n0 + r) * K + k0 + tx] = __float2half_rn(t[tx][r]);
    }
}

// ================= unified split GEMM (fp16, 2 terms: Xh*W + Xl*W) ==========
// 256 threads, 8 warps, warp tile 32x32 over 128x64 CTA tile, 2-stage, 2 CTA/SM.
// gmode: 0 = dense, 1 = gather-A rows via list (Sp at slots), 2 = scatter-C rows
#define G2_STAGE 40960
#define G2_SMEM  81920

__global__ __launch_bounds__(256, 2) void gemm2_kernel(
    const __half* __restrict__ Ah0, int loA, int ldA, long long zA,
    const __half* __restrict__ Bt0, long long zB, int K,
    const float* __restrict__ bias, int sBias,
    const float* __restrict__ res,
    float* __restrict__ C, long long sC,
    __half* __restrict__ Sp, long long zSp,
    __half* __restrict__ KH, __half* __restrict__ KL,
    __half* __restrict__ VH,
    const int* __restrict__ glist, const int* __restrict__ gcnt,
    int gmode, int N, int relu)
{
    extern __shared__ __align__(1024) char smem[];
    __shared__ int slist[128];
    const int tid = threadIdx.x, wid = tid >> 5, lane = tid & 31;
    const int wy = wid >> 1, wx = wid & 1;       // 4x2 warps, 32x32 each
    const int z = blockIdx.z;
    const int brow = blockIdx.y * 128, bcol = blockIdx.x * 64;

    int cnt = 0;
    if (gmode) {
        cnt = gcnt[z];
        if (brow >= cnt) return;
        if (tid < 128) {
            int i = brow + tid;
            slist[tid] = glist[z * BS + (i < cnt ? i : cnt - 1)];
        }
    }

    const __half* Ahz = Ah0 + (long long)z * zA;
    const __half* Bh = Bt0 + (long long)z * zB + (long long)bcol * K;
    if (bias) bias += (long long)z * sBias;
    if (C) C += (long long)z * sC;
    if (Sp) Sp += (long long)z * zSp;

    if (gmode) __syncthreads();

    const uint32_t sb = smem_u32(smem);
    const int NC = K >> 6;

    // stage layout: Ah 16K @0, Al 16K @16384, B 8K @32768 (40K total)
    auto load_tile = [&](int c, int s) {
        const int kc = c * 64;
        const uint32_t st = sb + s * G2_STAGE;
        #pragma unroll
        for (int i = 0; i < 10; i++) {
            int idx = tid + i * 256;          // 0..2559
            if (idx < 1024) {
                int r = idx >> 3, ch = idx & 7;
                int rowA = (gmode == 1) ? slist[r] : (brow + r);
                cp_async16(swz(st, r, ch),
                           (const char*)(Ahz + (long long)rowA * ldA + kc) + ch * 16);
            } else if (idx < 2048) {
                int j = idx - 1024;
                int r = j >> 3, ch = j & 7;
                int rowA = (gmode == 1) ? slist[r] : (brow + r);
                cp_async16(swz(st + 16384, r, ch),
                           (const char*)(Ahz + loA + (long long)rowA * ldA + kc) + ch * 16);
            } else {
                int j = idx - 2048;
                int r = j >> 3, ch = j & 7;
                cp_async16(swz(st + 32768, r, ch),
                           (const char*)(Bh + (long long)r * K + kc) + ch * 16);
            }
        }
        CP_COMMIT();
    };

    float acc[2][4][4] = {};
    load_tile(0, 0);
    load_tile(1, 1);

    for (int c = 0; c < NC; c++) {
        const int s = c & 1;
        if (c + 1 < NC) { CP_WAIT1(); } else { CP_WAIT0(); }
        __syncthreads();
        const uint32_t stA = sb + s * G2_STAGE;

        #pragma unroll
        for (int ks = 0; ks < 4; ks++) {
            const int cb = ks * 2;
            uint32_t ah[2][4], al[2][4];
            #pragma unroll
            for (int ms = 0; ms < 2; ms++) {
                int r = wy * 32 + ms * 16 + (lane & 15);
                int ch = cb + (lane >> 4);
                ldsm_x4(ah[ms][0], ah[ms][1], ah[ms][2], ah[ms][3], swz(stA, r, ch));
                ldsm_x4(al[ms][0], al[ms][1], al[ms][2], al[ms][3], swz(stA + 16384, r, ch));
            }
            uint32_t bh[4][2];
            #pragma unroll
            for (int nh = 0; nh < 2; nh++) {
                int g = lane >> 3;
                int r = wx * 32 + nh * 16 + ((g & 2) << 2) + (lane & 7);
                int ch = cb + (g & 1);
                uint32_t r0, r1, r2, r3;
                ldsm_x4(r0, r1, r2, r3, swz(stA + 32768, r, ch));
                bh[nh*2][0] = r0; bh[nh*2][1] = r1;
                bh[nh*2+1][0] = r2; bh[nh*2+1][1] = r3;
            }
            // term-major: 8 independent accumulators between reuses
            #pragma unroll
            for (int ms = 0; ms < 2; ms++)
                #pragma unroll
                for (int ns = 0; ns < 4; ns++)
                    mma16816(acc[ms][ns], ah[ms], bh[ns]);
            #pragma unroll
            for (int ms = 0; ms < 2; ms++)
                #pragma unroll
                for (int ns = 0; ns < 4; ns++)
                    mma16816(acc[ms][ns], al[ms], bh[ns]);
        }
        __syncthreads();
        if (c + 2 < NC) load_tile(c + 2, s);
    }

    // ---- epilogue ----
    const int qrow = lane >> 2, qcol = (lane & 3) * 2;
    #pragma unroll
    for (int ms = 0; ms < 2; ms++) {
        int m = brow + wy * 32 + ms * 16 + qrow;
        bool ok0 = !gmode || (m < cnt);
        bool ok1 = !gmode || (m + 8 < cnt);
        int crow0 = (gmode == 2 && ok0) ? slist[m - brow] : m;
        int crow1 = (gmode == 2 && ok1) ? slist[m + 8 - brow] : m + 8;
        #pragma unroll
        for (int ns = 0; ns < 4; ns++) {
            int n = bcol + wx * 32 + ns * 8 + qcol;
            float2 v0 = make_float2(acc[ms][ns][0], acc[ms][ns][1]);
            float2 v1 = make_float2(acc[ms][ns][2], acc[ms][ns][3]);
            if (bias) {
                float b0 = bias[n], b1 = bias[n + 1];
                v0.x += b0; v0.y += b1; v1.x += b0; v1.y += b1;
            }
            if (res) {
                float2 r0 = *(const float2*)(res + (long long)m * N + n);
                float2 r1 = *(const float2*)(res + (long long)(m + 8) * N + n);
                v0.x += r0.x; v0.y += r0.y; v1.x += r1.x; v1.y += r1.y;
            }
            if (relu) {
                v0.x = fmaxf(v0.x, 0.f); v0.y = fmaxf(v0.y, 0.f);
                v1.x = fmaxf(v1.x, 0.f); v1.y = fmaxf(v1.y, 0.f);
            }
            if (C) {
                if (ok0) *(float2*)(C + (long long)crow0 * N + n) = v0;
                if (ok1) *(float2*)(C + (long long)crow1 * N + n) = v1;
            }
            uint32_t hp0 = pack_h2(v0.x, v0.y);
            uint32_t hp1 = pack_h2(v1.x, v1.y);
            uint32_t lp0 = pack_h2(v0.x - h2_lo(hp0), v0.y - h2_hi(hp0));
            uint32_t lp1 = pack_h2(v1.x - h2_lo(hp1), v1.y - h2_hi(hp1));
            if (Sp) {
                long long r0 = (long long)m * 2 * N, r1 = (long long)(m + 8) * 2 * N;
                if (ok0) {
                    *(uint32_t*)(Sp + r0 + n)     = hp0;
                    *(uint32_t*)(Sp + r0 + N + n) = lp0;
                }
                if (ok1) {
                    *(uint32_t*)(Sp + r1 + n)     = hp1;
                    *(uint32_t*)(Sp + r1 + N + n) = lp1;
                }
            }
            if (KH) {
                long long a0 = (((long long)((m >> 10) * 8 + (n >> 6))) * 1024 + (m & 1023)) * 64 + (n & 63);
                long long a1 = a0 + 8LL * 64;
                *(uint32_t*)(KH + a0) = hp0;  *(uint32_t*)(KL + a0) = lp0;
                *(uint32_t*)(KH + a1) = hp1;  *(uint32_t*)(KL + a1) = lp1;
            }
            if (VH) {
                int b = m >> 10, h = n >> 6, d = n & 63, si = m & 1023;
                long long base = (((long long)(z * 32 + b * 8 + h)) * 64 + d) * 1024 + si;
                unsigned short* vh = (unsigned short*)VH;
                vh[base]            = (unsigned short)(hp0 & 0xffff);
                vh[base + 1024]     = (unsigned short)(hp0 >> 16);
                vh[base + 8]        = (unsigned short)(hp1 & 0xffff);
                vh[base + 1024 + 8] = (unsigned short)(hp1 >> 16);
            }
        }
    }
}

// ================= tensor-core flash attention (fp16 2-term) =================
// smem: Qhi @0 (8K), Qlo @8192; stages @16384 + s*16384: {Khi 8K, Vhi 8K}
#define ATTN_SMEM 49152

__global__ __launch_bounds__(128) void attn_mma_kernel(
    const __half* __restrict__ khh, const __half* __restrict__ khl,
    const __half* __restrict__ vth,
    __half* __restrict__ Cx)
{
    extern __shared__ __align__(1024) char smem[];
    const uint32_t sb = smem_u32(smem);
    const int tid = threadIdx.x, wid = tid >> 5, lane = tid & 31;
    const int qb = 15 - blockIdx.x;
    const int bh = blockIdx.y;
    const int q0 = qb * 64;

    const __half* Kh = khh + (long long)bh * S_ * 64;
    const __half* Kl = khl + (long long)bh * S_ * 64;
    const __half* Vh = vth + (long long)bh * 64 * S_;

    auto load_kv = [&](int jt, int s) {
        const int j0 = jt * 64;
        const uint32_t base = sb + 16384 + s * 16384;
        #pragma unroll
        for (int i = 0; i < 4; i++) {
            int idx = tid + i * 128;
            int r = idx >> 3, ch = idx & 7;
            cp_async16(swz(base, r, ch),
                       (const char*)(Kh + (long long)(j0 + r) * 64) + ch * 16);
            cp_async16(swz(base + 8192, r, ch),
                       (const char*)(Vh + (long long)r * S_ + j0) + ch * 16);
        }
        CP_COMMIT();
    };

    #pragma unroll
    for (int i = 0; i < 4; i++) {
        int idx = tid + i * 128;
        int r = idx >> 3, ch = idx & 7;
        cp_async16(swz(sb, r, ch),
                   (const char*)(Kh + (long long)(q0 + r) * 64) + ch * 16);
        cp_async16(swz(sb + 8192, r, ch),
                   (const char*)(Kl + (long long)(q0 + r) * 64) + ch * 16);
    }
    load_kv(0, 0);
    CP_WAIT0();
    __syncthreads();

    uint32_t qh[4][4], ql[4][4];
    #pragma unroll
    for (int ks = 0; ks < 4; ks++) {
        int r = wid * 16 + (lane & 15);
        int ch = 2 * ks + (lane >> 4);
        ldsm_x4(qh[ks][0], qh[ks][1], qh[ks][2], qh[ks][3], swz(sb, r, ch));
        ldsm_x4(ql[ks][0], ql[ks][1], ql[ks][2], ql[ks][3], swz(sb + 8192, r, ch));
    }

    float ctx[8][4] = {};
    float m0 = NEG_INF, m1 = NEG_INF, l0 = 0.f, l1 = 0.f;
    const int rg0 = q0 + wid * 16 + (lane >> 2);

    for (int jt = 0; jt <= qb; jt++) {
        const int s = jt & 1;
        if (jt < qb) { load_kv(jt + 1, s ^ 1); CP_WAIT1(); }
        else if (jt > 0) { CP_WAIT0(); }
        __syncthreads();

        const uint32_t bK = sb + 16384 + s * 16384;

        float sc[8][4] = {};
        #pragma unroll
        for (int ks = 0; ks < 4; ks++) {
            uint32_t bh_[8][2];
            #pragma unroll
            for (int ng = 0; ng < 4; ng++) {
                int g = lane >> 3;
                int r = ng * 16 + ((g & 2) << 2) + (lane & 7);
                int ch = 2 * ks + (g & 1);
                uint32_t a0, a1, a2, a3;
                ldsm_x4(a0, a1, a2, a3, swz(bK, r, ch));
                bh_[2*ng][0] = a0; bh_[2*ng][1] = a1;
                bh_[2*ng+1][0] = a2; bh_[2*ng+1][1] = a3;
            }
            #pragma unroll
            for (int nt = 0; nt < 8; nt++) {
                mma16816(sc[nt], qh[ks], bh_[nt]);
                mma16816(sc[nt], ql[ks], bh_[nt]);
            }
        }

        const int j0 = jt * 64;
        const bool diag = (jt == qb);
        const int cb0 = j0 + (lane & 3) * 2;
        float rm0 = NEG_INF, rm1 = NEG_INF;
        #pragma unroll
        for (int nt = 0; nt < 8; nt++) {
            int c0 = cb0 + nt * 8, c1 = c0 + 1;
            float s0 = sc[nt][0] * 0.125f, s1 = sc[nt][1] * 0.125f;
            float s2 = sc[nt][2] * 0.125f, s3 = sc[nt][3] * 0.125f;
            if (diag) {
                if (c0 >= rg0)     s0 = NEG_INF;
                if (c1 >= rg0)     s1 = NEG_INF;
                if (c0 >= rg0 + 8) s2 = NEG_INF;
                if (c1 >= rg0 + 8) s3 = NEG_INF;
            }
            sc[nt][0] = s0; sc[nt][1] = s1; sc[nt][2] = s2; sc[nt][3] = s3;
            rm0 = fmaxf(rm0, fmaxf(s0, s1));
            rm1 = fmaxf(rm1, fmaxf(s2, s3));
        }
        #pragma unroll
        for (int o = 1; o <= 2; o <<= 1) {
            rm0 = fmaxf(rm0, __shfl_xor_sync(0xffffffffu, rm0, o));
            rm1 = fmaxf(rm1, __shfl_xor_sync(0xffffffffu, rm1, o));
        }
        float mn0 = fmaxf(m0, rm0), mn1 = fmaxf(m1, rm1);
        float ms0 = (mn0 == NEG_INF) ? 0.f : mn0;
        float ms1 = (mn1 == NEG_INF) ? 0.f : mn1;
        float cr0 = __expf(m0 - ms0), cr1 = __expf(m1 - ms1);
        float rs0 = 0.f, rs1 = 0.f;
        #pragma unroll
        for (int nt = 0; nt < 8; nt++) {
            sc[nt][0] = __expf(sc[nt][0] - ms0); rs0 += sc[nt][0];
            sc[nt][1] = __expf(sc[nt][1] - ms0); rs0 += sc[nt][1];
            sc[nt][2] = __expf(sc[nt][2] - ms1); rs1 += sc[nt][2];
            sc[nt][3] = __expf(sc[nt][3] - ms1); rs1 += sc[nt][3];
        }
        #pragma unroll
        for (int o = 1; o <= 2; o <<= 1) {
            rs0 += __shfl_xor_sync(0xffffffffu, rs0, o);
            rs1 += __shfl_xor_sync(0xffffffffu, rs1, o);
        }
        l0 = l0 * cr0 + rs0; l1 = l1 * cr1 + rs1;
        m0 = mn0; m1 = mn1;
        #pragma unroll
        for (int nt = 0; nt < 8; nt++) {
            ctx[nt][0] *= cr0; ctx[nt][1] *= cr0;
            ctx[nt][2] *= cr1; ctx[nt][3] *= cr1;
        }

        uint32_t ph[4][4], pl[4][4];
        #pragma unroll
        for (int kj = 0; kj < 4; kj++) {
            const int t0 = 2 * kj, t1 = 2 * kj + 1;
            ph[kj][0] = pack_h2(sc[t0][0], sc[t0][1]);
            ph[kj][1] = pack_h2(sc[t0][2], sc[t0][3]);
            ph[kj][2] = pack_h2(sc[t1][0], sc[t1][1]);
            ph[kj][3] = pack_h2(sc[t1][2], sc[t1][3]);
            pl[kj][0] = pack_h2(sc[t0][0] - h2_lo(ph[kj][0]), sc[t0][1] - h2_hi(ph[kj][0]));
            pl[kj][1] = pack_h2(sc[t0][2] - h2_lo(ph[kj][1]), sc[t0][3] - h2_hi(ph[kj][1]));
            pl[kj][2] = pack_h2(sc[t1][0] - h2_lo(ph[kj][2]), sc[t1][1] - h2_hi(ph[kj][2]));
            pl[kj][3] = pack_h2(sc[t1][2] - h2_lo(ph[kj][3]), sc[t1][3] - h2_hi(ph[kj][3]));
        }

        const uint32_t bV = bK + 8192;
        #pragma unroll
        for (int kj = 0; kj < 4; kj++) {
            uint32_t vh_[8][2];
            #pragma unroll
            for (int dg = 0; dg < 4; dg++) {
                int g = lane >> 3;
                int r = dg * 16 + ((g & 2) << 2) + (lane & 7);
                int ch = 2 * kj + (g & 1);
                uint32_t a0, a1, a2, a3;
                ldsm_x4(a0, a1, a2, a3, swz(bV, r, ch));
                vh_[2*dg][0] = a0; vh_[2*dg][1] = a1;
                vh_[2*dg+1][0] = a2; vh_[2*dg+1][1] = a3;
            }
            #pragma unroll
            for (int nt = 0; nt < 8; nt++) {
                mma16816(ctx[nt], ph[kj], vh_[nt]);
                mma16816(ctx[nt], pl[kj], vh_[nt]);
            }
        }
        __syncthreads();
    }

    float inv0 = (l0 > 0.f) ? 1.f / l0 : 0.f;
    float inv1 = (l1 > 0.f) ? 1.f / l1 : 0.f;
    const int b = bh >> 3, h = bh & 7;
    const int row0 = b * S_ + q0 + wid * 16 + (lane >> 2);
    const int colb = h * 64 + (lane & 3) * 2;
    #pragma unroll
    for (int nt = 0; nt < 8; nt++) {
        float a0 = ctx[nt][0] * inv0, a1 = ctx[nt][1] * inv0;
        float a2 = ctx[nt][2] * inv1, a3 = ctx[nt][3] * inv1;
        uint32_t hp0 = pack_h2(a0, a1);
        uint32_t hp1 = pack_h2(a2, a3);
        uint32_t lp0 = pack_h2(a0 - h2_lo(hp0), a1 - h2_hi(hp0));
        uint32_t lp1 = pack_h2(a2 - h2_lo(hp1), a3 - h2_hi(hp1));
        long long r0 = (long long)row0 * 1024, r1 = (long long)(row0 + 8) * 1024;
        int cc = colb + nt * 8;
        *(uint32_t*)(Cx + r0 + cc)       = hp0;
        *(uint32_t*)(Cx + r0 + 512 + cc) = lp0;
        *(uint32_t*)(Cx + r1 + cc)       = hp1;
        *(uint32_t*)(Cx + r1 + 512 + cc) = lp1;
    }
}

// ---------------- positional embedding (also zero gate counters) -----------
__global__ void pe_kernel(float* __restrict__ pe) {
    if (blockIdx.x == 0 && threadIdx.x < 4) g_cnt[threadIdx.x] = 0;
    int s = blockIdx.x;
    int j = threadIdx.x;
    float div = expf((float)(2*j) * (-9.210340371976184f / (float)D_));
    float arg = (float)s * div;
    pe[s*D_ + 2*j]     = sinf(arg);
    pe[s*D_ + 2*j + 1] = cosf(arg);
}

__global__ __launch_bounds__(256) void add_pe_kernel(
    const float* __restrict__ qa, const float* __restrict__ pe,
    __half* __restrict__ yb)
{
    int i = blockIdx.x * 256 + threadIdx.x;
    float v = qa[i] + pe[i & (S_*D_ - 1)];
    int m = i >> 9, c = i & 511;
    __half h = __float2half_rn(v);
    yb[(long long)m * 1024 + c]       = h;
    yb[(long long)m * 1024 + 512 + c] = __float2half_rn(v - __half2float(h));
}

// ---------------- gate: logits -> top-2 weights + expert row lists ----------
__global__ __launch_bounds__(256) void gate_kernel(
    const float* __restrict__ summary, const float* __restrict__ m_seq,
    const float* __restrict__ gate_w,  const float* __restrict__ gate_b,
    float* __restrict__ wgt, int* __restrict__ cnt, int* __restrict__ list)
{
    __shared__ float red[4][8];
    const int row = blockIdx.x;
    const int tid = threadIdx.x;

    float p0 = 0, p1 = 0, p2 = 0, p3 = 0;
    for (int e = tid; e < D_ + SD_; e += 256) {
        float xv = (e < D_) ? summary[(long long)row * D_ + e]
                            : m_seq[(long long)row * SD_ + (e - D_)];
        float4 w = *(const float4*)(gate_w + e * 4);
        p0 += xv * w.x; p1 += xv * w.y; p2 += xv * w.z; p3 += xv * w.w;
    }
    #pragma unroll
    for (int o = 16; o > 0; o >>= 1) {
        p0 += __shfl_xor_sync(0xffffffffu, p0, o);
        p1 += __shfl_xor_sync(0xffffffffu, p1, o);
        p2 += __shfl_xor_sync(0xffffffffu, p2, o);
        p3 += __shfl_xor_sync(0xffffffffu, p3, o);
    }
    if ((tid & 31) == 0) {
        int w = tid >> 5;
        red[0][w] = p0; red[1][w] = p1; red[2][w] = p2; red[3][w] = p3;
    }
    __syncthreads();

    if (tid == 0) {
        float l[4];
        #pragma unroll
        for (int j = 0; j < 4; j++) {
            float t = gate_b[j];
            #pragma unroll
            for (int w = 0; w < 8; w++) t += red[j][w];
            l[j] = t;
        }
        float m1v = -INFINITY, m2v = -INFINITY;
        #pragma unroll
        for (int j = 0; j < 4; j++) {
            if (l[j] > m1v) { m2v = m1v; m1v = l[j]; }
            else if (l[j] > m2v) { m2v = l[j]; }
        }
        float sum = 0.f, e4[4];
        #pragma unroll
        for (int j = 0; j < 4; j++) {
            e4[j] = (l[j] >= m2v) ? __expf(l[j] - m1v) : 0.f;
            sum += e4[j];
        }
        #pragma unroll
        for (int j = 0; j < 4; j++) {
            wgt[row * 4 + j] = e4[j] / sum;
            if (l[j] >= m2v) {
                int p = atomicAdd(&cnt[j], 1);
                list[j * BS + p] = row;
            }
        }
    }
}

// ---------------- MoE combine + LN + PE -> x (fp32 + split) ----------------
__global__ __launch_bounds__(256) void moe_kernel(
    const float* __restrict__ wgt, const float* __restrict__ experts,
    const float* __restrict__ lng, const float* __restrict__ lnb,
    const float* __restrict__ pe, float* __restrict__ x,
    __half* __restrict__ xb)
{
    __shared__ float r1[8], r2[8];
    const int row = blockIdx.x;
    const int tid = threadIdx.x;
    const int s_idx = row & (S_ - 1);

    const float w0 = wgt[row*4], w1 = wgt[row*4+1], w2 = wgt[row*4+2], w3 = wgt[row*4+3];
    const long long base = (long long)row * D_;
    const int t2 = tid + 256;
    float c0 = w0 * experts[0*BSD + base + tid] + w1 * experts[1*BSD + base + tid]
             + w2 * experts[2*BSD + base + tid] + w3 * experts[3*BSD + base + tid];
    float c1 = w0 * experts[0*BSD + base + t2]  + w1 * experts[1*BSD + base + t2]
             + w2 * experts[2*BSD + base + t2]  + w3 * experts[3*BSD + base + t2];

    float s = c0 + c1, q = c0 * c0 + c1 * c1;
    #pragma unroll
    for (int o = 16; o > 0; o >>= 1) {
        s += __shfl_xor_sync(0xffffffffu, s, o);
        q += __shfl_xor_sync(0xffffffffu, q, o);
    }
    if ((tid & 31) == 0) { r1[tid >> 5] = s; r2[tid >> 5] = q; }
    __syncthreads();
    float ts = 0, tq = 0;
    #pragma unroll
    for (int w = 0; w < 8; w++) { ts += r1[w]; tq += r2[w]; }
    float mu = ts * (1.f / 512.f);
    float var = tq * (1.f / 512.f) - mu * mu;
    float rstd = rsqrtf(var + 1e-5f);

    float o0 = (c0 - mu) * rstd * lng[tid] + lnb[tid] + pe[s_idx * D_ + tid];
    float o1 = (c1 - mu) * rstd * lng[t2]  + lnb[t2]  + pe[s_idx * D_ + t2];
    x[base + tid] = o0;
    x[base + t2]  = o1;
    long long b2 = (long long)row * 1024;
    __half h0 = __float2half_rn(o0);
    __half h1 = __float2half_rn(o1);
    xb[b2 + tid]        = h0;
    xb[b2 + t2]         = h1;
    xb[b2 + 512 + tid]  = __float2half_rn(o0 - __half2float(h0));
    xb[b2 + 512 + t2]   = __float2half_rn(o1 - __half2float(h1));
}

// ---------------- LayerNorm (fp32 out + optional split) --------------------
__global__ __launch_bounds__(256) void ln_kernel(
    const float* __restrict__ in, const float* __restrict__ g,
    const float* __restrict__ b, float* __restrict__ out,
    __half* __restrict__ sp)
{
    __shared__ float r1[8], r2[8];
    const int row = blockIdx.x, tid = threadIdx.x;
    const long long base = (long long)row * D_;
    float v0 = in[base + tid], v1 = in[base + tid + 256];
    float s = v0 + v1, q = v0 * v0 + v1 * v1;
    #pragma unroll
    for (int o = 16; o > 0; o >>= 1) {
        s += __shfl_xor_sync(0xffffffffu, s, o);
        q += __shfl_xor_sync(0xffffffffu, q, o);
    }
    if ((tid & 31) == 0) { r1[tid >> 5] = s; r2[tid >> 5] = q; }
    __syncthreads();
    float ts = 0, tq = 0;
    #pragma unroll
    for (int w = 0; w < 8; w++) { ts += r1[w]; tq += r2[w]; }
    float mu = ts * (1.f / 512.f);
    float var = tq * (1.f / 512.f) - mu * mu;
    float rstd = rsqrtf(var + 1e-5f);
    float o0 = (v0 - mu) * rstd * g[tid]       + b[tid];
    float o1 = (v1 - mu) * rstd * g[tid + 256] + b[tid + 256];
    out[base + tid]       = o0;
    out[base + tid + 256] = o1;
    if (sp) {
        long long b2 = (long long)row * 1024;
        __half h0 = __float2half_rn(o0);
        __half h1 = __float2half_rn(o1);
        sp[b2 + tid]       = h0;
        sp[b2 + tid + 256] = h1;
        sp[b2 + 512 + tid]       = __float2half_rn(o0 - __half2float(h0));
        sp[b2 + 512 + tid + 256] = __float2half_rn(o1 - __half2float(h1));
    }
}

// ================= host wrapper ==============================================
typedef __half h16;

static void gemmL(const h16* Ah, int loA, int ldA, long long zA,
                  const h16* Bt, long long zB, int K,
                  const float* bias, int sBias, const float* res,
                  float* C, long long sC, h16* Sp, long long zSp,
                  h16* KH, h16* KL, h16* VH,
                  const int* glist, const int* gcnt, int gmode,
                  int N, int nz, int relu)
{
    gemm2_kernel<<<dim3(N/64, 32, nz), 256, G2_SMEM>>>(
        Ah, loA, ldA, zA, Bt, zB, K, bias, sBias, res, C, sC,
        Sp, zSp, KH, KL, VH, glist, gcnt, gmode, N, relu);
}

extern "C" void kernel_launch(void* const* d_in, const int* in_sizes, int n_in,
                              void* d_out, int out_size)
{
    const float* q_raw   = (const float*)d_in[0];
    const float* m_seq   = (const float*)d_in[1];
    const float* qa      = (const float*)d_in[2];
    const float* exp_w1  = (const float*)d_in[3];
    const float* exp_b1  = (const float*)d_in[4];
    const float* exp_w2  = (const float*)d_in[5];
    const float* exp_b2  = (const float*)d_in[6];
    const float* adapt_w = (const float*)d_in[7];
    const float* adapt_b = (const float*)d_in[8];
    const float* gate_w  = (const float*)d_in[9];
    const float* gate_b  = (const float*)d_in[10];
    const float* moe_g   = (const float*)d_in[11];
    const float* moe_b   = (const float*)d_in[12];
    const float* kw      = (const float*)d_in[13];
    const float* kb      = (const float*)d_in[14];
    const float* vw      = (const float*)d_in[15];
    const float* vb      = (const float*)d_in[16];
    const float* ow      = (const float*)d_in[17];
    const float* ob      = (const float*)d_in[18];
    const float* ln1g    = (const float*)d_in[19];
    const float* ln1b    = (const float*)d_in[20];
    const float* fw1     = (const float*)d_in[21];
    const float* fb1     = (const float*)d_in[22];
    const float* fw2     = (const float*)d_in[23];
    const float* fb2     = (const float*)d_in[24];
    const float* ln2g    = (const float*)d_in[25];
    const float* ln2b    = (const float*)d_in[26];

    float *pe, *x, *experts, *summary, *wgtp;
    int *cntp, *listp;
    h16 *qbf, *h1bf, *ybf, *xbf, *ctxbf, *ffnbf, *wbf, *khh, *khl, *vth;
    cudaGetSymbolAddress((void**)&pe, g_pe);
    cudaGetSymbolAddress((void**)&x, g_x);
    cudaGetSymbolAddress((void**)&experts, g_experts);
    cudaGetSymbolAddress((void**)&summary, g_summary);
    cudaGetSymbolAddress((void**)&wgtp, g_wgt);
    cudaGetSymbolAddress((void**)&cntp, g_cnt);
    cudaGetSymbolAddress((void**)&listp, g_list);
    cudaGetSymbolAddress((void**)&qbf, g_qbf);
    cudaGetSymbolAddress((void**)&h1bf, g_h1bf);
    cudaGetSymbolAddress((void**)&ybf, g_ybf);
    cudaGetSymbolAddress((void**)&xbf, g_xbf);
    cudaGetSymbolAddress((void**)&ctxbf, g_ctxbf);
    cudaGetSymbolAddress((void**)&ffnbf, g_ffnbf);
    cudaGetSymbolAddress((void**)&wbf, g_wbf);
    cudaGetSymbolAddress((void**)&khh, g_khh);
    cudaGetSymbolAddress((void**)&khl, g_khl);
    cudaGetSymbolAddress((void**)&vth, g_vth);

    static int attr_set = 0;
    if (!attr_set) {
        cudaFuncSetAttribute(gemm2_kernel,
                             cudaFuncAttributeMaxDynamicSharedMemorySize, G2_SMEM);
        cudaFuncSetAttribute(attn_mma_kernel,
                             cudaFuncAttributeMaxDynamicSharedMemorySize, ATTN_SMEM);
        attr_set = 1;
    }

    // 0: pe (+ zero gate counters)
    pe_kernel<<<S_, 256>>>(pe);
    // 1: q_raw split
    conv_qraw_kernel<<<4096 * 768 / 256, 256>>>(q_raw, qbf);
    // 2: ALL weights -> single fp16, one launch
    {
        ConvSegs cs;
        cs.src[0] = exp_w1;  cs.dstOff[0] = W_EXPW1; cs.K[0] = 768;  cs.N[0] = 768;  cs.tOff[0] = 0;
        cs.src[1] = exp_w2;  cs.dstOff[1] = W_EXPW2; cs.K[1] = 768;  cs.N[1] = 512;  cs.tOff[1] = 2304;
        cs.src[2] = adapt_w; cs.dstOff[2] = W_ADAPT; cs.K[2] = 3072; cs.N[2] = 512;  cs.tOff[2] = 3840;
        cs.src[3] = kw;      cs.dstOff[3] = W_KW;    cs.K[3] = 512;  cs.N[3] = 512;  cs.tOff[3] = 5376;
        cs.src[4] = vw;      cs.dstOff[4] = W_VW;    cs.K[4] = 512;  cs.N[4] = 512;  cs.tOff[4] = 6400;
        cs.src[5] = ow;      cs.dstOff[5] = W_OW;    cs.K[5] = 512;  cs.N[5] = 512;  cs.tOff[5] = 7424;
        cs.src[6] = fw1;     cs.dstOff[6] = W_FW1;   cs.K[6] = 512;  cs.N[6] = 2048; cs.tOff[6] = 8448;
        cs.src[7] = fw2;     cs.dstOff[7] = W_FW2;   cs.K[7] = 2048; cs.N[7] = 512;  cs.tOff[7] = 12544;
        convB_all_kernel<<<16640, dim3(32, 8)>>>(cs, wbf);
    }
    // 3: summary = relu(q_flat @ adapt_w + b)
    gemmL(qbf, 3072, 6144, 0, wbf + W_ADAPT, 0, 3072, adapt_b, 0, nullptr,
          summary, 0, nullptr, 0, nullptr, nullptr, nullptr,
          nullptr, nullptr, 0, 512, 1, 1);
    // 4: gate -> weights + expert row lists
    gate_kernel<<<BS, 256>>>(summary, m_seq, gate_w, gate_b, wgtp, cntp, listp);
    // 5: h1 = relu(gathered q_raw @ exp_w1 + b1) -> compacted split
    gemmL(qbf, 3072, 6144, 768, wbf + W_EXPW1, 768LL*768, 768, exp_b1, IN_, nullptr,
          nullptr, 0, h1bf, (long long)BS * 1536, nullptr, nullptr, nullptr,
          listp, cntp, 1, 768, NS_, 1);
    // 6: experts = compacted h1 @ exp_w2 + b2 -> scattered fp32
    gemmL(h1bf, 768, 1536, (long long)BS * 1536, wbf + W_EXPW2, 512LL*768, 768,
          exp_b2, D_, nullptr, experts, BSD, nullptr, 0,
          nullptr, nullptr, nullptr, listp, cntp, 2, 512, NS_, 0);
    // 7: combine + moe LN + pe
    moe_kernel<<<BS, 256>>>(wgtp, experts, moe_g, moe_b, pe, x, xbf);
    // 8: y' = qa + pe split
    add_pe_kernel<<<(int)(BSD / 256), 256>>>(qa, pe, ybf);
    // 9: V for all layers -> transposed fp16 (hi only)
    gemmL(ybf, 512, 1024, 0, wbf + W_VW, 512LL*512, 512, vb, D_, nullptr,
          nullptr, 0, nullptr, 0, nullptr, nullptr, vth,
          nullptr, nullptr, 0, 512, L_, 0);

    for (int i = 0; i < L_; i++) {
        gemmL(xbf, 512, 1024, 0, wbf + W_KW + (long long)i * 262144, 0, 512,
              kb + i*D_, 0, nullptr, nullptr, 0, nullptr, 0,
              khh, khl, nullptr, nullptr, nullptr, 0, 512, 1, 0);
        attn_mma_kernel<<<dim3(16, 32), 128, ATTN_SMEM>>>(
            khh, khl, vth + (long long)i * 2097152, ctxbf);
        gemmL(ctxbf, 512, 1024, 0, wbf + W_OW + (long long)i * 262144, 0, 512,
              ob + i*D_, 0, x, x, 0, nullptr, 0,
              nullptr, nullptr, nullptr, nullptr, nullptr, 0, 512, 1, 0);
        ln_kernel<<<BS, 256>>>(x, ln1g + i*D_, ln1b + i*D_, x, xbf);
        gemmL(xbf, 512, 1024, 0, wbf + W_FW1 + (long long)i * 1048576, 0, 512,
              fb1 + i*FF_, 0, nullptr, nullptr, 0, ffnbf, 0,
              nullptr, nullptr, nullptr, nullptr, nullptr, 0, 2048, 1, 1);
        gemmL(ffnbf, 2048, 4096, 0, wbf + W_FW2 + (long long)i * 1048576, 0, 2048,
              fb2 + i*D_, 0, x, x, 0, nullptr, 0,
              nullptr, nullptr, nullptr, nullptr, nullptr, 0, 512, 1, 0);
        ln_kernel<<<BS, 256>>>(x, ln2g + i*D_, ln2b + i*D_,
                               (i == L_-1) ? (float*)d_out : x,
                               (i == L_-1) ? nullptr : xbf);
    }
}

// round 13
// speedup vs baseline: 4.8036x; 1.0232x over previous
#include <cuda_runtime.h>
#include <cuda_fp16.h>
#include <cstdint>
#include <math.h>

// Problem dims
#define B_  4
#define S_  1024
#define D_  512
#define H_  8
#define DK_ 64
#define FF_ 2048
#define L_  4
#define IN_ 768
#define NS_ 4
#define SD_ 64

#define BS  (B_*S_)            // 4096
#define BSD ((long long)BS*D_) // 2097152
#define NEG_INF __int_as_float(0xff800000)

// ---------------- scratch (device globals: allocation-free) ----------------
__device__ float g_pe[S_*D_];
__device__ float g_x[BS*D_];
__device__ float g_experts[NS_*BS*D_];
__device__ float g_summary[BS*D_];
__device__ float g_wgt[BS*4];
__device__ int   g_cnt[4];
__device__ int   g_list[4*BS];
// split fp16 buffers, layout [m][hi K | lo K]
__device__ __half g_qbf[25165824];    // q_raw' [4096][6144]
__device__ __half g_h1bf[25165824];   // h1'   [4][4096][1536] (compacted slots)
__device__ __half g_ybf[4194304];     // y'    [4096][1024]
__device__ __half g_xbf[4194304];     // x'    [4096][1024]
__device__ __half g_ctxbf[4194304];   // ctx'  [4096][1024]
__device__ __half g_ffnbf[16777216];  // ffn'  [4096][4096]
__device__ __half g_khh[2097152];     // K hi [32][1024][64]
__device__ __half g_khl[2097152];     // K lo
__device__ __half g_vth[8388608];     // Vt hi [4][32][64][1024]
// all weights, SINGLE fp16 [n][K]
__device__ __half g_wbf[17039360];

// weight buffer offsets (fp16 elements)
#define W_EXPW1 0LL
#define W_EXPW2 2359296LL
#define W_ADAPT 3932160LL
#define W_KW    5505024LL
#define W_VW    6553600LL
#define W_OW    7602176LL
#define W_FW1   8650752LL
#define W_FW2   12845056LL

// ================= PTX helpers ===============================================
__device__ __forceinline__ uint32_t smem_u32(const void* p) {
    uint32_t a;
    asm("{ .reg .u64 t; cvta.to.shared.u64 t, %1; cvt.u32.u64 %0, t; }" : "=r"(a) : "l"(p));
    return a;
}
__device__ __forceinline__ void cp_async16(uint32_t dst, const void* src) {
    asm volatile("cp.async.cg.shared.global [%0], [%1], 16;" :: "r"(dst), "l"(src));
}
#define CP_COMMIT() asm volatile("cp.async.commit_group;" ::: "memory")
#define CP_WAIT0()  asm volatile("cp.async.wait_group 0;" ::: "memory")
#define CP_WAIT1()  asm volatile("cp.async.wait_group 1;" ::: "memory")

__device__ __forceinline__ void ldsm_x4(uint32_t& r0, uint32_t& r1, uint32_t& r2,
                                        uint32_t& r3, uint32_t addr) {
    asm volatile("ldmatrix.sync.aligned.m8n8.x4.shared.b16 {%0,%1,%2,%3}, [%4];"
        : "=r"(r0), "=r"(r1), "=r"(r2), "=r"(r3) : "r"(addr));
}
__device__ __forceinline__ void mma16816(float* c, const uint32_t* a, const uint32_t* b) {
    asm volatile(
        "mma.sync.aligned.m16n8k16.row.col.f32.f16.f16.f32 "
        "{%0,%1,%2,%3}, {%4,%5,%6,%7}, {%8,%9}, {%0,%1,%2,%3};"
        : "+f"(c[0]), "+f"(c[1]), "+f"(c[2]), "+f"(c[3])
        : "r"(a[0]), "r"(a[1]), "r"(a[2]), "r"(a[3]), "r"(b[0]), "r"(b[1]));
}
__device__ __forceinline__ uint32_t pack_h2(float lo, float hi) {
    uint32_t d;
    asm("cvt.rn.f16x2.f32 %0, %1, %2;" : "=r"(d) : "f"(hi), "f"(lo));
    return d;
}
__device__ __forceinline__ float h2_lo(uint32_t p) {
    return __half2float(__ushort_as_half((unsigned short)(p & 0xffff)));
}
__device__ __forceinline__ float h2_hi(uint32_t p) {
    return __half2float(__ushort_as_half((unsigned short)(p >> 16)));
}

__device__ __forceinline__ uint32_t swz(uint32_t base, int r, int ch) {
    return base + r * 128 + ((ch ^ (r & 7)) << 4);
}

// ================= conversions ==============================================
// q_raw [4096][3072] fp32 -> q' [4096][6144] = [hi 3072 | lo 3072]
__global__ __launch_bounds__(256) void conv_qraw_kernel(
    const float* __restrict__ src, __half* __restrict__ dst)
{
    int idx = blockIdx.x * 256 + threadIdx.x;
    int m = idx / 768;
    int k = (idx - m * 768) * 4;
    float4 v = *(const float4*)(src + (long long)m * 3072 + k);
    unsigned short hb[4], lb[4];
    float vv[4] = {v.x, v.y, v.z, v.w};
    #pragma unroll
    for (int i = 0; i < 4; i++) {
        __half h = __float2half_rn(vv[i]);
        __half l = __float2half_rn(vv[i] - __half2float(h));
        hb[i] = __half_as_ushort(h);
        lb[i] = __half_as_ushort(l);
    }
    long long base = (long long)m * 6144;
    *(uint2*)(dst + base + k) = make_uint2((uint32_t)hb[0] | ((uint32_t)hb[1] << 16),
                                           (uint32_t)hb[2] | ((uint32_t)hb[3] << 16));
    *(uint2*)(dst + base + 3072 + k) = make_uint2((uint32_t)lb[0] | ((uint32_t)lb[1] << 16),
                                                  (uint32_t)lb[2] | ((uint32_t)lb[3] << 16));
}

// all weights W [z][K][N] fp32 -> W' [z][n][K] single fp16, one launch
struct ConvSegs {
    const float* src[8];
    long long dstOff[8];
    int K[8], N[8], tOff[8];
};

__global__ void convB_all_kernel(ConvSegs segs, __half* __restrict__ wb)
{
    __shared__ float t[32][33];
    int bx = blockIdx.x;
    int seg = 0;
    #pragma unroll
    for (int i = 7; i >= 1; i--) if (bx >= segs.tOff[i]) { seg = i; break; }
    const int K = segs.K[seg], N = segs.N[seg];
    int tl = bx - segs.tOff[seg];
    int tz = (K >> 5) * (N >> 5);
    int z = tl / tz, rr = tl - z * tz;
    int k0 = (rr % (K >> 5)) * 32, n0 = (rr / (K >> 5)) * 32;
    const float* s = segs.src[seg] + (long long)z * K * N;
    __half* dstz = wb + segs.dstOff[seg] + (long long)z * N * K;
    int tx = threadIdx.x, ty = threadIdx.y;
    #pragma unroll
    for (int r = ty; r < 32; r += 8)
        t[r][tx] = s[(long long)(k0 + r) * N + n0 + tx];
    __syncthreads();
    #pragma unroll
    for (int r = ty; r < 32; r += 8) {
        dstz[(long long)(n0 + r) * K + k0 + tx] = __float2half_rn(t[tx][r]);
    }
}

// ================= unified split GEMM (fp16, 2 terms: Xh*W + Xl*W) ==========
// 256 threads, 8 warps, warp tile 32x32 over 128x64 CTA tile, 2-stage, 2 CTA/SM.
// gmode: 0 = dense, 1 = gather-A rows via list (Sp at slots), 2 = scatter-C rows
#define G2_STAGE 40960
#define G2_SMEM  81920

__global__ __launch_bounds__(256, 2) void gemm2_kernel(
    const __half* __restrict__ Ah0, int loA, int ldA, long long zA,
    const __half* __restrict__ Bt0, long long zB, int K,
    const float* __restrict__ bias, int sBias,
    const float* __restrict__ res,
    float* __restrict__ C, long long sC,
    __half* __restrict__ Sp, long long zSp,
    __half* __restrict__ KH, __half* __restrict__ KL,
    __half* __restrict__ VH,
    const int* __restrict__ glist, const int* __restrict__ gcnt,
    int gmode, int N, int relu)
{
    extern __shared__ __align__(1024) char smem[];
    __shared__ int slist[128];
    const int tid = threadIdx.x, wid = tid >> 5, lane = tid & 31;
    const int wy = wid >> 1, wx = wid & 1;       // 4x2 warps, 32x32 each
    const int z = blockIdx.z;
    const int brow = blockIdx.y * 128, bcol = blockIdx.x * 64;

    int cnt = 0;
    if (gmode) {
        cnt = gcnt[z];
        if (brow >= cnt) return;
        if (tid < 128) {
            int i = brow + tid;
            slist[tid] = glist[z * BS + (i < cnt ? i : cnt - 1)];
        }
    }

    const __half* Ahz = Ah0 + (long long)z * zA;
    const __half* Bh = Bt0 + (long long)z * zB + (long long)bcol * K;
    if (bias) bias += (long long)z * sBias;
    if (C) C += (long long)z * sC;
    if (Sp) Sp += (long long)z * zSp;

    if (gmode) __syncthreads();

    const uint32_t sb = smem_u32(smem);
    const int NC = K >> 6;

    // stage layout: Ah 16K @0, Al 16K @16384, B 8K @32768 (40K total)
    auto load_tile = [&](int c, int s) {
        const int kc = c * 64;
        const uint32_t st = sb + s * G2_STAGE;
        #pragma unroll
        for (int i = 0; i < 10; i++) {
            int idx = tid + i * 256;          // 0..2559
            if (idx < 1024) {
                int r = idx >> 3, ch = idx & 7;
                int rowA = (gmode == 1) ? slist[r] : (brow + r);
                cp_async16(swz(st, r, ch),
                           (const char*)(Ahz + (long long)rowA * ldA + kc) + ch * 16);
            } else if (idx < 2048) {
                int j = idx - 1024;
                int r = j >> 3, ch = j & 7;
                int rowA = (gmode == 1) ? slist[r] : (brow + r);
                cp_async16(swz(st + 16384, r, ch),
                           (const char*)(Ahz + loA + (long long)rowA * ldA + kc) + ch * 16);
            } else {
                int j = idx - 2048;
                int r = j >> 3, ch = j & 7;
                cp_async16(swz(st + 32768, r, ch),
                           (const char*)(Bh + (long long)r * K + kc) + ch * 16);
            }
        }
        CP_COMMIT();
    };

    float acc[2][4][4] = {};
    load_tile(0, 0);
    load_tile(1, 1);

    for (int c = 0; c < NC; c++) {
        const int s = c & 1;
        if (c + 1 < NC) { CP_WAIT1(); } else { CP_WAIT0(); }
        __syncthreads();
        const uint32_t stA = sb + s * G2_STAGE;

        #pragma unroll
        for (int ks = 0; ks < 4; ks++) {
            const int cb = ks * 2;
            uint32_t ah[2][4], al[2][4];
            #pragma unroll
            for (int ms = 0; ms < 2; ms++) {
                int r = wy * 32 + ms * 16 + (lane & 15);
                int ch = cb + (lane >> 4);
                ldsm_x4(ah[ms][0], ah[ms][1], ah[ms][2], ah[ms][3], swz(stA, r, ch));
                ldsm_x4(al[ms][0], al[ms][1], al[ms][2], al[ms][3], swz(stA + 16384, r, ch));
            }
            uint32_t bh[4][2];
            #pragma unroll
            for (int nh = 0; nh < 2; nh++) {
                int g = lane >> 3;
                int r = wx * 32 + nh * 16 + ((g & 2) << 2) + (lane & 7);
                int ch = cb + (g & 1);
                uint32_t r0, r1, r2, r3;
                ldsm_x4(r0, r1, r2, r3, swz(stA + 32768, r, ch));
                bh[nh*2][0] = r0; bh[nh*2][1] = r1;
                bh[nh*2+1][0] = r2; bh[nh*2+1][1] = r3;
            }
            // term-major: 8 independent accumulators between reuses
            #pragma unroll
            for (int ms = 0; ms < 2; ms++)
                #pragma unroll
                for (int ns = 0; ns < 4; ns++)
                    mma16816(acc[ms][ns], ah[ms], bh[ns]);
            #pragma unroll
            for (int ms = 0; ms < 2; ms++)
                #pragma unroll
                for (int ns = 0; ns < 4; ns++)
                    mma16816(acc[ms][ns], al[ms], bh[ns]);
        }
        __syncthreads();
        if (c + 2 < NC) load_tile(c + 2, s);
    }

    // ---- epilogue ----
    const int qrow = lane >> 2, qcol = (lane & 3) * 2;
    #pragma unroll
    for (int ms = 0; ms < 2; ms++) {
        int m = brow + wy * 32 + ms * 16 + qrow;
        bool ok0 = !gmode || (m < cnt);
        bool ok1 = !gmode || (m + 8 < cnt);
        int crow0 = (gmode == 2 && ok0) ? slist[m - brow] : m;
        int crow1 = (gmode == 2 && ok1) ? slist[m + 8 - brow] : m + 8;
        #pragma unroll
        for (int ns = 0; ns < 4; ns++) {
            int n = bcol + wx * 32 + ns * 8 + qcol;
            float2 v0 = make_float2(acc[ms][ns][0], acc[ms][ns][1]);
            float2 v1 = make_float2(acc[ms][ns][2], acc[ms][ns][3]);
            if (bias) {
                float b0 = bias[n], b1 = bias[n + 1];
                v0.x += b0; v0.y += b1; v1.x += b0; v1.y += b1;
            }
            if (res) {
                float2 r0 = *(const float2*)(res + (long long)m * N + n);
                float2 r1 = *(const float2*)(res + (long long)(m + 8) * N + n);
                v0.x += r0.x; v0.y += r0.y; v1.x += r1.x; v1.y += r1.y;
            }
            if (relu) {
                v0.x = fmaxf(v0.x, 0.f); v0.y = fmaxf(v0.y, 0.f);
                v1.x = fmaxf(v1.x, 0.f); v1.y = fmaxf(v1.y, 0.f);
            }
            if (C) {
                if (ok0) *(float2*)(C + (long long)crow0 * N + n) = v0;
                if (ok1) *(float2*)(C + (long long)crow1 * N + n) = v1;
            }
            uint32_t hp0 = pack_h2(v0.x, v0.y);
            uint32_t hp1 = pack_h2(v1.x, v1.y);
            uint32_t lp0 = pack_h2(v0.x - h2_lo(hp0), v0.y - h2_hi(hp0));
            uint32_t lp1 = pack_h2(v1.x - h2_lo(hp1), v1.y - h2_hi(hp1));
            if (Sp) {
                long long r0 = (long long)m * 2 * N, r1 = (long long)(m + 8) * 2 * N;
                if (ok0) {
                    *(uint32_t*)(Sp + r0 + n)     = hp0;
                    *(uint32_t*)(Sp + r0 + N + n) = lp0;
                }
                if (ok1) {
                    *(uint32_t*)(Sp + r1 + n)     = hp1;
                    *(uint32_t*)(Sp + r1 + N + n) = lp1;
                }
            }
            if (KH) {
                long long a0 = (((long long)((m >> 10) * 8 + (n >> 6))) * 1024 + (m & 1023)) * 64 + (n & 63);
                long long a1 = a0 + 8LL * 64;
                *(uint32_t*)(KH + a0) = hp0;  *(uint32_t*)(KL + a0) = lp0;
                *(uint32_t*)(KH + a1) = hp1;  *(uint32_t*)(KL + a1) = lp1;
            }
            if (VH) {
                int b = m >> 10, h = n >> 6, d = n & 63, si = m & 1023;
                long long base = (((long long)(z * 32 + b * 8 + h)) * 64 + d) * 1024 + si;
                unsigned short* vh = (unsigned short*)VH;
                vh[base]            = (unsigned short)(hp0 & 0xffff);
                vh[base + 1024]     = (unsigned short)(hp0 >> 16);
                vh[base + 8]        = (unsigned short)(hp1 & 0xffff);
                vh[base + 1024 + 8] = (unsigned short)(hp1 >> 16);
            }
        }
    }
}

// ================= tensor-core flash attention (fp16 2-term) =================
// smem: Qhi @0 (8K), Qlo @8192; stages @16384 + s*16384: {Khi 8K, Vhi 8K}
#define ATTN_SMEM 49152

__global__ __launch_bounds__(128) void attn_mma_kernel(
    const __half* __restrict__ khh, const __half* __restrict__ khl,
    const __half* __restrict__ vth,
    __half* __restrict__ Cx)
{
    extern __shared__ __align__(1024) char smem[];
    const uint32_t sb = smem_u32(smem);
    const int tid = threadIdx.x, wid = tid >> 5, lane = tid & 31;
    const int qb = 15 - blockIdx.x;
    const int bh = blockIdx.y;
    const int q0 = qb * 64;

    const __half* Kh = khh + (long long)bh * S_ * 64;
    const __half* Kl = khl + (long long)bh * S_ * 64;
    const __half* Vh = vth + (long long)bh * 64 * S_;

    auto load_kv = [&](int jt, int s) {
        const int j0 = jt * 64;
        const uint32_t base = sb + 16384 + s * 16384;
        #pragma unroll
        for (int i = 0; i < 4; i++) {
            int idx = tid + i * 128;
            int r = idx >> 3, ch = idx & 7;
            cp_async16(swz(base, r, ch),
                       (const char*)(Kh + (long long)(j0 + r) * 64) + ch * 16);
            cp_async16(swz(base + 8192, r, ch),
                       (const char*)(Vh + (long long)r * S_ + j0) + ch * 16);
        }
        CP_COMMIT();
    };

    #pragma unroll
    for (int i = 0; i < 4; i++) {
        int idx = tid + i * 128;
        int r = idx >> 3, ch = idx & 7;
        cp_async16(swz(sb, r, ch),
                   (const char*)(Kh + (long long)(q0 + r) * 64) + ch * 16);
        cp_async16(swz(sb + 8192, r, ch),
                   (const char*)(Kl + (long long)(q0 + r) * 64) + ch * 16);
    }
    load_kv(0, 0);
    CP_WAIT0();
    __syncthreads();

    uint32_t qh[4][4], ql[4][4];
    #pragma unroll
    for (int ks = 0; ks < 4; ks++) {
        int r = wid * 16 + (lane & 15);
        int ch = 2 * ks + (lane >> 4);
        ldsm_x4(qh[ks][0], qh[ks][1], qh[ks][2], qh[ks][3], swz(sb, r, ch));
        ldsm_x4(ql[ks][0], ql[ks][1], ql[ks][2], ql[ks][3], swz(sb + 8192, r, ch));
    }

    float ctx[8][4] = {};
    float m0 = NEG_INF, m1 = NEG_INF, l0 = 0.f, l1 = 0.f;
    const int rg0 = q0 + wid * 16 + (lane >> 2);

    for (int jt = 0; jt <= qb; jt++) {
        const int s = jt & 1;
        if (jt < qb) { load_kv(jt + 1, s ^ 1); CP_WAIT1(); }
        else if (jt > 0) { CP_WAIT0(); }
        __syncthreads();

        const uint32_t bK = sb + 16384 + s * 16384;

        float sc[8][4] = {};
        #pragma unroll
        for (int ks = 0; ks < 4; ks++) {
            uint32_t bh_[8][2];
            #pragma unroll
            for (int ng = 0; ng < 4; ng++) {
                int g = lane >> 3;
                int r = ng * 16 + ((g & 2) << 2) + (lane & 7);
                int ch = 2 * ks + (g & 1);
                uint32_t a0, a1, a2, a3;
                ldsm_x4(a0, a1, a2, a3, swz(bK, r, ch));
                bh_[2*ng][0] = a0; bh_[2*ng][1] = a1;
                bh_[2*ng+1][0] = a2; bh_[2*ng+1][1] = a3;
            }
            #pragma unroll
            for (int nt = 0; nt < 8; nt++) {
                mma16816(sc[nt], qh[ks], bh_[nt]);
                mma16816(sc[nt], ql[ks], bh_[nt]);
            }
        }

        const int j0 = jt * 64;
        const bool diag = (jt == qb);
        const int cb0 = j0 + (lane & 3) * 2;
        float rm0 = NEG_INF, rm1 = NEG_INF;
        #pragma unroll
        for (int nt = 0; nt < 8; nt++) {
            int c0 = cb0 + nt * 8, c1 = c0 + 1;
            float s0 = sc[nt][0] * 0.125f, s1 = sc[nt][1] * 0.125f;
            float s2 = sc[nt][2] * 0.125f, s3 = sc[nt][3] * 0.125f;
            if (diag) {
                if (c0 >= rg0)     s0 = NEG_INF;
                if (c1 >= rg0)     s1 = NEG_INF;
                if (c0 >= rg0 + 8) s2 = NEG_INF;
                if (c1 >= rg0 + 8) s3 = NEG_INF;
            }
            sc[nt][0] = s0; sc[nt][1] = s1; sc[nt][2] = s2; sc[nt][3] = s3;
            rm0 = fmaxf(rm0, fmaxf(s0, s1));
            rm1 = fmaxf(rm1, fmaxf(s2, s3));
        }
        #pragma unroll
        for (int o = 1; o <= 2; o <<= 1) {
            rm0 = fmaxf(rm0, __shfl_xor_sync(0xffffffffu, rm0, o));
            rm1 = fmaxf(rm1, __shfl_xor_sync(0xffffffffu, rm1, o));
        }
        float mn0 = fmaxf(m0, rm0), mn1 = fmaxf(m1, rm1);
        float ms0 = (mn0 == NEG_INF) ? 0.f : mn0;
        float ms1 = (mn1 == NEG_INF) ? 0.f : mn1;
        float cr0 = __expf(m0 - ms0), cr1 = __expf(m1 - ms1);
        float rs0 = 0.f, rs1 = 0.f;
        #pragma unroll
        for (int nt = 0; nt < 8; nt++) {
            sc[nt][0] = __expf(sc[nt][0] - ms0); rs0 += sc[nt][0];
            sc[nt][1] = __expf(sc[nt][1] - ms0); rs0 += sc[nt][1];
            sc[nt][2] = __expf(sc[nt][2] - ms1); rs1 += sc[nt][2];
            sc[nt][3] = __expf(sc[nt][3] - ms1); rs1 += sc[nt][3];
        }
        #pragma unroll
        for (int o = 1; o <= 2; o <<= 1) {
            rs0 += __shfl_xor_sync(0xffffffffu, rs0, o);
            rs1 += __shfl_xor_sync(0xffffffffu, rs1, o);
        }
        l0 = l0 * cr0 + rs0; l1 = l1 * cr1 + rs1;
        m0 = mn0; m1 = mn1;
        #pragma unroll
        for (int nt = 0; nt < 8; nt++) {
            ctx[nt][0] *= cr0; ctx[nt][1] *= cr0;
            ctx[nt][2] *= cr1; ctx[nt][3] *= cr1;
        }

        uint32_t ph[4][4], pl[4][4];
        #pragma unroll
        for (int kj = 0; kj < 4; kj++) {
            const int t0 = 2 * kj, t1 = 2 * kj + 1;
            ph[kj][0] = pack_h2(sc[t0][0], sc[t0][1]);
            ph[kj][1] = pack_h2(sc[t0][2], sc[t0][3]);
            ph[kj][2] = pack_h2(sc[t1][0], sc[t1][1]);
            ph[kj][3] = pack_h2(sc[t1][2], sc[t1][3]);
            pl[kj][0] = pack_h2(sc[t0][0] - h2_lo(ph[kj][0]), sc[t0][1] - h2_hi(ph[kj][0]));
            pl[kj][1] = pack_h2(sc[t0][2] - h2_lo(ph[kj][1]), sc[t0][3] - h2_hi(ph[kj][1]));
            pl[kj][2] = pack_h2(sc[t1][0] - h2_lo(ph[kj][2]), sc[t1][1] - h2_hi(ph[kj][2]));
            pl[kj][3] = pack_h2(sc[t1][2] - h2_lo(ph[kj][3]), sc[t1][3] - h2_hi(ph[kj][3]));
        }

        const uint32_t bV = bK + 8192;
        #pragma unroll
        for (int kj = 0; kj < 4; kj++) {
            uint32_t vh_[8][2];
            #pragma unroll
            for (int dg = 0; dg < 4; dg++) {
                int g = lane >> 3;
                int r = dg * 16 + ((g & 2) << 2) + (lane & 7);
                int ch = 2 * kj + (g & 1);
                uint32_t a0, a1, a2, a3;
                ldsm_x4(a0, a1, a2, a3, swz(bV, r, ch));
                vh_[2*dg][0] = a0; vh_[2*dg][1] = a1;
                vh_[2*dg+1][0] = a2; vh_[2*dg+1][1] = a3;
            }
            #pragma unroll
            for (int nt = 0; nt < 8; nt++) {
                mma16816(ctx[nt], ph[kj], vh_[nt]);
                mma16816(ctx[nt], pl[kj], vh_[nt]);
            }
        }
        __syncthreads();
    }

    float inv0 = (l0 > 0.f) ? 1.f / l0 : 0.f;
    float inv1 = (l1 > 0.f) ? 1.f / l1 : 0.f;
    const int b = bh >> 3, h = bh & 7;
    const int row0 = b * S_ + q0 + wid * 16 + (lane >> 2);
    const int colb = h * 64 + (lane & 3) * 2;
    #pragma unroll
    for (int nt = 0; nt < 8; nt++) {
        float a0 = ctx[nt][0] * inv0, a1 = ctx[nt][1] * inv0;
        float a2 = ctx[nt][2] * inv1, a3 = ctx[nt][3] * inv1;
        uint32_t hp0 = pack_h2(a0, a1);
        uint32_t hp1 = pack_h2(a2, a3);
        uint32_t lp0 = pack_h2(a0 - h2_lo(hp0), a1 - h2_hi(hp0));
        uint32_t lp1 = pack_h2(a2 - h2_lo(hp1), a3 - h2_hi(hp1));
        long long r0 = (long long)row0 * 1024, r1 = (long long)(row0 + 8) * 1024;
        int cc = colb + nt * 8;
        *(uint32_t*)(Cx + r0 + cc)       = hp0;
        *(uint32_t*)(Cx + r0 + 512 + cc) = lp0;
        *(uint32_t*)(Cx + r1 + cc)       = hp1;
        *(uint32_t*)(Cx + r1 + 512 + cc) = lp1;
    }
}

// ---------------- positional embedding (also zero gate counters) -----------
__global__ void pe_kernel(float* __restrict__ pe) {
    if (blockIdx.x == 0 && threadIdx.x < 4) g_cnt[threadIdx.x] = 0;
    int s = blockIdx.x;
    int j = threadIdx.x;
    float div = expf((float)(2*j) * (-9.210340371976184f / (float)D_));
    float arg = (float)s * div;
    pe[s*D_ + 2*j]     = sinf(arg);
    pe[s*D_ + 2*j + 1] = cosf(arg);
}

__global__ __launch_bounds__(256) void add_pe_kernel(
    const float* __restrict__ qa, const float* __restrict__ pe,
    __half* __restrict__ yb)
{
    int i = blockIdx.x * 256 + threadIdx.x;
    float v = qa[i] + pe[i & (S_*D_ - 1)];
    int m = i >> 9, c = i & 511;
    __half h = __float2half_rn(v);
    yb[(long long)m * 1024 + c]       = h;
    yb[(long long)m * 1024 + 512 + c] = __float2half_rn(v - __half2float(h));
}

// ---------------- gate: logits -> top-2 weights + expert row lists ----------
__global__ __launch_bounds__(256) void gate_kernel(
    const float* __restrict__ summary, const float* __restrict__ m_seq,
    const float* __restrict__ gate_w,  const float* __restrict__ gate_b,
    float* __restrict__ wgt, int* __restrict__ cnt, int* __restrict__ list)
{
    __shared__ float red[4][8];
    const int row = blockIdx.x;
    const int tid = threadIdx.x;

    float p0 = 0, p1 = 0, p2 = 0, p3 = 0;
    for (int e = tid; e < D_ + SD_; e += 256) {
        float xv = (e < D_) ? summary[(long long)row * D_ + e]
                            : m_seq[(long long)row * SD_ + (e - D_)];
        float4 w = *(const float4*)(gate_w + e * 4);
        p0 += xv * w.x; p1 += xv * w.y; p2 += xv * w.z; p3 += xv * w.w;
    }
    #pragma unroll
    for (int o = 16; o > 0; o >>= 1) {
        p0 += __shfl_xor_sync(0xffffffffu, p0, o);
        p1 += __shfl_xor_sync(0xffffffffu, p1, o);
        p2 += __shfl_xor_sync(0xffffffffu, p2, o);
        p3 += __shfl_xor_sync(0xffffffffu, p3, o);
    }
    if ((tid & 31) == 0) {
        int w = tid >> 5;
        red[0][w] = p0; red[1][w] = p1; red[2][w] = p2; red[3][w] = p3;
    }
    __syncthreads();

    if (tid == 0) {
        float l[4];
        #pragma unroll
        for (int j = 0; j < 4; j++) {
            float t = gate_b[j];
            #pragma unroll
            for (int w = 0; w < 8; w++) t += red[j][w];
            l[j] = t;
        }
        float m1v = -INFINITY, m2v = -INFINITY;
        #pragma unroll
        for (int j = 0; j < 4; j++) {
            if (l[j] > m1v) { m2v = m1v; m1v = l[j]; }
            else if (l[j] > m2v) { m2v = l[j]; }
        }
        float sum = 0.f, e4[4];
        #pragma unroll
        for (int j = 0; j < 4; j++) {
            e4[j] = (l[j] >= m2v) ? __expf(l[j] - m1v) : 0.f;
            sum += e4[j];
        }
        #pragma unroll
        for (int j = 0; j < 4; j++) {
            wgt[row * 4 + j] = e4[j] / sum;
            if (l[j] >= m2v) {
                int p = atomicAdd(&cnt[j], 1);
                list[j * BS + p] = row;
            }
        }
    }
}

// ---------------- MoE combine + LN + PE -> x (fp32 + split) ----------------
__global__ __launch_bounds__(256) void moe_kernel(
    const float* __restrict__ wgt, const float* __restrict__ experts,
    const float* __restrict__ lng, const float* __restrict__ lnb,
    const float* __restrict__ pe, float* __restrict__ x,
    __half* __restrict__ xb)
{
    __shared__ float r1[8], r2[8];
    const int row = blockIdx.x;
    const int tid = threadIdx.x;
    const int s_idx = row & (S_ - 1);

    const float w0 = wgt[row*4], w1 = wgt[row*4+1], w2 = wgt[row*4+2], w3 = wgt[row*4+3];
    const long long base = (long long)row * D_;
    const int t2 = tid + 256;
    float c0 = w0 * experts[0*BSD + base + tid] + w1 * experts[1*BSD + base + tid]
             + w2 * experts[2*BSD + base + tid] + w3 * experts[3*BSD + base + tid];
    float c1 = w0 * experts[0*BSD + base + t2]  + w1 * experts[1*BSD + base + t2]
             + w2 * experts[2*BSD + base + t2]  + w3 * experts[3*BSD + base + t2];

    float s = c0 + c1, q = c0 * c0 + c1 * c1;
    #pragma unroll
    for (int o = 16; o > 0; o >>= 1) {
        s += __shfl_xor_sync(0xffffffffu, s, o);
        q += __shfl_xor_sync(0xffffffffu, q, o);
    }
    if ((tid & 31) == 0) { r1[tid >> 5] = s; r2[tid >> 5] = q; }
    __syncthreads();
    float ts = 0, tq = 0;
    #pragma unroll
    for (int w = 0; w < 8; w++) { ts += r1[w]; tq += r2[w]; }
    float mu = ts * (1.f / 512.f);
    float var = tq * (1.f / 512.f) - mu * mu;
    float rstd = rsqrtf(var + 1e-5f);

    float o0 = (c0 - mu) * rstd * lng[tid] + lnb[tid] + pe[s_idx * D_ + tid];
    float o1 = (c1 - mu) * rstd * lng[t2]  + lnb[t2]  + pe[s_idx * D_ + t2];
    x[base + tid] = o0;
    x[base + t2]  = o1;
    long long b2 = (long long)row * 1024;
    __half h0 = __float2half_rn(o0);
    __half h1 = __float2half_rn(o1);
    xb[b2 + tid]        = h0;
    xb[b2 + t2]         = h1;
    xb[b2 + 512 + tid]  = __float2half_rn(o0 - __half2float(h0));
    xb[b2 + 512 + t2]   = __float2half_rn(o1 - __half2float(h1));
}

// ---------------- LayerNorm (fp32 out + optional split) --------------------
__global__ __launch_bounds__(256) void ln_kernel(
    const float* __restrict__ in, const float* __restrict__ g,
    const float* __restrict__ b, float* __restrict__ out,
    __half* __restrict__ sp)
{
    __shared__ float r1[8], r2[8];
    const int row = blockIdx.x, tid = threadIdx.x;
    const long long base = (long long)row * D_;
    float v0 = in[base + tid], v1 = in[base + tid + 256];
    float s = v0 + v1, q = v0 * v0 + v1 * v1;
    #pragma unroll
    for (int o = 16; o > 0; o >>= 1) {
        s += __shfl_xor_sync(0xffffffffu, s, o);
        q += __shfl_xor_sync(0xffffffffu, q, o);
    }
    if ((tid & 31) == 0) { r1[tid >> 5] = s; r2[tid >> 5] = q; }
    __syncthreads();
    float ts = 0, tq = 0;
    #pragma unroll
    for (int w = 0; w < 8; w++) { ts += r1[w]; tq += r2[w]; }
    float mu = ts * (1.f / 512.f);
    float var = tq * (1.f / 512.f) - mu * mu;
    float rstd = rsqrtf(var + 1e-5f);
    float o0 = (v0 - mu) * rstd * g[tid]       + b[tid];
    float o1 = (v1 - mu) * rstd * g[tid + 256] + b[tid + 256];
    out[base + tid]       = o0;
    out[base + tid + 256] = o1;
    if (sp) {
        long long b2 = (long long)row * 1024;
        __half h0 = __float2half_rn(o0);
        __half h1 = __float2half_rn(o1);
        sp[b2 + tid]       = h0;
        sp[b2 + tid + 256] = h1;
        sp[b2 + 512 + tid]       = __float2half_rn(o0 - __half2float(h0));
        sp[b2 + 512 + tid + 256] = __float2half_rn(o1 - __half2float(h1));
    }
}

// ================= host wrapper ==============================================
typedef __half h16;

static void gemmS(cudaStream_t st,
                  const h16* Ah, int loA, int ldA, long long zA,
                  const h16* Bt, long long zB, int K,
                  const float* bias, int sBias, const float* res,
                  float* C, long long sC, h16* Sp, long long zSp,
                  h16* KH, h16* KL, h16* VH,
                  const int* glist, const int* gcnt, int gmode,
                  int N, int nz, int relu)
{
    gemm2_kernel<<<dim3(N/64, 32, nz), 256, G2_SMEM, st>>>(
        Ah, loA, ldA, zA, Bt, zB, K, bias, sBias, res, C, sC,
        Sp, zSp, KH, KL, VH, glist, gcnt, gmode, N, relu);
}

extern "C" void kernel_launch(void* const* d_in, const int* in_sizes, int n_in,
                              void* d_out, int out_size)
{
    const float* q_raw   = (const float*)d_in[0];
    const float* m_seq   = (const float*)d_in[1];
    const float* qa      = (const float*)d_in[2];
    const float* exp_w1  = (const float*)d_in[3];
    const float* exp_b1  = (const float*)d_in[4];
    const float* exp_w2  = (const float*)d_in[5];
    const float* exp_b2  = (const float*)d_in[6];
    const float* adapt_w = (const float*)d_in[7];
    const float* adapt_b = (const float*)d_in[8];
    const float* gate_w  = (const float*)d_in[9];
    const float* gate_b  = (const float*)d_in[10];
    const float* moe_g   = (const float*)d_in[11];
    const float* moe_b   = (const float*)d_in[12];
    const float* kw      = (const float*)d_in[13];
    const float* kb      = (const float*)d_in[14];
    const float* vw      = (const float*)d_in[15];
    const float* vb      = (const float*)d_in[16];
    const float* ow      = (const float*)d_in[17];
    const float* ob      = (const float*)d_in[18];
    const float* ln1g    = (const float*)d_in[19];
    const float* ln1b    = (const float*)d_in[20];
    const float* fw1     = (const float*)d_in[21];
    const float* fb1     = (const float*)d_in[22];
    const float* fw2     = (const float*)d_in[23];
    const float* fb2     = (const float*)d_in[24];
    const float* ln2g    = (const float*)d_in[25];
    const float* ln2b    = (const float*)d_in[26];

    float *pe, *x, *experts, *summary, *wgtp;
    int *cntp, *listp;
    h16 *qbf, *h1bf, *ybf, *xbf, *ctxbf, *ffnbf, *wbf, *khh, *khl, *vth;
    cudaGetSymbolAddress((void**)&pe, g_pe);
    cudaGetSymbolAddress((void**)&x, g_x);
    cudaGetSymbolAddress((void**)&experts, g_experts);
    cudaGetSymbolAddress((void**)&summary, g_summary);
    cudaGetSymbolAddress((void**)&wgtp, g_wgt);
    cudaGetSymbolAddress((void**)&cntp, g_cnt);
    cudaGetSymbolAddress((void**)&listp, g_list);
    cudaGetSymbolAddress((void**)&qbf, g_qbf);
    cudaGetSymbolAddress((void**)&h1bf, g_h1bf);
    cudaGetSymbolAddress((void**)&ybf, g_ybf);
    cudaGetSymbolAddress((void**)&xbf, g_xbf);
    cudaGetSymbolAddress((void**)&ctxbf, g_ctxbf);
    cudaGetSymbolAddress((void**)&ffnbf, g_ffnbf);
    cudaGetSymbolAddress((void**)&wbf, g_wbf);
    cudaGetSymbolAddress((void**)&khh, g_khh);
    cudaGetSymbolAddress((void**)&khl, g_khl);
    cudaGetSymbolAddress((void**)&vth, g_vth);

    static int attr_set = 0;
    static cudaStream_t s2;
    static cudaEvent_t evFork, evJoin;
    if (!attr_set) {
        cudaFuncSetAttribute(gemm2_kernel,
                             cudaFuncAttributeMaxDynamicSharedMemorySize, G2_SMEM);
        cudaFuncSetAttribute(attn_mma_kernel,
                             cudaFuncAttributeMaxDynamicSharedMemorySize, ATTN_SMEM);
        cudaStreamCreateWithFlags(&s2, cudaStreamNonBlocking);
        cudaEventCreateWithFlags(&evFork, cudaEventDisableTiming);
        cudaEventCreateWithFlags(&evJoin, cudaEventDisableTiming);
        attr_set = 1;
    }
    cudaStream_t s0 = 0;

    // --- stream 0: shared prologue ---
    pe_kernel<<<S_, 256, 0, s0>>>(pe);
    conv_qraw_kernel<<<4096 * 768 / 256, 256, 0, s0>>>(q_raw, qbf);
    {
        ConvSegs cs;
        cs.src[0] = exp_w1;  cs.dstOff[0] = W_EXPW1; cs.K[0] = 768;  cs.N[0] = 768;  cs.tOff[0] = 0;
        cs.src[1] = exp_w2;  cs.dstOff[1] = W_EXPW2; cs.K[1] = 768;  cs.N[1] = 512;  cs.tOff[1] = 2304;
        cs.src[2] = adapt_w; cs.dstOff[2] = W_ADAPT; cs.K[2] = 3072; cs.N[2] = 512;  cs.tOff[2] = 3840;
        cs.src[3] = kw;      cs.dstOff[3] = W_KW;    cs.K[3] = 512;  cs.N[3] = 512;  cs.tOff[3] = 5376;
        cs.src[4] = vw;      cs.dstOff[4] = W_VW;    cs.K[4] = 512;  cs.N[4] = 512;  cs.tOff[4] = 6400;
        cs.src[5] = ow;      cs.dstOff[5] = W_OW;    cs.K[5] = 512;  cs.N[5] = 512;  cs.tOff[5] = 7424;
        cs.src[6] = fw1;     cs.dstOff[6] = W_FW1;   cs.K[6] = 512;  cs.N[6] = 2048; cs.tOff[6] = 8448;
        cs.src[7] = fw2;     cs.dstOff[7] = W_FW2;   cs.K[7] = 2048; cs.N[7] = 512;  cs.tOff[7] = 12544;
        convB_all_kernel<<<16640, dim3(32, 8), 0, s0>>>(cs, wbf);
    }

    // --- fork: stream 2 runs the V chain while stream 0 runs the MoE chain ---
    cudaEventRecord(evFork, s0);
    cudaStreamWaitEvent(s2, evFork, 0);

    // stream 2: y' = qa + pe, then V for all layers -> transposed fp16
    add_pe_kernel<<<(int)(BSD / 256), 256, 0, s2>>>(qa, pe, ybf);
    gemmS(s2, ybf, 512, 1024, 0, wbf + W_VW, 512LL*512, 512, vb, D_, nullptr,
          nullptr, 0, nullptr, 0, nullptr, nullptr, vth,
          nullptr, nullptr, 0, 512, L_, 0);
    cudaEventRecord(evJoin, s2);

    // stream 0: MoE chain
    gemmS(s0, qbf, 3072, 6144, 0, wbf + W_ADAPT, 0, 3072, adapt_b, 0, nullptr,
          summary, 0, nullptr, 0, nullptr, nullptr, nullptr,
          nullptr, nullptr, 0, 512, 1, 1);
    gate_kernel<<<BS, 256, 0, s0>>>(summary, m_seq, gate_w, gate_b, wgtp, cntp, listp);
    gemmS(s0, qbf, 3072, 6144, 768, wbf + W_EXPW1, 768LL*768, 768, exp_b1, IN_, nullptr,
          nullptr, 0, h1bf, (long long)BS * 1536, nullptr, nullptr, nullptr,
          listp, cntp, 1, 768, NS_, 1);
    gemmS(s0, h1bf, 768, 1536, (long long)BS * 1536, wbf + W_EXPW2, 512LL*768, 768,
          exp_b2, D_, nullptr, experts, BSD, nullptr, 0,
          nullptr, nullptr, nullptr, listp, cntp, 2, 512, NS_, 0);
    moe_kernel<<<BS, 256, 0, s0>>>(wgtp, experts, moe_g, moe_b, pe, x, xbf);

    // --- join: layer loop needs vth (s2) and xbf (s0) ---
    cudaStreamWaitEvent(s0, evJoin, 0);

    for (int i = 0; i < L_; i++) {
        gemmS(s0, xbf, 512, 1024, 0, wbf + W_KW + (long long)i * 262144, 0, 512,
              kb + i*D_, 0, nullptr, nullptr, 0, nullptr, 0,
              khh, khl, nullptr, nullptr, nullptr, 0, 512, 1, 0);
        attn_mma_kernel<<<dim3(16, 32), 128, ATTN_SMEM, s0>>>(
            khh, khl, vth + (long long)i * 2097152, ctxbf);
        gemmS(s0, ctxbf, 512, 1024, 0, wbf + W_OW + (long long)i * 262144, 0, 512,
              ob + i*D_, 0, x, x, 0, nullptr, 0,
              nullptr, nullptr, nullptr, nullptr, nullptr, 0, 512, 1, 0);
        ln_kernel<<<BS, 256, 0, s0>>>(x, ln1g + i*D_, ln1b + i*D_, x, xbf);
        gemmS(s0, xbf, 512, 1024, 0, wbf + W_FW1 + (long long)i * 1048576, 0, 512,
              fb1 + i*FF_, 0, nullptr, nullptr, 0, ffnbf, 0,
              nullptr, nullptr, nullptr, nullptr, nullptr, 0, 2048, 1, 1);
        gemmS(s0, ffnbf, 2048, 4096, 0, wbf + W_FW2 + (long long)i * 1048576, 0, 2048,
              fb2 + i*D_, 0, x, x, 0, nullptr, 0,
              nullptr, nullptr, nullptr, nullptr, nullptr, 0, 512, 1, 0);
        ln_kernel<<<BS, 256, 0, s0>>>(x, ln2g + i*D_, ln2b + i*D_,
                               (i == L_-1) ? (float*)d_out : x,
                               (i == L_-1) ? nullptr : xbf);
    }
}